// round 2
// baseline (speedup 1.0000x reference)
#include <cuda_runtime.h>
#include <math.h>

#define B_  4
#define T_  2048
#define V_  2048
#define D_  512
#define H_  8
#define L_  4
#define HD_ 64

// Scratch buffers (no allocation allowed) — 5 x 16MB
__device__ __align__(16) float g_h[B_ * T_ * D_];
__device__ __align__(16) float g_q[B_ * T_ * D_];
__device__ __align__(16) float g_k[B_ * T_ * D_];
__device__ __align__(16) float g_v[B_ * T_ * D_];
__device__ __align__(16) float g_o[B_ * T_ * D_];

// ---------------------------------------------------------------------------
// NT GEMM: C[M,N] = alpha * A[M,K] @ B[N,K]^T  (+ bias[(row % T_)*N + col])
// 128x128 tile, BK=8, 256 threads, 8x8 microtile.
// ---------------------------------------------------------------------------
__global__ void __launch_bounds__(256) gemm_nt_kernel(
    const float* __restrict__ A, const float* __restrict__ Bm,
    float* __restrict__ C, const float* __restrict__ bias,
    int M, int N, int K, float alpha)
{
    __shared__ float As[8][128];
    __shared__ float Bs[8][128];

    const int tid  = threadIdx.x;
    const int bm   = blockIdx.y * 128;
    const int bn   = blockIdx.x * 128;
    const int lrow = tid >> 1;
    const int lcol = (tid & 1) << 2;

    const float* Ap = A  + (size_t)(bm + lrow) * K + lcol;
    const float* Bp = Bm + (size_t)(bn + lrow) * K + lcol;

    const int ty = tid >> 4;
    const int tx = tid & 15;

    float acc[8][8];
#pragma unroll
    for (int i = 0; i < 8; i++)
#pragma unroll
        for (int j = 0; j < 8; j++) acc[i][j] = 0.f;

    for (int k0 = 0; k0 < K; k0 += 8) {
        float4 av = *(const float4*)(Ap + k0);
        float4 bv = *(const float4*)(Bp + k0);
        As[lcol + 0][lrow] = av.x;
        As[lcol + 1][lrow] = av.y;
        As[lcol + 2][lrow] = av.z;
        As[lcol + 3][lrow] = av.w;
        Bs[lcol + 0][lrow] = bv.x;
        Bs[lcol + 1][lrow] = bv.y;
        Bs[lcol + 2][lrow] = bv.z;
        Bs[lcol + 3][lrow] = bv.w;
        __syncthreads();

#pragma unroll
        for (int kk = 0; kk < 8; kk++) {
            float a[8], b[8];
            *(float4*)&a[0] = *(const float4*)&As[kk][ty * 8];
            *(float4*)&a[4] = *(const float4*)&As[kk][ty * 8 + 4];
            *(float4*)&b[0] = *(const float4*)&Bs[kk][tx * 8];
            *(float4*)&b[4] = *(const float4*)&Bs[kk][tx * 8 + 4];
#pragma unroll
            for (int i = 0; i < 8; i++)
#pragma unroll
                for (int j = 0; j < 8; j++)
                    acc[i][j] += a[i] * b[j];
        }
        __syncthreads();
    }

#pragma unroll
    for (int i = 0; i < 8; i++) {
        int row = bm + ty * 8 + i;
        const float* bp = bias ? (bias + (size_t)(row & (T_ - 1)) * N) : nullptr;
#pragma unroll
        for (int j = 0; j < 8; j += 4) {
            int col = bn + tx * 8 + j;
            float4 ov;
            ov.x = acc[i][j + 0] * alpha;
            ov.y = acc[i][j + 1] * alpha;
            ov.z = acc[i][j + 2] * alpha;
            ov.w = acc[i][j + 3] * alpha;
            if (bp) {
                ov.x += bp[col + 0];
                ov.y += bp[col + 1];
                ov.z += bp[col + 2];
                ov.w += bp[col + 3];
            }
            *(float4*)&C[(size_t)row * N + col] = ov;
        }
    }
}

// ---------------------------------------------------------------------------
// Flash-style attention (full, non-causal), fp32.
// Q,K,V,O: [B, T, D] with head h occupying cols [h*64, h*64+64).
// grid = (T/BQ, H, B), 256 threads. Online softmax, m/l in registers.
// ---------------------------------------------------------------------------
#define BQ   64
#define BKV  32
#define KSTR 65   // padded K-tile row stride (64 dims + 1) — conflict-free reads

__global__ void __launch_bounds__(256) attn_kernel(
    const float* __restrict__ Q, const float* __restrict__ K,
    const float* __restrict__ V, float* __restrict__ O)
{
    __shared__ float Qs[BQ * HD_];    // [64][64]
    __shared__ float Ks[BKV * KSTR];  // [32][65]
    __shared__ float Vs[BKV * HD_];   // [32][64]
    __shared__ float Ps[BQ * BKV];    // [64][32]

    const int tid = threadIdx.x;
    const int q0  = blockIdx.x * BQ;
    const int hh  = blockIdx.y;
    const int bb  = blockIdx.z;
    const size_t base = ((size_t)bb * T_) * D_ + (size_t)hh * HD_;

    const int lr = tid >> 4;         // 0..15
    const int lc = (tid & 15) << 2;  // 0..60 step 4

    // Load Q tile (64 rows x 64 cols)
#pragma unroll
    for (int p = 0; p < 4; p++) {
        int row = lr + p * 16;
        *(float4*)&Qs[row * HD_ + lc] =
            *(const float4*)(Q + base + (size_t)(q0 + row) * D_ + lc);
    }

    const int ty  = tid >> 4;
    const int tx  = tid & 15;
    const int i0  = ty * 4;   // 4 query rows owned by this thread
    const int j0s = tx * 2;   // 2 score cols (KV tokens)
    const int j0o = tx * 4;   // 4 output cols (head dims)

    float o[4][4];
    float mrow[4], lrow[4];
#pragma unroll
    for (int a = 0; a < 4; a++) {
        mrow[a] = -INFINITY;
        lrow[a] = 0.f;
#pragma unroll
        for (int j = 0; j < 4; j++) o[a][j] = 0.f;
    }

    for (int t = 0; t < T_ / BKV; t++) {
        __syncthreads();  // prior O-phase done reading Ks/Vs/Ps (and Qs ready, iter 0)

        // Load K,V tile (32 rows x 64 cols each)
#pragma unroll
        for (int p = 0; p < 2; p++) {
            int row = lr + p * 16;
            size_t g = base + (size_t)(t * BKV + row) * D_ + lc;
            float4 kv = *(const float4*)(K + g);
            Ks[row * KSTR + lc + 0] = kv.x;
            Ks[row * KSTR + lc + 1] = kv.y;
            Ks[row * KSTR + lc + 2] = kv.z;
            Ks[row * KSTR + lc + 3] = kv.w;
            *(float4*)&Vs[row * HD_ + lc] = *(const float4*)(V + g);
        }
        __syncthreads();

        // S = Q K^T (4x2 microtile per thread)
        float s0[4], s1[4];
#pragma unroll
        for (int a = 0; a < 4; a++) { s0[a] = 0.f; s1[a] = 0.f; }
#pragma unroll 8
        for (int d = 0; d < HD_; d++) {
            float k0v = Ks[(j0s + 0) * KSTR + d];
            float k1v = Ks[(j0s + 1) * KSTR + d];
#pragma unroll
            for (int a = 0; a < 4; a++) {
                float qv = Qs[(i0 + a) * HD_ + d];
                s0[a] += qv * k0v;
                s1[a] += qv * k1v;
            }
        }

        // Online softmax per row (16-lane group owns one row set)
#pragma unroll
        for (int a = 0; a < 4; a++) {
            float e0 = s0[a] * 0.125f;   // 1/sqrt(HD)
            float e1 = s1[a] * 0.125f;
            float mx = fmaxf(e0, e1);
#pragma unroll
            for (int off = 8; off >= 1; off >>= 1)
                mx = fmaxf(mx, __shfl_xor_sync(0xffffffffu, mx, off));
            float mnew  = fmaxf(mrow[a], mx);
            float alpha = __expf(mrow[a] - mnew);
            float p0 = __expf(e0 - mnew);
            float p1 = __expf(e1 - mnew);
            float rs = p0 + p1;
#pragma unroll
            for (int off = 8; off >= 1; off >>= 1)
                rs += __shfl_xor_sync(0xffffffffu, rs, off);
            lrow[a] = lrow[a] * alpha + rs;
            mrow[a] = mnew;
#pragma unroll
            for (int j = 0; j < 4; j++) o[a][j] *= alpha;
            *(float2*)&Ps[(i0 + a) * BKV + j0s] = make_float2(p0, p1);
        }
        __syncthreads();  // Ps visible to O-phase

        // O += P @ V  (4x4 microtile over head dims)
#pragma unroll 4
        for (int k = 0; k < BKV; k++) {
            float4 v4 = *(const float4*)&Vs[k * HD_ + j0o];
#pragma unroll
            for (int a = 0; a < 4; a++) {
                float pv = Ps[(i0 + a) * BKV + k];
                o[a][0] += pv * v4.x;
                o[a][1] += pv * v4.y;
                o[a][2] += pv * v4.z;
                o[a][3] += pv * v4.w;
            }
        }
    }

    // Normalize and store
#pragma unroll
    for (int a = 0; a < 4; a++) {
        float inv = 1.f / lrow[a];
        float4 ov = make_float4(o[a][0] * inv, o[a][1] * inv,
                                o[a][2] * inv, o[a][3] * inv);
        *(float4*)&O[base + (size_t)(q0 + i0 + a) * D_ + j0o] = ov;
    }
}

// ---------------------------------------------------------------------------
// Readout: logits[b,v] = dot(h[b, T-1, :], R[v, :]) / sqrt(D)
// ---------------------------------------------------------------------------
__global__ void __launch_bounds__(256) readout_kernel(
    const float* __restrict__ hbuf, const float* __restrict__ R,
    float* __restrict__ out)
{
    __shared__ float hs[B_][D_];
    for (int i = threadIdx.x; i < B_ * D_; i += 256) {
        int b = i >> 9, d = i & 511;
        hs[b][d] = hbuf[((size_t)b * T_ + (T_ - 1)) * D_ + d];
    }
    __syncthreads();

    int v = blockIdx.x * 256 + threadIdx.x;
    float a0 = 0.f, a1 = 0.f, a2 = 0.f, a3 = 0.f;
    const float* r = R + (size_t)v * D_;
    for (int d = 0; d < D_; d += 4) {
        float4 rv = *(const float4*)(r + d);
        a0 += rv.x * hs[0][d] + rv.y * hs[0][d + 1] + rv.z * hs[0][d + 2] + rv.w * hs[0][d + 3];
        a1 += rv.x * hs[1][d] + rv.y * hs[1][d + 1] + rv.z * hs[1][d + 2] + rv.w * hs[1][d + 3];
        a2 += rv.x * hs[2][d] + rv.y * hs[2][d + 1] + rv.z * hs[2][d + 2] + rv.w * hs[2][d + 3];
        a3 += rv.x * hs[3][d] + rv.y * hs[3][d + 1] + rv.z * hs[3][d + 2] + rv.w * hs[3][d + 3];
    }
    const float sc = 0.04419417382415922f;  // 1/sqrt(512)
    out[0 * V_ + v] = a0 * sc;
    out[1 * V_ + v] = a1 * sc;
    out[2 * V_ + v] = a2 * sc;
    out[3 * V_ + v] = a3 * sc;
}

// ---------------------------------------------------------------------------
extern "C" void kernel_launch(void* const* d_in, const int* in_sizes, int n_in,
                              void* d_out, int out_size)
{
    const float* x  = (const float*)d_in[0];  // [B,T,V]
    const float* te = (const float*)d_in[1];  // [D,V]
    const float* pe = (const float*)d_in[2];  // [T,D]
    const float* Wk = (const float*)d_in[3];  // [L,D,D]
    const float* Wq = (const float*)d_in[4];
    const float* Wv = (const float*)d_in[5];
    const float* Wp = (const float*)d_in[6];
    const float* ro = (const float*)d_in[7];  // [V,D]
    float* out = (float*)d_out;               // [B,V]

    float *h, *q, *k, *v, *o;
    cudaGetSymbolAddress((void**)&h, g_h);
    cudaGetSymbolAddress((void**)&q, g_q);
    cudaGetSymbolAddress((void**)&k, g_k);
    cudaGetSymbolAddress((void**)&v, g_v);
    cudaGetSymbolAddress((void**)&o, g_o);

    const float sV = 0.022097086912079608f;  // 1/sqrt(2048)
    const float sD = 0.04419417382415922f;   // 1/sqrt(512)

    // h = x @ TE^T / sqrt(V) + pos
    gemm_nt_kernel<<<dim3(D_ / 128, (B_ * T_) / 128), 256>>>(
        x, te, h, pe, B_ * T_, D_, V_, sV);

    for (int l = 0; l < L_; l++) {
        const float* wq = Wq + (size_t)l * D_ * D_;
        const float* wk = Wk + (size_t)l * D_ * D_;
        const float* wv = Wv + (size_t)l * D_ * D_;
        const float* wp = Wp + (size_t)l * D_ * D_;

        gemm_nt_kernel<<<dim3(D_ / 128, (B_ * T_) / 128), 256>>>(
            h, wq, q, nullptr, B_ * T_, D_, D_, sD);
        gemm_nt_kernel<<<dim3(D_ / 128, (B_ * T_) / 128), 256>>>(
            h, wk, k, nullptr, B_ * T_, D_, D_, sD);
        gemm_nt_kernel<<<dim3(D_ / 128, (B_ * T_) / 128), 256>>>(
            h, wv, v, nullptr, B_ * T_, D_, D_, sD);

        attn_kernel<<<dim3(T_ / BQ, H_, B_), 256>>>(q, k, v, o);

        gemm_nt_kernel<<<dim3(D_ / 128, (B_ * T_) / 128), 256>>>(
            o, wp, h, nullptr, B_ * T_, D_, D_, sD);
    }

    readout_kernel<<<V_ / 256, 256>>>(h, ro, out);
}

// round 3
// speedup vs baseline: 1.6337x; 1.6337x over previous
#include <cuda_runtime.h>
#include <cuda_bf16.h>
#include <math.h>
#include <stdint.h>

#define B_  4
#define T_  2048
#define V_  2048
#define D_  512
#define H_  8
#define L_  4
#define HD_ 64

// Scratch buffers (no allocation allowed)
__device__ __align__(16) float g_h[B_ * T_ * D_];
__device__ __align__(16) float g_q[B_ * T_ * D_];
__device__ __align__(16) float g_k[B_ * T_ * D_];
__device__ __align__(16) float g_v[B_ * T_ * D_];
__device__ __align__(16) float g_o[B_ * T_ * D_];

// ---------------------------------------------------------------------------
// bf16x3 helpers: a = hi + lo with |err| ~ 2^-17 |a|
// ---------------------------------------------------------------------------
__device__ __forceinline__ void split2(float x, float y, uint32_t& h, uint32_t& l)
{
    __nv_bfloat16 xh = __float2bfloat16_rn(x);
    __nv_bfloat16 yh = __float2bfloat16_rn(y);
    __nv_bfloat16 xl = __float2bfloat16_rn(x - __bfloat162float(xh));
    __nv_bfloat16 yl = __float2bfloat16_rn(y - __bfloat162float(yh));
    __nv_bfloat162 hv = __halves2bfloat162(xh, yh);
    __nv_bfloat162 lv = __halves2bfloat162(xl, yl);
    h = *reinterpret_cast<uint32_t*>(&hv);
    l = *reinterpret_cast<uint32_t*>(&lv);
}

// D += A * B  (m16n8k16, bf16 in, fp32 acc)
__device__ __forceinline__ void mma16816(float* d, const uint32_t* a, const uint32_t* b)
{
    asm volatile(
        "mma.sync.aligned.m16n8k16.row.col.f32.bf16.bf16.f32 "
        "{%0,%1,%2,%3}, {%4,%5,%6,%7}, {%8,%9}, {%0,%1,%2,%3};\n"
        : "+f"(d[0]), "+f"(d[1]), "+f"(d[2]), "+f"(d[3])
        : "r"(a[0]), "r"(a[1]), "r"(a[2]), "r"(a[3]), "r"(b[0]), "r"(b[1]));
}

// ---------------------------------------------------------------------------
// NT GEMM on tensor cores with bf16x3: C[M,N] = alpha * A[M,K] @ B[N,K]^T (+bias)
// Block tile 128x128, BK=16, 256 threads (8 warps, warp tile 32x64).
// smem: hi/lo bf16 tiles, double-buffered, XOR-swizzled (8 words/row).
// ---------------------------------------------------------------------------
__global__ void __launch_bounds__(256) gemm_nt_mma(
    const float* __restrict__ A, const float* __restrict__ Bm,
    float* __restrict__ C, const float* __restrict__ bias,
    int M, int N, int K, float alpha)
{
    __shared__ uint32_t Ah[2][128 * 8], Al[2][128 * 8];
    __shared__ uint32_t Bh[2][128 * 8], Bl[2][128 * 8];

    const int tid  = threadIdx.x;
    const int lane = tid & 31;
    const int wid  = tid >> 5;
    const int wm   = (wid & 3) * 32;   // warp m offset in tile
    const int wn   = (wid >> 2) * 64;  // warp n offset
    const int bm   = blockIdx.y * 128;
    const int bn   = blockIdx.x * 128;
    const int g    = lane >> 2;
    const int j    = lane & 3;

    const int lrow  = tid >> 1;
    const int lhalf = tid & 1;
    const float* Ap = A  + (size_t)(bm + lrow) * K + lhalf * 8;
    const float* Bp = Bm + (size_t)(bn + lrow) * K + lhalf * 8;
    const int sw   = lrow * 8;
    const int sx   = lrow & 7;

    float acc[2][8][4];
#pragma unroll
    for (int mt = 0; mt < 2; mt++)
#pragma unroll
        for (int nt = 0; nt < 8; nt++)
#pragma unroll
            for (int i = 0; i < 4; i++) acc[mt][nt][i] = 0.f;

    const int KT = K >> 4;
    float ra[8], rb[8];

    // prologue: tile 0 -> regs -> smem stage 0
    *(float4*)&ra[0] = *(const float4*)(Ap);
    *(float4*)&ra[4] = *(const float4*)(Ap + 4);
    *(float4*)&rb[0] = *(const float4*)(Bp);
    *(float4*)&rb[4] = *(const float4*)(Bp + 4);
#pragma unroll
    for (int i = 0; i < 4; i++) {
        int wp = (lhalf * 4 + i) ^ sx;
        uint32_t h, l;
        split2(ra[2 * i], ra[2 * i + 1], h, l);
        Ah[0][sw + wp] = h; Al[0][sw + wp] = l;
        split2(rb[2 * i], rb[2 * i + 1], h, l);
        Bh[0][sw + wp] = h; Bl[0][sw + wp] = l;
    }
    __syncthreads();

    for (int ks = 0; ks < KT; ks++) {
        const int cur = ks & 1, nxt = cur ^ 1;

        if (ks + 1 < KT) {  // prefetch next tile to regs
            int k0 = (ks + 1) << 4;
            *(float4*)&ra[0] = *(const float4*)(Ap + k0);
            *(float4*)&ra[4] = *(const float4*)(Ap + k0 + 4);
            *(float4*)&rb[0] = *(const float4*)(Bp + k0);
            *(float4*)&rb[4] = *(const float4*)(Bp + k0 + 4);
        }

        // A fragments (hi/lo) for both m-tiles
        uint32_t fah[2][4], fal[2][4];
#pragma unroll
        for (int mt = 0; mt < 2; mt++) {
            int r0 = wm + mt * 16 + g;
            int b0 = r0 * 8, b1 = (r0 + 8) * 8, x = r0 & 7;
            fah[mt][0] = Ah[cur][b0 + (j ^ x)];
            fah[mt][1] = Ah[cur][b1 + (j ^ x)];
            fah[mt][2] = Ah[cur][b0 + ((j + 4) ^ x)];
            fah[mt][3] = Ah[cur][b1 + ((j + 4) ^ x)];
            fal[mt][0] = Al[cur][b0 + (j ^ x)];
            fal[mt][1] = Al[cur][b1 + (j ^ x)];
            fal[mt][2] = Al[cur][b0 + ((j + 4) ^ x)];
            fal[mt][3] = Al[cur][b1 + ((j + 4) ^ x)];
        }
#pragma unroll
        for (int nt = 0; nt < 8; nt++) {
            int rn = wn + nt * 8 + g;
            int bb = rn * 8, x = rn & 7;
            uint32_t fbh[2] = { Bh[cur][bb + (j ^ x)], Bh[cur][bb + ((j + 4) ^ x)] };
            uint32_t fbl[2] = { Bl[cur][bb + (j ^ x)], Bl[cur][bb + ((j + 4) ^ x)] };
#pragma unroll
            for (int mt = 0; mt < 2; mt++) {
                mma16816(acc[mt][nt], fah[mt], fbh);
                mma16816(acc[mt][nt], fal[mt], fbh);
                mma16816(acc[mt][nt], fah[mt], fbl);
            }
        }

        if (ks + 1 < KT) {
#pragma unroll
            for (int i = 0; i < 4; i++) {
                int wp = (lhalf * 4 + i) ^ sx;
                uint32_t h, l;
                split2(ra[2 * i], ra[2 * i + 1], h, l);
                Ah[nxt][sw + wp] = h; Al[nxt][sw + wp] = l;
                split2(rb[2 * i], rb[2 * i + 1], h, l);
                Bh[nxt][sw + wp] = h; Bl[nxt][sw + wp] = l;
            }
        }
        __syncthreads();
    }

    // epilogue
#pragma unroll
    for (int mt = 0; mt < 2; mt++) {
#pragma unroll
        for (int nt = 0; nt < 8; nt++) {
            int row = bm + wm + mt * 16 + g;
            int col = bn + wn + nt * 8 + j * 2;
            float2 v0 = make_float2(acc[mt][nt][0] * alpha, acc[mt][nt][1] * alpha);
            float2 v1 = make_float2(acc[mt][nt][2] * alpha, acc[mt][nt][3] * alpha);
            if (bias) {
                const float* b0 = bias + (size_t)(row & (T_ - 1)) * N + col;
                const float* b1 = bias + (size_t)((row + 8) & (T_ - 1)) * N + col;
                v0.x += b0[0]; v0.y += b0[1];
                v1.x += b1[0]; v1.y += b1[1];
            }
            *(float2*)&C[(size_t)row * N + col]       = v0;
            *(float2*)&C[(size_t)(row + 8) * N + col] = v1;
        }
    }
}

// ---------------------------------------------------------------------------
// Flash attention on tensor cores, bf16x3. BQ=64, BKV=64, 4 warps (128 thr).
// Q fragments register-resident; P reused from S accumulator fragments.
// smem rows padded to 36 words (conflict-free fragment reads).
// ---------------------------------------------------------------------------
#define VSTR 36

__global__ void __launch_bounds__(128) attn_mma(
    const float* __restrict__ Q, const float* __restrict__ K,
    const float* __restrict__ V, float* __restrict__ O)
{
    __shared__ uint32_t Kh[64 * VSTR], Kl[64 * VSTR];  // also Q staging
    __shared__ uint32_t Vh[64 * VSTR], Vl[64 * VSTR];  // V transposed [d][kv/2]

    const int tid  = threadIdx.x;
    const int lane = tid & 31;
    const int wid  = tid >> 5;
    const int g    = lane >> 2;
    const int j    = lane & 3;

    const int q0 = blockIdx.x * 64;
    const int hh = blockIdx.y;
    const int bb = blockIdx.z;
    const size_t base = ((size_t)bb * T_) * D_ + (size_t)hh * HD_;

    const int lrow  = tid >> 1;     // 0..63
    const int lhalf = tid & 1;      // 0..1 (32-col halves)

    // ---- stage Q tile into Kh/Kl, pull fragments to registers ----
    {
        const float* qp = Q + base + (size_t)(q0 + lrow) * D_ + lhalf * 32;
#pragma unroll
        for (int i = 0; i < 8; i++) {
            float4 f = *(const float4*)(qp + i * 4);
            uint32_t h0, l0, h1, l1;
            split2(f.x, f.y, h0, l0);
            split2(f.z, f.w, h1, l1);
            int w0 = lhalf * 16 + i * 2;
            Kh[lrow * VSTR + w0]     = h0; Kl[lrow * VSTR + w0]     = l0;
            Kh[lrow * VSTR + w0 + 1] = h1; Kl[lrow * VSTR + w0 + 1] = l1;
        }
    }
    __syncthreads();

    uint32_t Qh[4][4], Ql[4][4];
    {
        int r0 = wid * 16 + g, r1 = r0 + 8;
#pragma unroll
        for (int kf = 0; kf < 4; kf++) {
            Qh[kf][0] = Kh[r0 * VSTR + kf * 8 + j];
            Qh[kf][1] = Kh[r1 * VSTR + kf * 8 + j];
            Qh[kf][2] = Kh[r0 * VSTR + kf * 8 + 4 + j];
            Qh[kf][3] = Kh[r1 * VSTR + kf * 8 + 4 + j];
            Ql[kf][0] = Kl[r0 * VSTR + kf * 8 + j];
            Ql[kf][1] = Kl[r1 * VSTR + kf * 8 + j];
            Ql[kf][2] = Kl[r0 * VSTR + kf * 8 + 4 + j];
            Ql[kf][3] = Kl[r1 * VSTR + kf * 8 + 4 + j];
        }
    }
    __syncthreads();

    float oac[8][4];
#pragma unroll
    for (int nt = 0; nt < 8; nt++)
#pragma unroll
        for (int i = 0; i < 4; i++) oac[nt][i] = 0.f;
    float m0 = -INFINITY, m1 = -INFINITY, l0 = 0.f, l1 = 0.f;

    const int dgrp = tid & 15;  // V loader: d0 = dgrp*4
    const int kvg  = tid >> 4;  // kv0 = kvg*8

    for (int t = 0; t < T_ / 64; t++) {
        // ---- load K tile (rows kv, cols d) ----
        {
            const float* kp = K + base + (size_t)(t * 64 + lrow) * D_ + lhalf * 32;
#pragma unroll
            for (int i = 0; i < 8; i++) {
                float4 f = *(const float4*)(kp + i * 4);
                uint32_t h0, lo0, h1, lo1;
                split2(f.x, f.y, h0, lo0);
                split2(f.z, f.w, h1, lo1);
                int w0 = lhalf * 16 + i * 2;
                Kh[lrow * VSTR + w0]     = h0; Kl[lrow * VSTR + w0]     = lo0;
                Kh[lrow * VSTR + w0 + 1] = h1; Kl[lrow * VSTR + w0 + 1] = lo1;
            }
        }
        // ---- load V tile transposed: Vh[d][kv/2] ----
        {
            float vv[8][4];
#pragma unroll
            for (int i = 0; i < 8; i++)
                *(float4*)vv[i] = *(const float4*)(V + base +
                    (size_t)(t * 64 + kvg * 8 + i) * D_ + dgrp * 4);
#pragma unroll
            for (int dd = 0; dd < 4; dd++)
#pragma unroll
                for (int wi = 0; wi < 4; wi++) {
                    uint32_t h, l;
                    split2(vv[2 * wi][dd], vv[2 * wi + 1][dd], h, l);
                    Vh[(dgrp * 4 + dd) * VSTR + kvg * 4 + wi] = h;
                    Vl[(dgrp * 4 + dd) * VSTR + kvg * 4 + wi] = l;
                }
        }
        __syncthreads();

        // ---- S = Q K^T ----
        float sac[8][4];
#pragma unroll
        for (int nt = 0; nt < 8; nt++)
#pragma unroll
            for (int i = 0; i < 4; i++) sac[nt][i] = 0.f;

#pragma unroll
        for (int kf = 0; kf < 4; kf++) {
#pragma unroll
            for (int nt = 0; nt < 8; nt++) {
                int rn = nt * 8 + g;
                uint32_t bh[2] = { Kh[rn * VSTR + kf * 8 + j], Kh[rn * VSTR + kf * 8 + 4 + j] };
                uint32_t bl[2] = { Kl[rn * VSTR + kf * 8 + j], Kl[rn * VSTR + kf * 8 + 4 + j] };
                mma16816(sac[nt], Qh[kf], bh);
                mma16816(sac[nt], Ql[kf], bh);
                mma16816(sac[nt], Qh[kf], bl);
            }
        }

        // ---- online softmax (rows g and g+8) ----
        float mx0 = -INFINITY, mx1 = -INFINITY;
#pragma unroll
        for (int nt = 0; nt < 8; nt++) {
#pragma unroll
            for (int i = 0; i < 4; i++) sac[nt][i] *= 0.125f;
            mx0 = fmaxf(mx0, fmaxf(sac[nt][0], sac[nt][1]));
            mx1 = fmaxf(mx1, fmaxf(sac[nt][2], sac[nt][3]));
        }
#pragma unroll
        for (int off = 1; off <= 2; off <<= 1) {
            mx0 = fmaxf(mx0, __shfl_xor_sync(0xffffffffu, mx0, off));
            mx1 = fmaxf(mx1, __shfl_xor_sync(0xffffffffu, mx1, off));
        }
        float mn0 = fmaxf(m0, mx0), mn1 = fmaxf(m1, mx1);
        float al0 = __expf(m0 - mn0), al1 = __expf(m1 - mn1);
        m0 = mn0; m1 = mn1;

        float rs0 = 0.f, rs1 = 0.f;
#pragma unroll
        for (int nt = 0; nt < 8; nt++) {
            sac[nt][0] = __expf(sac[nt][0] - mn0);
            sac[nt][1] = __expf(sac[nt][1] - mn0);
            sac[nt][2] = __expf(sac[nt][2] - mn1);
            sac[nt][3] = __expf(sac[nt][3] - mn1);
            rs0 += sac[nt][0] + sac[nt][1];
            rs1 += sac[nt][2] + sac[nt][3];
        }
#pragma unroll
        for (int off = 1; off <= 2; off <<= 1) {
            rs0 += __shfl_xor_sync(0xffffffffu, rs0, off);
            rs1 += __shfl_xor_sync(0xffffffffu, rs1, off);
        }
        l0 = l0 * al0 + rs0;
        l1 = l1 * al1 + rs1;
#pragma unroll
        for (int nt = 0; nt < 8; nt++) {
            oac[nt][0] *= al0; oac[nt][1] *= al0;
            oac[nt][2] *= al1; oac[nt][3] *= al1;
        }

        // ---- O += P V : P fragments built in-register from sac ----
#pragma unroll
        for (int kf = 0; kf < 4; kf++) {
            uint32_t ph[4], pl[4];
            split2(sac[2 * kf][0],     sac[2 * kf][1],     ph[0], pl[0]);
            split2(sac[2 * kf][2],     sac[2 * kf][3],     ph[1], pl[1]);
            split2(sac[2 * kf + 1][0], sac[2 * kf + 1][1], ph[2], pl[2]);
            split2(sac[2 * kf + 1][2], sac[2 * kf + 1][3], ph[3], pl[3]);
#pragma unroll
            for (int nt = 0; nt < 8; nt++) {
                int rd = nt * 8 + g;
                uint32_t vh[2] = { Vh[rd * VSTR + kf * 8 + j], Vh[rd * VSTR + kf * 8 + 4 + j] };
                uint32_t vl[2] = { Vl[rd * VSTR + kf * 8 + j], Vl[rd * VSTR + kf * 8 + 4 + j] };
                mma16816(oac[nt], ph, vh);
                mma16816(oac[nt], pl, vh);
                mma16816(oac[nt], ph, vl);
            }
        }
        __syncthreads();
    }

    // ---- epilogue ----
    float inv0 = 1.f / l0, inv1 = 1.f / l1;
    int row = q0 + wid * 16 + g;
#pragma unroll
    for (int nt = 0; nt < 8; nt++) {
        int col = nt * 8 + j * 2;
        *(float2*)&O[base + (size_t)row * D_ + col] =
            make_float2(oac[nt][0] * inv0, oac[nt][1] * inv0);
        *(float2*)&O[base + (size_t)(row + 8) * D_ + col] =
            make_float2(oac[nt][2] * inv1, oac[nt][3] * inv1);
    }
}

// ---------------------------------------------------------------------------
// Readout: logits[b,v] = dot(h[b, T-1, :], R[v, :]) / sqrt(D)
// ---------------------------------------------------------------------------
__global__ void __launch_bounds__(256) readout_kernel(
    const float* __restrict__ hbuf, const float* __restrict__ R,
    float* __restrict__ out)
{
    __shared__ float hs[B_][D_];
    for (int i = threadIdx.x; i < B_ * D_; i += 256) {
        int b = i >> 9, d = i & 511;
        hs[b][d] = hbuf[((size_t)b * T_ + (T_ - 1)) * D_ + d];
    }
    __syncthreads();

    int v = blockIdx.x * 256 + threadIdx.x;
    float a0 = 0.f, a1 = 0.f, a2 = 0.f, a3 = 0.f;
    const float* r = R + (size_t)v * D_;
    for (int d = 0; d < D_; d += 4) {
        float4 rv = *(const float4*)(r + d);
        a0 += rv.x * hs[0][d] + rv.y * hs[0][d + 1] + rv.z * hs[0][d + 2] + rv.w * hs[0][d + 3];
        a1 += rv.x * hs[1][d] + rv.y * hs[1][d + 1] + rv.z * hs[1][d + 2] + rv.w * hs[1][d + 3];
        a2 += rv.x * hs[2][d] + rv.y * hs[2][d + 1] + rv.z * hs[2][d + 2] + rv.w * hs[2][d + 3];
        a3 += rv.x * hs[3][d] + rv.y * hs[3][d + 1] + rv.z * hs[3][d + 2] + rv.w * hs[3][d + 3];
    }
    const float sc = 0.04419417382415922f;  // 1/sqrt(512)
    out[0 * V_ + v] = a0 * sc;
    out[1 * V_ + v] = a1 * sc;
    out[2 * V_ + v] = a2 * sc;
    out[3 * V_ + v] = a3 * sc;
}

// ---------------------------------------------------------------------------
extern "C" void kernel_launch(void* const* d_in, const int* in_sizes, int n_in,
                              void* d_out, int out_size)
{
    const float* x  = (const float*)d_in[0];  // [B,T,V]
    const float* te = (const float*)d_in[1];  // [D,V]
    const float* pe = (const float*)d_in[2];  // [T,D]
    const float* Wk = (const float*)d_in[3];  // [L,D,D]
    const float* Wq = (const float*)d_in[4];
    const float* Wv = (const float*)d_in[5];
    const float* Wp = (const float*)d_in[6];
    const float* ro = (const float*)d_in[7];  // [V,D]
    float* out = (float*)d_out;               // [B,V]

    float *h, *q, *k, *v, *o;
    cudaGetSymbolAddress((void**)&h, g_h);
    cudaGetSymbolAddress((void**)&q, g_q);
    cudaGetSymbolAddress((void**)&k, g_k);
    cudaGetSymbolAddress((void**)&v, g_v);
    cudaGetSymbolAddress((void**)&o, g_o);

    const float sV = 0.022097086912079608f;  // 1/sqrt(2048)
    const float sD = 0.04419417382415922f;   // 1/sqrt(512)

    dim3 ggrid(D_ / 128, (B_ * T_) / 128);

    // h = x @ TE^T / sqrt(V) + pos
    gemm_nt_mma<<<ggrid, 256>>>(x, te, h, pe, B_ * T_, D_, V_, sV);

    for (int l = 0; l < L_; l++) {
        const float* wq = Wq + (size_t)l * D_ * D_;
        const float* wk = Wk + (size_t)l * D_ * D_;
        const float* wv = Wv + (size_t)l * D_ * D_;
        const float* wp = Wp + (size_t)l * D_ * D_;

        gemm_nt_mma<<<ggrid, 256>>>(h, wq, q, nullptr, B_ * T_, D_, D_, sD);
        gemm_nt_mma<<<ggrid, 256>>>(h, wk, k, nullptr, B_ * T_, D_, D_, sD);
        gemm_nt_mma<<<ggrid, 256>>>(h, wv, v, nullptr, B_ * T_, D_, D_, sD);

        attn_mma<<<dim3(T_ / 64, H_, B_), 128>>>(q, k, v, o);

        gemm_nt_mma<<<ggrid, 256>>>(o, wp, h, nullptr, B_ * T_, D_, D_, sD);
    }

    readout_kernel<<<V_ / 256, 256>>>(h, ro, out);
}

// round 4
// speedup vs baseline: 2.3352x; 1.4294x over previous
#include <cuda_runtime.h>
#include <cuda_bf16.h>
#include <math.h>
#include <stdint.h>

#define B_  4
#define T_  2048
#define V_  2048
#define D_  512
#define H_  8
#define L_  4
#define HD_ 64
#define NT_ (B_ * T_ * D_)   // 4M elems

// ---- global scratch (no allocation allowed) ----
__device__ __align__(16) float g_h[NT_];                       // fp32 h (for readout)
__device__ __align__(16) __nv_bfloat16 g_hh[NT_], g_hl[NT_];
__device__ __align__(16) __nv_bfloat16 g_qh[NT_], g_ql[NT_];
__device__ __align__(16) __nv_bfloat16 g_kh[NT_], g_kl[NT_];
__device__ __align__(16) __nv_bfloat16 g_vh[NT_], g_vl[NT_];
__device__ __align__(16) __nv_bfloat16 g_oh[NT_], g_ol[NT_];
__device__ __align__(16) __nv_bfloat16 g_xh[B_ * T_ * V_], g_xl[B_ * T_ * V_];
__device__ __align__(16) __nv_bfloat16 g_teh[D_ * V_], g_tel[D_ * V_];
__device__ __align__(16) __nv_bfloat16 g_wqh[L_ * D_ * D_], g_wql[L_ * D_ * D_];
__device__ __align__(16) __nv_bfloat16 g_wkh[L_ * D_ * D_], g_wkl[L_ * D_ * D_];
__device__ __align__(16) __nv_bfloat16 g_wvh[L_ * D_ * D_], g_wvl[L_ * D_ * D_];
__device__ __align__(16) __nv_bfloat16 g_wph[L_ * D_ * D_], g_wpl[L_ * D_ * D_];

// ---------------------------------------------------------------------------
__device__ __forceinline__ void split2(float x, float y, uint32_t& h, uint32_t& l)
{
    __nv_bfloat16 xh = __float2bfloat16_rn(x);
    __nv_bfloat16 yh = __float2bfloat16_rn(y);
    __nv_bfloat16 xl = __float2bfloat16_rn(x - __bfloat162float(xh));
    __nv_bfloat16 yl = __float2bfloat16_rn(y - __bfloat162float(yh));
    __nv_bfloat162 hv = __halves2bfloat162(xh, yh);
    __nv_bfloat162 lv = __halves2bfloat162(xl, yl);
    h = *reinterpret_cast<uint32_t*>(&hv);
    l = *reinterpret_cast<uint32_t*>(&lv);
}

__device__ __forceinline__ void mma16816(float* d, const uint32_t* a, const uint32_t* b)
{
    asm volatile(
        "mma.sync.aligned.m16n8k16.row.col.f32.bf16.bf16.f32 "
        "{%0,%1,%2,%3}, {%4,%5,%6,%7}, {%8,%9}, {%0,%1,%2,%3};\n"
        : "+f"(d[0]), "+f"(d[1]), "+f"(d[2]), "+f"(d[3])
        : "r"(a[0]), "r"(a[1]), "r"(a[2]), "r"(a[3]), "r"(b[0]), "r"(b[1]));
}

__device__ __forceinline__ void ldsm4(uint32_t* r, uint32_t addr)
{
    asm volatile("ldmatrix.sync.aligned.m8n8.x4.shared.b16 {%0,%1,%2,%3}, [%4];"
                 : "=r"(r[0]), "=r"(r[1]), "=r"(r[2]), "=r"(r[3]) : "r"(addr));
}
__device__ __forceinline__ void ldsm4t(uint32_t* r, uint32_t addr)
{
    asm volatile("ldmatrix.sync.aligned.m8n8.x4.trans.shared.b16 {%0,%1,%2,%3}, [%4];"
                 : "=r"(r[0]), "=r"(r[1]), "=r"(r[2]), "=r"(r[3]) : "r"(addr));
}

// ---------------------------------------------------------------------------
// fp32 -> bf16 hi/lo splitter (elementwise, n divisible by 4)
// ---------------------------------------------------------------------------
__global__ void __launch_bounds__(256) split_kernel(
    const float4* __restrict__ src, uint2* __restrict__ hi, uint2* __restrict__ lo, int n4)
{
    int i = blockIdx.x * 256 + threadIdx.x;
    if (i < n4) {
        float4 f = src[i];
        uint32_t h0, l0, h1, l1;
        split2(f.x, f.y, h0, l0);
        split2(f.z, f.w, h1, l1);
        hi[i] = make_uint2(h0, h1);
        lo[i] = make_uint2(l0, l1);
    }
}

// ---------------------------------------------------------------------------
// NT GEMM, bf16 hi/lo inputs: C = alpha * A @ B^T (+bias).
// 128x128x16 double-buffered, 8 warps, ldmatrix fragment loads.
// Outputs: optional fp32 Cf, optional bf16 hi/lo pair (Chi, Clo).
// ---------------------------------------------------------------------------
#define GST 24          // smem row stride in bf16 (48 bytes)
#define GBUF 3072       // 128 * 24 bf16 per (part, stage)

__global__ void __launch_bounds__(256) gemm_nt_bf16(
    const __nv_bfloat16* __restrict__ Ah, const __nv_bfloat16* __restrict__ Al,
    const __nv_bfloat16* __restrict__ Bh, const __nv_bfloat16* __restrict__ Bl,
    float* __restrict__ Cf, __nv_bfloat16* __restrict__ Chi, __nv_bfloat16* __restrict__ Clo,
    const float* __restrict__ bias, int M, int N, int K, float alpha)
{
    __shared__ __align__(16) __nv_bfloat16 sm[2][4][GBUF];  // [stage][Ah,Al,Bh,Bl] = 48KB

    const int tid  = threadIdx.x;
    const int lane = tid & 31;
    const int wid  = tid >> 5;
    const int wm   = (wid & 3) * 32;
    const int wn   = (wid >> 2) * 64;
    const int bm   = blockIdx.y * 128;
    const int bn   = blockIdx.x * 128;
    const int g    = lane >> 2;
    const int j    = lane & 3;

    const int lrow  = tid >> 1;
    const int lhalf = tid & 1;
    const __nv_bfloat16* pAh = Ah + (size_t)(bm + lrow) * K + lhalf * 8;
    const __nv_bfloat16* pAl = Al + (size_t)(bm + lrow) * K + lhalf * 8;
    const __nv_bfloat16* pBh = Bh + (size_t)(bn + lrow) * K + lhalf * 8;
    const __nv_bfloat16* pBl = Bl + (size_t)(bn + lrow) * K + lhalf * 8;
    const int sidx = lrow * GST + lhalf * 8;  // bf16 index into each part buffer

    // ldmatrix per-lane byte offsets (within a part buffer)
    const int lr8  = (lane & 7) + ((lane >> 3) & 1) * 8;
    const int lc16 = (lane >> 4) * 16;
    const uint32_t smbase = (uint32_t)__cvta_generic_to_shared(&sm[0][0][0]);
    uint32_t offA[2], offB[4];
#pragma unroll
    for (int mt = 0; mt < 2; mt++) offA[mt] = (wm + mt * 16 + lr8) * 48 + lc16;
#pragma unroll
    for (int np = 0; np < 4; np++) offB[np] = (wn + np * 16 + lr8) * 48 + lc16;

    float acc[2][8][4];
#pragma unroll
    for (int mt = 0; mt < 2; mt++)
#pragma unroll
        for (int nt = 0; nt < 8; nt++)
#pragma unroll
            for (int i = 0; i < 4; i++) acc[mt][nt][i] = 0.f;

    const int KT = K >> 4;

    // prologue: stage 0
    {
        *(uint4*)&sm[0][0][sidx] = *(const uint4*)pAh;
        *(uint4*)&sm[0][1][sidx] = *(const uint4*)pAl;
        *(uint4*)&sm[0][2][sidx] = *(const uint4*)pBh;
        *(uint4*)&sm[0][3][sidx] = *(const uint4*)pBl;
    }
    __syncthreads();

    for (int ks = 0; ks < KT; ks++) {
        const int cur = ks & 1, nxt = cur ^ 1;

        uint4 rah, ral, rbh, rbl;
        if (ks + 1 < KT) {
            int k0 = (ks + 1) << 4;
            rah = *(const uint4*)(pAh + k0);
            ral = *(const uint4*)(pAl + k0);
            rbh = *(const uint4*)(pBh + k0);
            rbl = *(const uint4*)(pBl + k0);
        }

        const uint32_t sb = smbase + cur * (4 * GBUF * 2);
        uint32_t fah[2][4], fal[2][4];
#pragma unroll
        for (int mt = 0; mt < 2; mt++) {
            ldsm4(fah[mt], sb + 0 * (GBUF * 2) + offA[mt]);
            ldsm4(fal[mt], sb + 1 * (GBUF * 2) + offA[mt]);
        }
#pragma unroll
        for (int np = 0; np < 4; np++) {
            uint32_t bh[4], bl[4];
            ldsm4(bh, sb + 2 * (GBUF * 2) + offB[np]);
            ldsm4(bl, sb + 3 * (GBUF * 2) + offB[np]);
            uint32_t bA_h[2] = { bh[0], bh[2] }, bB_h[2] = { bh[1], bh[3] };
            uint32_t bA_l[2] = { bl[0], bl[2] }, bB_l[2] = { bl[1], bl[3] };
#pragma unroll
            for (int mt = 0; mt < 2; mt++) {
                mma16816(acc[mt][np * 2],     fah[mt], bA_h);
                mma16816(acc[mt][np * 2],     fal[mt], bA_h);
                mma16816(acc[mt][np * 2],     fah[mt], bA_l);
                mma16816(acc[mt][np * 2 + 1], fah[mt], bB_h);
                mma16816(acc[mt][np * 2 + 1], fal[mt], bB_h);
                mma16816(acc[mt][np * 2 + 1], fah[mt], bB_l);
            }
        }

        if (ks + 1 < KT) {
            *(uint4*)&sm[nxt][0][sidx] = rah;
            *(uint4*)&sm[nxt][1][sidx] = ral;
            *(uint4*)&sm[nxt][2][sidx] = rbh;
            *(uint4*)&sm[nxt][3][sidx] = rbl;
        }
        __syncthreads();
    }

    // epilogue
#pragma unroll
    for (int mt = 0; mt < 2; mt++) {
#pragma unroll
        for (int nt = 0; nt < 8; nt++) {
            int row = bm + wm + mt * 16 + g;
            int col = bn + wn + nt * 8 + j * 2;
            float2 v0 = make_float2(acc[mt][nt][0] * alpha, acc[mt][nt][1] * alpha);
            float2 v1 = make_float2(acc[mt][nt][2] * alpha, acc[mt][nt][3] * alpha);
            if (bias) {
                const float* b0 = bias + (size_t)(row & (T_ - 1)) * N + col;
                const float* b1 = bias + (size_t)((row + 8) & (T_ - 1)) * N + col;
                v0.x += b0[0]; v0.y += b0[1];
                v1.x += b1[0]; v1.y += b1[1];
            }
            size_t i0 = (size_t)row * N + col;
            size_t i1 = (size_t)(row + 8) * N + col;
            if (Cf) {
                *(float2*)&Cf[i0] = v0;
                *(float2*)&Cf[i1] = v1;
            }
            if (Chi) {
                uint32_t h, l;
                split2(v0.x, v0.y, h, l);
                *(uint32_t*)&Chi[i0] = h; *(uint32_t*)&Clo[i0] = l;
                split2(v1.x, v1.y, h, l);
                *(uint32_t*)&Chi[i1] = h; *(uint32_t*)&Clo[i1] = l;
            }
        }
    }
}

// ---------------------------------------------------------------------------
// Flash attention, bf16 hi/lo in, bf16 hi/lo out. BQ=128, BKV=64, 8 warps.
// K: non-trans ldmatrix; V: ldmatrix.trans; P from S accumulators in-register.
// ---------------------------------------------------------------------------
#define ASTR 72   // smem row stride in bf16 (144 bytes)

__global__ void __launch_bounds__(256) attn_bf16(
    const __nv_bfloat16* __restrict__ Qh, const __nv_bfloat16* __restrict__ Ql,
    const __nv_bfloat16* __restrict__ Kh, const __nv_bfloat16* __restrict__ Kl,
    const __nv_bfloat16* __restrict__ Vh, const __nv_bfloat16* __restrict__ Vl,
    __nv_bfloat16* __restrict__ Ohi, __nv_bfloat16* __restrict__ Olo)
{
    __shared__ __align__(16) __nv_bfloat16 sKh[64 * ASTR], sKl[64 * ASTR];
    __shared__ __align__(16) __nv_bfloat16 sVh[64 * ASTR], sVl[64 * ASTR];

    const int tid  = threadIdx.x;
    const int lane = tid & 31;
    const int wid  = tid >> 5;
    const int g    = lane >> 2;
    const int j    = lane & 3;

    const int q0 = blockIdx.x * 128;
    const int hh = blockIdx.y;
    const int bb = blockIdx.z;
    const size_t base = ((size_t)bb * T_) * D_ + (size_t)hh * HD_;

    // ---- Q fragments from global (register resident) ----
    uint32_t Qfh[4][4], Qfl[4][4];
    {
        const uint32_t* qh32 = (const uint32_t*)(Qh + base);
        const uint32_t* ql32 = (const uint32_t*)(Ql + base);
        int r0 = q0 + wid * 16 + g;
#pragma unroll
        for (int kf = 0; kf < 4; kf++) {
            int w0 = kf * 8 + j, w1 = kf * 8 + 4 + j;
            Qfh[kf][0] = qh32[(size_t)r0 * (D_ / 2) + w0];
            Qfh[kf][1] = qh32[(size_t)(r0 + 8) * (D_ / 2) + w0];
            Qfh[kf][2] = qh32[(size_t)r0 * (D_ / 2) + w1];
            Qfh[kf][3] = qh32[(size_t)(r0 + 8) * (D_ / 2) + w1];
            Qfl[kf][0] = ql32[(size_t)r0 * (D_ / 2) + w0];
            Qfl[kf][1] = ql32[(size_t)(r0 + 8) * (D_ / 2) + w0];
            Qfl[kf][2] = ql32[(size_t)r0 * (D_ / 2) + w1];
            Qfl[kf][3] = ql32[(size_t)(r0 + 8) * (D_ / 2) + w1];
        }
    }

    const int lr8  = (lane & 7) + ((lane >> 3) & 1) * 8;
    const int lc16 = (lane >> 4) * 16;
    const uint32_t kh_b = (uint32_t)__cvta_generic_to_shared(sKh);
    const uint32_t kl_b = (uint32_t)__cvta_generic_to_shared(sKl);
    const uint32_t vh_b = (uint32_t)__cvta_generic_to_shared(sVh);
    const uint32_t vl_b = (uint32_t)__cvta_generic_to_shared(sVl);

    float oac[8][4];
#pragma unroll
    for (int nt = 0; nt < 8; nt++)
#pragma unroll
        for (int i = 0; i < 4; i++) oac[nt][i] = 0.f;
    float m0 = -INFINITY, m1 = -INFINITY, l0 = 0.f, l1 = 0.f;

    const int ldrow = tid >> 2;       // 0..63
    const int ldc   = tid & 3;        // chunk 0..3 (+4)

    for (int t = 0; t < T_ / 64; t++) {
        __syncthreads();  // previous iter done reading smem

        // ---- load K/V tiles (64 x 64 bf16 each part) ----
        {
            size_t grow = base + (size_t)(t * 64 + ldrow) * D_;
            const uint4* gkh = (const uint4*)(Kh + grow);
            const uint4* gkl = (const uint4*)(Kl + grow);
            const uint4* gvh = (const uint4*)(Vh + grow);
            const uint4* gvl = (const uint4*)(Vl + grow);
            int s0 = ldrow * ASTR + ldc * 8;
            int s1 = ldrow * ASTR + (ldc + 4) * 8;
            *(uint4*)&sKh[s0] = gkh[ldc];     *(uint4*)&sKh[s1] = gkh[ldc + 4];
            *(uint4*)&sKl[s0] = gkl[ldc];     *(uint4*)&sKl[s1] = gkl[ldc + 4];
            *(uint4*)&sVh[s0] = gvh[ldc];     *(uint4*)&sVh[s1] = gvh[ldc + 4];
            *(uint4*)&sVl[s0] = gvl[ldc];     *(uint4*)&sVl[s1] = gvl[ldc + 4];
        }
        __syncthreads();

        // ---- S = Q K^T ----
        float sac[8][4];
#pragma unroll
        for (int nt = 0; nt < 8; nt++)
#pragma unroll
            for (int i = 0; i < 4; i++) sac[nt][i] = 0.f;

#pragma unroll
        for (int kf = 0; kf < 4; kf++) {
#pragma unroll
            for (int np = 0; np < 4; np++) {
                uint32_t off = (np * 16 + lr8) * 144 + kf * 32 + lc16;
                uint32_t bh[4], bl[4];
                ldsm4(bh, kh_b + off);
                ldsm4(bl, kl_b + off);
                uint32_t bA_h[2] = { bh[0], bh[2] }, bB_h[2] = { bh[1], bh[3] };
                uint32_t bA_l[2] = { bl[0], bl[2] }, bB_l[2] = { bl[1], bl[3] };
                mma16816(sac[np * 2],     Qfh[kf], bA_h);
                mma16816(sac[np * 2],     Qfl[kf], bA_h);
                mma16816(sac[np * 2],     Qfh[kf], bA_l);
                mma16816(sac[np * 2 + 1], Qfh[kf], bB_h);
                mma16816(sac[np * 2 + 1], Qfl[kf], bB_h);
                mma16816(sac[np * 2 + 1], Qfh[kf], bB_l);
            }
        }

        // ---- online softmax (rows g and g+8 within warp's 16 rows) ----
        float mx0 = -INFINITY, mx1 = -INFINITY;
#pragma unroll
        for (int nt = 0; nt < 8; nt++) {
#pragma unroll
            for (int i = 0; i < 4; i++) sac[nt][i] *= 0.125f;
            mx0 = fmaxf(mx0, fmaxf(sac[nt][0], sac[nt][1]));
            mx1 = fmaxf(mx1, fmaxf(sac[nt][2], sac[nt][3]));
        }
#pragma unroll
        for (int off = 1; off <= 2; off <<= 1) {
            mx0 = fmaxf(mx0, __shfl_xor_sync(0xffffffffu, mx0, off));
            mx1 = fmaxf(mx1, __shfl_xor_sync(0xffffffffu, mx1, off));
        }
        float mn0 = fmaxf(m0, mx0), mn1 = fmaxf(m1, mx1);
        float al0 = __expf(m0 - mn0), al1 = __expf(m1 - mn1);
        m0 = mn0; m1 = mn1;

        float rs0 = 0.f, rs1 = 0.f;
#pragma unroll
        for (int nt = 0; nt < 8; nt++) {
            sac[nt][0] = __expf(sac[nt][0] - mn0);
            sac[nt][1] = __expf(sac[nt][1] - mn0);
            sac[nt][2] = __expf(sac[nt][2] - mn1);
            sac[nt][3] = __expf(sac[nt][3] - mn1);
            rs0 += sac[nt][0] + sac[nt][1];
            rs1 += sac[nt][2] + sac[nt][3];
        }
#pragma unroll
        for (int off = 1; off <= 2; off <<= 1) {
            rs0 += __shfl_xor_sync(0xffffffffu, rs0, off);
            rs1 += __shfl_xor_sync(0xffffffffu, rs1, off);
        }
        l0 = l0 * al0 + rs0;
        l1 = l1 * al1 + rs1;
#pragma unroll
        for (int nt = 0; nt < 8; nt++) {
            oac[nt][0] *= al0; oac[nt][1] *= al0;
            oac[nt][2] *= al1; oac[nt][3] *= al1;
        }

        // ---- O += P V (V via ldmatrix.trans; P split in-register) ----
#pragma unroll
        for (int kf = 0; kf < 4; kf++) {
            uint32_t ph[4], pl[4];
            split2(sac[2 * kf][0],     sac[2 * kf][1],     ph[0], pl[0]);
            split2(sac[2 * kf][2],     sac[2 * kf][3],     ph[1], pl[1]);
            split2(sac[2 * kf + 1][0], sac[2 * kf + 1][1], ph[2], pl[2]);
            split2(sac[2 * kf + 1][2], sac[2 * kf + 1][3], ph[3], pl[3]);
#pragma unroll
            for (int np = 0; np < 4; np++) {
                uint32_t off = (kf * 16 + lr8) * 144 + np * 32 + lc16;
                uint32_t vh[4], vl[4];
                ldsm4t(vh, vh_b + off);
                ldsm4t(vl, vl_b + off);
                uint32_t vA_h[2] = { vh[0], vh[1] }, vB_h[2] = { vh[2], vh[3] };
                uint32_t vA_l[2] = { vl[0], vl[1] }, vB_l[2] = { vl[2], vl[3] };
                mma16816(oac[np * 2],     ph, vA_h);
                mma16816(oac[np * 2],     pl, vA_h);
                mma16816(oac[np * 2],     ph, vA_l);
                mma16816(oac[np * 2 + 1], ph, vB_h);
                mma16816(oac[np * 2 + 1], pl, vB_h);
                mma16816(oac[np * 2 + 1], ph, vB_l);
            }
        }
    }

    // ---- epilogue: normalize + split to bf16 hi/lo ----
    float inv0 = 1.f / l0, inv1 = 1.f / l1;
    int row = q0 + wid * 16 + g;
    uint32_t* oh32 = (uint32_t*)(Ohi + base);
    uint32_t* ol32 = (uint32_t*)(Olo + base);
#pragma unroll
    for (int nt = 0; nt < 8; nt++) {
        int w = nt * 4 + j;
        uint32_t h, l;
        split2(oac[nt][0] * inv0, oac[nt][1] * inv0, h, l);
        oh32[(size_t)row * (D_ / 2) + w] = h;
        ol32[(size_t)row * (D_ / 2) + w] = l;
        split2(oac[nt][2] * inv1, oac[nt][3] * inv1, h, l);
        oh32[(size_t)(row + 8) * (D_ / 2) + w] = h;
        ol32[(size_t)(row + 8) * (D_ / 2) + w] = l;
    }
}

// ---------------------------------------------------------------------------
// Readout: logits[b,v] = dot(h[b, T-1, :], R[v, :]) / sqrt(D)
// ---------------------------------------------------------------------------
__global__ void __launch_bounds__(256) readout_kernel(
    const float* __restrict__ hbuf, const float* __restrict__ R,
    float* __restrict__ out)
{
    __shared__ float hs[B_][D_];
    for (int i = threadIdx.x; i < B_ * D_; i += 256) {
        int b = i >> 9, d = i & 511;
        hs[b][d] = hbuf[((size_t)b * T_ + (T_ - 1)) * D_ + d];
    }
    __syncthreads();

    int v = blockIdx.x * 256 + threadIdx.x;
    float a0 = 0.f, a1 = 0.f, a2 = 0.f, a3 = 0.f;
    const float* r = R + (size_t)v * D_;
    for (int d = 0; d < D_; d += 4) {
        float4 rv = *(const float4*)(r + d);
        a0 += rv.x * hs[0][d] + rv.y * hs[0][d + 1] + rv.z * hs[0][d + 2] + rv.w * hs[0][d + 3];
        a1 += rv.x * hs[1][d] + rv.y * hs[1][d + 1] + rv.z * hs[1][d + 2] + rv.w * hs[1][d + 3];
        a2 += rv.x * hs[2][d] + rv.y * hs[2][d + 1] + rv.z * hs[2][d + 2] + rv.w * hs[2][d + 3];
        a3 += rv.x * hs[3][d] + rv.y * hs[3][d + 1] + rv.z * hs[3][d + 2] + rv.w * hs[3][d + 3];
    }
    const float sc = 0.04419417382415922f;  // 1/sqrt(512)
    out[0 * V_ + v] = a0 * sc;
    out[1 * V_ + v] = a1 * sc;
    out[2 * V_ + v] = a2 * sc;
    out[3 * V_ + v] = a3 * sc;
}

// ---------------------------------------------------------------------------
extern "C" void kernel_launch(void* const* d_in, const int* in_sizes, int n_in,
                              void* d_out, int out_size)
{
    const float* x  = (const float*)d_in[0];
    const float* te = (const float*)d_in[1];
    const float* pe = (const float*)d_in[2];
    const float* Wk = (const float*)d_in[3];
    const float* Wq = (const float*)d_in[4];
    const float* Wv = (const float*)d_in[5];
    const float* Wp = (const float*)d_in[6];
    const float* ro = (const float*)d_in[7];
    float* out = (float*)d_out;

    float* hf;
    __nv_bfloat16 *hh, *hl, *qh, *ql, *kh, *kl, *vh, *vl, *oh, *ol;
    __nv_bfloat16 *xh, *xl, *teh, *tel;
    __nv_bfloat16 *wqh, *wql, *wkh, *wkl, *wvh, *wvl, *wph, *wpl;
    cudaGetSymbolAddress((void**)&hf,  g_h);
    cudaGetSymbolAddress((void**)&hh,  g_hh);  cudaGetSymbolAddress((void**)&hl, g_hl);
    cudaGetSymbolAddress((void**)&qh,  g_qh);  cudaGetSymbolAddress((void**)&ql, g_ql);
    cudaGetSymbolAddress((void**)&kh,  g_kh);  cudaGetSymbolAddress((void**)&kl, g_kl);
    cudaGetSymbolAddress((void**)&vh,  g_vh);  cudaGetSymbolAddress((void**)&vl, g_vl);
    cudaGetSymbolAddress((void**)&oh,  g_oh);  cudaGetSymbolAddress((void**)&ol, g_ol);
    cudaGetSymbolAddress((void**)&xh,  g_xh);  cudaGetSymbolAddress((void**)&xl, g_xl);
    cudaGetSymbolAddress((void**)&teh, g_teh); cudaGetSymbolAddress((void**)&tel, g_tel);
    cudaGetSymbolAddress((void**)&wqh, g_wqh); cudaGetSymbolAddress((void**)&wql, g_wql);
    cudaGetSymbolAddress((void**)&wkh, g_wkh); cudaGetSymbolAddress((void**)&wkl, g_wkl);
    cudaGetSymbolAddress((void**)&wvh, g_wvh); cudaGetSymbolAddress((void**)&wvl, g_wvl);
    cudaGetSymbolAddress((void**)&wph, g_wph); cudaGetSymbolAddress((void**)&wpl, g_wpl);

    const float sV = 0.022097086912079608f;  // 1/sqrt(2048)
    const float sD = 0.04419417382415922f;   // 1/sqrt(512)

    // ---- pre-split all static operands ----
    {
        int n4 = (B_ * T_ * V_) / 4;
        split_kernel<<<(n4 + 255) / 256, 256>>>((const float4*)x, (uint2*)xh, (uint2*)xl, n4);
        n4 = (D_ * V_) / 4;
        split_kernel<<<(n4 + 255) / 256, 256>>>((const float4*)te, (uint2*)teh, (uint2*)tel, n4);
        n4 = (L_ * D_ * D_) / 4;
        split_kernel<<<(n4 + 255) / 256, 256>>>((const float4*)Wq, (uint2*)wqh, (uint2*)wql, n4);
        split_kernel<<<(n4 + 255) / 256, 256>>>((const float4*)Wk, (uint2*)wkh, (uint2*)wkl, n4);
        split_kernel<<<(n4 + 255) / 256, 256>>>((const float4*)Wv, (uint2*)wvh, (uint2*)wvl, n4);
        split_kernel<<<(n4 + 255) / 256, 256>>>((const float4*)Wp, (uint2*)wph, (uint2*)wpl, n4);
    }

    dim3 ggrid(D_ / 128, (B_ * T_) / 128);

    // embed: h = x @ TE^T / sqrt(V) + pos  (writes bf16 hi/lo only)
    gemm_nt_bf16<<<ggrid, 256>>>(xh, xl, teh, tel,
                                 nullptr, hh, hl, pe, B_ * T_, D_, V_, sV);

    for (int l = 0; l < L_; l++) {
        size_t wo = (size_t)l * D_ * D_;
        gemm_nt_bf16<<<ggrid, 256>>>(hh, hl, wqh + wo, wql + wo,
                                     nullptr, qh, ql, nullptr, B_ * T_, D_, D_, sD);
        gemm_nt_bf16<<<ggrid, 256>>>(hh, hl, wkh + wo, wkl + wo,
                                     nullptr, kh, kl, nullptr, B_ * T_, D_, D_, sD);
        gemm_nt_bf16<<<ggrid, 256>>>(hh, hl, wvh + wo, wvl + wo,
                                     nullptr, vh, vl, nullptr, B_ * T_, D_, D_, sD);

        attn_bf16<<<dim3(T_ / 128, H_, B_), 256>>>(qh, ql, kh, kl, vh, vl, oh, ol);

        gemm_nt_bf16<<<ggrid, 256>>>(oh, ol, wph + wo, wpl + wo,
                                     hf, hh, hl, nullptr, B_ * T_, D_, D_, sD);
    }

    readout_kernel<<<V_ / 256, 256>>>(hf, ro, out);
}

// round 6
// speedup vs baseline: 2.4771x; 1.0607x over previous
#include <cuda_runtime.h>
#include <cuda_bf16.h>
#include <math.h>
#include <stdint.h>

#define B_  4
#define T_  2048
#define V_  2048
#define D_  512
#define H_  8
#define L_  4
#define HD_ 64
#define NT_ (B_ * T_ * D_)   // 4M elems

// ---- global scratch (no allocation allowed) ----
__device__ __align__(16) float g_h[NT_];                       // fp32 h (for readout)
__device__ __align__(16) __nv_bfloat16 g_hh[NT_], g_hl[NT_];
__device__ __align__(16) __nv_bfloat16 g_qh[NT_], g_ql[NT_];
__device__ __align__(16) __nv_bfloat16 g_kh[NT_], g_kl[NT_];
__device__ __align__(16) __nv_bfloat16 g_vh[NT_], g_vl[NT_];
__device__ __align__(16) __nv_bfloat16 g_oh[NT_], g_ol[NT_];
__device__ __align__(16) __nv_bfloat16 g_xh[B_ * T_ * V_], g_xl[B_ * T_ * V_];
__device__ __align__(16) __nv_bfloat16 g_teh[D_ * V_], g_tel[D_ * V_];
__device__ __align__(16) __nv_bfloat16 g_wqh[L_ * D_ * D_], g_wql[L_ * D_ * D_];
__device__ __align__(16) __nv_bfloat16 g_wkh[L_ * D_ * D_], g_wkl[L_ * D_ * D_];
__device__ __align__(16) __nv_bfloat16 g_wvh[L_ * D_ * D_], g_wvl[L_ * D_ * D_];
__device__ __align__(16) __nv_bfloat16 g_wph[L_ * D_ * D_], g_wpl[L_ * D_ * D_];

// ---------------------------------------------------------------------------
__device__ __forceinline__ void split2(float x, float y, uint32_t& h, uint32_t& l)
{
    __nv_bfloat16 xh = __float2bfloat16_rn(x);
    __nv_bfloat16 yh = __float2bfloat16_rn(y);
    __nv_bfloat16 xl = __float2bfloat16_rn(x - __bfloat162float(xh));
    __nv_bfloat16 yl = __float2bfloat16_rn(y - __bfloat162float(yh));
    __nv_bfloat162 hv = __halves2bfloat162(xh, yh);
    __nv_bfloat162 lv = __halves2bfloat162(xl, yl);
    h = *reinterpret_cast<uint32_t*>(&hv);
    l = *reinterpret_cast<uint32_t*>(&lv);
}

__device__ __forceinline__ void mma16816(float* d, const uint32_t* a, const uint32_t* b)
{
    asm volatile(
        "mma.sync.aligned.m16n8k16.row.col.f32.bf16.bf16.f32 "
        "{%0,%1,%2,%3}, {%4,%5,%6,%7}, {%8,%9}, {%0,%1,%2,%3};\n"
        : "+f"(d[0]), "+f"(d[1]), "+f"(d[2]), "+f"(d[3])
        : "r"(a[0]), "r"(a[1]), "r"(a[2]), "r"(a[3]), "r"(b[0]), "r"(b[1]));
}

__device__ __forceinline__ void ldsm4(uint32_t* r, uint32_t addr)
{
    asm volatile("ldmatrix.sync.aligned.m8n8.x4.shared.b16 {%0,%1,%2,%3}, [%4];"
                 : "=r"(r[0]), "=r"(r[1]), "=r"(r[2]), "=r"(r[3]) : "r"(addr));
}
__device__ __forceinline__ void ldsm4t(uint32_t* r, uint32_t addr)
{
    asm volatile("ldmatrix.sync.aligned.m8n8.x4.trans.shared.b16 {%0,%1,%2,%3}, [%4];"
                 : "=r"(r[0]), "=r"(r[1]), "=r"(r[2]), "=r"(r[3]) : "r"(addr));
}

__device__ __forceinline__ uint32_t smem_u32(const void* p)
{
    uint32_t a;
    asm("{ .reg .u64 t; cvta.to.shared.u64 t, %1; cvt.u32.u64 %0, t; }" : "=r"(a) : "l"(p));
    return a;
}

__device__ __forceinline__ void cp16(uint32_t saddr, const void* gaddr)
{
    asm volatile("cp.async.cg.shared.global [%0], [%1], 16;" :: "r"(saddr), "l"(gaddr));
}

// ---------------------------------------------------------------------------
// fp32 -> bf16 hi/lo splitter
// ---------------------------------------------------------------------------
__global__ void __launch_bounds__(256) split_kernel(
    const float4* __restrict__ src, uint2* __restrict__ hi, uint2* __restrict__ lo, int n4)
{
    int i = blockIdx.x * 256 + threadIdx.x;
    if (i < n4) {
        float4 f = src[i];
        uint32_t h0, l0, h1, l1;
        split2(f.x, f.y, h0, l0);
        split2(f.z, f.w, h1, l1);
        hi[i] = make_uint2(h0, h1);
        lo[i] = make_uint2(l0, l1);
    }
}

// ---------------------------------------------------------------------------
// NT GEMM, bf16 hi/lo inputs (mma.sync, proven at ~35us for 8192x512x512)
// ---------------------------------------------------------------------------
#define GST 24          // smem row stride in bf16 (48 bytes)
#define GBUF 3072       // 128 * 24 bf16 per (part, stage)

__global__ void __launch_bounds__(256) gemm_nt_bf16(
    const __nv_bfloat16* __restrict__ Ah, const __nv_bfloat16* __restrict__ Al,
    const __nv_bfloat16* __restrict__ Bh, const __nv_bfloat16* __restrict__ Bl,
    float* __restrict__ Cf, __nv_bfloat16* __restrict__ Chi, __nv_bfloat16* __restrict__ Clo,
    const float* __restrict__ bias, int M, int N, int K, float alpha)
{
    __shared__ __align__(16) __nv_bfloat16 sm[2][4][GBUF];  // 48KB

    const int tid  = threadIdx.x;
    const int lane = tid & 31;
    const int wid  = tid >> 5;
    const int wm   = (wid & 3) * 32;
    const int wn   = (wid >> 2) * 64;
    const int bm   = blockIdx.y * 128;
    const int bn   = blockIdx.x * 128;
    const int g    = lane >> 2;
    const int j    = lane & 3;

    const int lrow  = tid >> 1;
    const int lhalf = tid & 1;
    const __nv_bfloat16* pAh = Ah + (size_t)(bm + lrow) * K + lhalf * 8;
    const __nv_bfloat16* pAl = Al + (size_t)(bm + lrow) * K + lhalf * 8;
    const __nv_bfloat16* pBh = Bh + (size_t)(bn + lrow) * K + lhalf * 8;
    const __nv_bfloat16* pBl = Bl + (size_t)(bn + lrow) * K + lhalf * 8;
    const int sidx = lrow * GST + lhalf * 8;

    const int lr8  = (lane & 7) + ((lane >> 3) & 1) * 8;
    const int lc16 = (lane >> 4) * 16;
    const uint32_t smbase = smem_u32(&sm[0][0][0]);
    uint32_t offA[2], offB[4];
#pragma unroll
    for (int mt = 0; mt < 2; mt++) offA[mt] = (wm + mt * 16 + lr8) * 48 + lc16;
#pragma unroll
    for (int np = 0; np < 4; np++) offB[np] = (wn + np * 16 + lr8) * 48 + lc16;

    float acc[2][8][4];
#pragma unroll
    for (int mt = 0; mt < 2; mt++)
#pragma unroll
        for (int nt = 0; nt < 8; nt++)
#pragma unroll
            for (int i = 0; i < 4; i++) acc[mt][nt][i] = 0.f;

    const int KT = K >> 4;

    {
        *(uint4*)&sm[0][0][sidx] = *(const uint4*)pAh;
        *(uint4*)&sm[0][1][sidx] = *(const uint4*)pAl;
        *(uint4*)&sm[0][2][sidx] = *(const uint4*)pBh;
        *(uint4*)&sm[0][3][sidx] = *(const uint4*)pBl;
    }
    __syncthreads();

    for (int ks = 0; ks < KT; ks++) {
        const int cur = ks & 1, nxt = cur ^ 1;

        uint4 rah, ral, rbh, rbl;
        if (ks + 1 < KT) {
            int k0 = (ks + 1) << 4;
            rah = *(const uint4*)(pAh + k0);
            ral = *(const uint4*)(pAl + k0);
            rbh = *(const uint4*)(pBh + k0);
            rbl = *(const uint4*)(pBl + k0);
        }

        const uint32_t sb = smbase + cur * (4 * GBUF * 2);
        uint32_t fah[2][4], fal[2][4];
#pragma unroll
        for (int mt = 0; mt < 2; mt++) {
            ldsm4(fah[mt], sb + 0 * (GBUF * 2) + offA[mt]);
            ldsm4(fal[mt], sb + 1 * (GBUF * 2) + offA[mt]);
        }
#pragma unroll
        for (int np = 0; np < 4; np++) {
            uint32_t bh[4], bl[4];
            ldsm4(bh, sb + 2 * (GBUF * 2) + offB[np]);
            ldsm4(bl, sb + 3 * (GBUF * 2) + offB[np]);
            uint32_t bA_h[2] = { bh[0], bh[2] }, bB_h[2] = { bh[1], bh[3] };
            uint32_t bA_l[2] = { bl[0], bl[2] }, bB_l[2] = { bl[1], bl[3] };
#pragma unroll
            for (int mt = 0; mt < 2; mt++) {
                mma16816(acc[mt][np * 2],     fah[mt], bA_h);
                mma16816(acc[mt][np * 2],     fal[mt], bA_h);
                mma16816(acc[mt][np * 2],     fah[mt], bA_l);
                mma16816(acc[mt][np * 2 + 1], fah[mt], bB_h);
                mma16816(acc[mt][np * 2 + 1], fal[mt], bB_h);
                mma16816(acc[mt][np * 2 + 1], fah[mt], bB_l);
            }
        }

        if (ks + 1 < KT) {
            *(uint4*)&sm[nxt][0][sidx] = rah;
            *(uint4*)&sm[nxt][1][sidx] = ral;
            *(uint4*)&sm[nxt][2][sidx] = rbh;
            *(uint4*)&sm[nxt][3][sidx] = rbl;
        }
        __syncthreads();
    }

#pragma unroll
    for (int mt = 0; mt < 2; mt++) {
#pragma unroll
        for (int nt = 0; nt < 8; nt++) {
            int row = bm + wm + mt * 16 + g;
            int col = bn + wn + nt * 8 + j * 2;
            float2 v0 = make_float2(acc[mt][nt][0] * alpha, acc[mt][nt][1] * alpha);
            float2 v1 = make_float2(acc[mt][nt][2] * alpha, acc[mt][nt][3] * alpha);
            if (bias) {
                const float* b0 = bias + (size_t)(row & (T_ - 1)) * N + col;
                const float* b1 = bias + (size_t)((row + 8) & (T_ - 1)) * N + col;
                v0.x += b0[0]; v0.y += b0[1];
                v1.x += b1[0]; v1.y += b1[1];
            }
            size_t i0 = (size_t)row * N + col;
            size_t i1 = (size_t)(row + 8) * N + col;
            if (Cf) {
                *(float2*)&Cf[i0] = v0;
                *(float2*)&Cf[i1] = v1;
            }
            if (Chi) {
                uint32_t h, l;
                split2(v0.x, v0.y, h, l);
                *(uint32_t*)&Chi[i0] = h; *(uint32_t*)&Clo[i0] = l;
                split2(v1.x, v1.y, h, l);
                *(uint32_t*)&Chi[i1] = h; *(uint32_t*)&Clo[i1] = l;
            }
        }
    }
}

// ---------------------------------------------------------------------------
// Flash attention, cp.async double-buffered K/V stages (dynamic smem 73.7KB).
// BQ=128, BKV=64, 8 warps. Q frags register-resident; P from S accumulators.
// ---------------------------------------------------------------------------
#define ASTR       72                 // bf16 row stride (144 bytes)
#define A_ARR      9216               // bytes per array (64 rows * 144B)
#define A_STAGE    (4 * A_ARR)        // Kh,Kl,Vh,Vl per stage = 36864B
#define A_SMEM     (2 * A_STAGE)      // 73728B

extern __shared__ char attnsmem[];

__device__ __forceinline__ void attn_issue(
    uint32_t sbase, int s,
    const __nv_bfloat16* Kh, const __nv_bfloat16* Kl,
    const __nv_bfloat16* Vh, const __nv_bfloat16* Vl,
    size_t base, int t, int ldrow, int ldc)
{
    size_t grow = base + (size_t)(t * 64 + ldrow) * D_;
    uint32_t so = sbase + s * A_STAGE + ldrow * 144;
    cp16(so + 0 * A_ARR + ldc * 16,       Kh + grow + ldc * 8);
    cp16(so + 0 * A_ARR + (ldc + 4) * 16, Kh + grow + (ldc + 4) * 8);
    cp16(so + 1 * A_ARR + ldc * 16,       Kl + grow + ldc * 8);
    cp16(so + 1 * A_ARR + (ldc + 4) * 16, Kl + grow + (ldc + 4) * 8);
    cp16(so + 2 * A_ARR + ldc * 16,       Vh + grow + ldc * 8);
    cp16(so + 2 * A_ARR + (ldc + 4) * 16, Vh + grow + (ldc + 4) * 8);
    cp16(so + 3 * A_ARR + ldc * 16,       Vl + grow + ldc * 8);
    cp16(so + 3 * A_ARR + (ldc + 4) * 16, Vl + grow + (ldc + 4) * 8);
    asm volatile("cp.async.commit_group;" ::: "memory");
}

__global__ void __launch_bounds__(256) attn_bf16(
    const __nv_bfloat16* __restrict__ Qh, const __nv_bfloat16* __restrict__ Ql,
    const __nv_bfloat16* __restrict__ Kh, const __nv_bfloat16* __restrict__ Kl,
    const __nv_bfloat16* __restrict__ Vh, const __nv_bfloat16* __restrict__ Vl,
    __nv_bfloat16* __restrict__ Ohi, __nv_bfloat16* __restrict__ Olo)
{
    const int tid  = threadIdx.x;
    const int lane = tid & 31;
    const int wid  = tid >> 5;
    const int g    = lane >> 2;
    const int j    = lane & 3;

    const int q0 = blockIdx.x * 128;
    const int hh = blockIdx.y;
    const int bb = blockIdx.z;
    const size_t base = ((size_t)bb * T_) * D_ + (size_t)hh * HD_;

    const int ldrow = tid >> 2;
    const int ldc   = tid & 3;
    const uint32_t sbase = smem_u32(attnsmem);

    // kick off stage 0 loads before doing Q fragment loads
    attn_issue(sbase, 0, Kh, Kl, Vh, Vl, base, 0, ldrow, ldc);

    // ---- Q fragments from global (register resident) ----
    uint32_t Qfh[4][4], Qfl[4][4];
    {
        const uint32_t* qh32 = (const uint32_t*)(Qh + base);
        const uint32_t* ql32 = (const uint32_t*)(Ql + base);
        int r0 = q0 + wid * 16 + g;
#pragma unroll
        for (int kf = 0; kf < 4; kf++) {
            int w0 = kf * 8 + j, w1 = kf * 8 + 4 + j;
            Qfh[kf][0] = qh32[(size_t)r0 * (D_ / 2) + w0];
            Qfh[kf][1] = qh32[(size_t)(r0 + 8) * (D_ / 2) + w0];
            Qfh[kf][2] = qh32[(size_t)r0 * (D_ / 2) + w1];
            Qfh[kf][3] = qh32[(size_t)(r0 + 8) * (D_ / 2) + w1];
            Qfl[kf][0] = ql32[(size_t)r0 * (D_ / 2) + w0];
            Qfl[kf][1] = ql32[(size_t)(r0 + 8) * (D_ / 2) + w0];
            Qfl[kf][2] = ql32[(size_t)r0 * (D_ / 2) + w1];
            Qfl[kf][3] = ql32[(size_t)(r0 + 8) * (D_ / 2) + w1];
        }
    }

    const int lr8  = (lane & 7) + ((lane >> 3) & 1) * 8;
    const int lc16 = (lane >> 4) * 16;

    float oac[8][4];
#pragma unroll
    for (int nt = 0; nt < 8; nt++)
#pragma unroll
        for (int i = 0; i < 4; i++) oac[nt][i] = 0.f;
    float m0 = -INFINITY, m1 = -INFINITY, l0 = 0.f, l1 = 0.f;

    const int NTILE = T_ / 64;

    for (int t = 0; t < NTILE; t++) {
        const int s = t & 1;

        if (t + 1 < NTILE) {
            attn_issue(sbase, s ^ 1, Kh, Kl, Vh, Vl, base, t + 1, ldrow, ldc);
            asm volatile("cp.async.wait_group 1;" ::: "memory");
        } else {
            asm volatile("cp.async.wait_group 0;" ::: "memory");
        }
        __syncthreads();   // stage s fully populated for all threads

        const uint32_t kh_b = sbase + s * A_STAGE + 0 * A_ARR;
        const uint32_t kl_b = sbase + s * A_STAGE + 1 * A_ARR;
        const uint32_t vh_b = sbase + s * A_STAGE + 2 * A_ARR;
        const uint32_t vl_b = sbase + s * A_STAGE + 3 * A_ARR;

        // ---- S = Q K^T ----
        float sac[8][4];
#pragma unroll
        for (int nt = 0; nt < 8; nt++)
#pragma unroll
            for (int i = 0; i < 4; i++) sac[nt][i] = 0.f;

#pragma unroll
        for (int kf = 0; kf < 4; kf++) {
#pragma unroll
            for (int np = 0; np < 4; np++) {
                uint32_t off = (np * 16 + lr8) * 144 + kf * 32 + lc16;
                uint32_t bh[4], bl[4];
                ldsm4(bh, kh_b + off);
                ldsm4(bl, kl_b + off);
                uint32_t bA_h[2] = { bh[0], bh[2] }, bB_h[2] = { bh[1], bh[3] };
                uint32_t bA_l[2] = { bl[0], bl[2] }, bB_l[2] = { bl[1], bl[3] };
                mma16816(sac[np * 2],     Qfh[kf], bA_h);
                mma16816(sac[np * 2],     Qfl[kf], bA_h);
                mma16816(sac[np * 2],     Qfh[kf], bA_l);
                mma16816(sac[np * 2 + 1], Qfh[kf], bB_h);
                mma16816(sac[np * 2 + 1], Qfl[kf], bB_h);
                mma16816(sac[np * 2 + 1], Qfh[kf], bB_l);
            }
        }

        // ---- online softmax ----
        float mx0 = -INFINITY, mx1 = -INFINITY;
#pragma unroll
        for (int nt = 0; nt < 8; nt++) {
#pragma unroll
            for (int i = 0; i < 4; i++) sac[nt][i] *= 0.125f;
            mx0 = fmaxf(mx0, fmaxf(sac[nt][0], sac[nt][1]));
            mx1 = fmaxf(mx1, fmaxf(sac[nt][2], sac[nt][3]));
        }
#pragma unroll
        for (int off = 1; off <= 2; off <<= 1) {
            mx0 = fmaxf(mx0, __shfl_xor_sync(0xffffffffu, mx0, off));
            mx1 = fmaxf(mx1, __shfl_xor_sync(0xffffffffu, mx1, off));
        }
        float mn0 = fmaxf(m0, mx0), mn1 = fmaxf(m1, mx1);
        float al0 = __expf(m0 - mn0), al1 = __expf(m1 - mn1);
        m0 = mn0; m1 = mn1;

        float rs0 = 0.f, rs1 = 0.f;
#pragma unroll
        for (int nt = 0; nt < 8; nt++) {
            sac[nt][0] = __expf(sac[nt][0] - mn0);
            sac[nt][1] = __expf(sac[nt][1] - mn0);
            sac[nt][2] = __expf(sac[nt][2] - mn1);
            sac[nt][3] = __expf(sac[nt][3] - mn1);
            rs0 += sac[nt][0] + sac[nt][1];
            rs1 += sac[nt][2] + sac[nt][3];
        }
#pragma unroll
        for (int off = 1; off <= 2; off <<= 1) {
            rs0 += __shfl_xor_sync(0xffffffffu, rs0, off);
            rs1 += __shfl_xor_sync(0xffffffffu, rs1, off);
        }
        l0 = l0 * al0 + rs0;
        l1 = l1 * al1 + rs1;
#pragma unroll
        for (int nt = 0; nt < 8; nt++) {
            oac[nt][0] *= al0; oac[nt][1] *= al0;
            oac[nt][2] *= al1; oac[nt][3] *= al1;
        }

        // ---- O += P V ----
#pragma unroll
        for (int kf = 0; kf < 4; kf++) {
            uint32_t ph[4], pl[4];
            split2(sac[2 * kf][0],     sac[2 * kf][1],     ph[0], pl[0]);
            split2(sac[2 * kf][2],     sac[2 * kf][3],     ph[1], pl[1]);
            split2(sac[2 * kf + 1][0], sac[2 * kf + 1][1], ph[2], pl[2]);
            split2(sac[2 * kf + 1][2], sac[2 * kf + 1][3], ph[3], pl[3]);
#pragma unroll
            for (int np = 0; np < 4; np++) {
                uint32_t off = (kf * 16 + lr8) * 144 + np * 32 + lc16;
                uint32_t vh[4], vl[4];
                ldsm4t(vh, vh_b + off);
                ldsm4t(vl, vl_b + off);
                uint32_t vA_h[2] = { vh[0], vh[1] }, vB_h[2] = { vh[2], vh[3] };
                uint32_t vA_l[2] = { vl[0], vl[1] }, vB_l[2] = { vl[2], vl[3] };
                mma16816(oac[np * 2],     ph, vA_h);
                mma16816(oac[np * 2],     pl, vA_h);
                mma16816(oac[np * 2],     ph, vA_l);
                mma16816(oac[np * 2 + 1], ph, vB_h);
                mma16816(oac[np * 2 + 1], pl, vB_h);
                mma16816(oac[np * 2 + 1], ph, vB_l);
            }
        }
        __syncthreads();   // all warps done reading stage s before it is re-filled
    }

    // ---- epilogue ----
    float inv0 = 1.f / l0, inv1 = 1.f / l1;
    int row = q0 + wid * 16 + g;
    uint32_t* oh32 = (uint32_t*)(Ohi + base);
    uint32_t* ol32 = (uint32_t*)(Olo + base);
#pragma unroll
    for (int nt = 0; nt < 8; nt++) {
        int w = nt * 4 + j;
        uint32_t h, l;
        split2(oac[nt][0] * inv0, oac[nt][1] * inv0, h, l);
        oh32[(size_t)row * (D_ / 2) + w] = h;
        ol32[(size_t)row * (D_ / 2) + w] = l;
        split2(oac[nt][2] * inv1, oac[nt][3] * inv1, h, l);
        oh32[(size_t)(row + 8) * (D_ / 2) + w] = h;
        ol32[(size_t)(row + 8) * (D_ / 2) + w] = l;
    }
}

// ---------------------------------------------------------------------------
__global__ void __launch_bounds__(256) readout_kernel(
    const float* __restrict__ hbuf, const float* __restrict__ R,
    float* __restrict__ out)
{
    __shared__ float hs[B_][D_];
    for (int i = threadIdx.x; i < B_ * D_; i += 256) {
        int b = i >> 9, d = i & 511;
        hs[b][d] = hbuf[((size_t)b * T_ + (T_ - 1)) * D_ + d];
    }
    __syncthreads();

    int v = blockIdx.x * 256 + threadIdx.x;
    float a0 = 0.f, a1 = 0.f, a2 = 0.f, a3 = 0.f;
    const float* r = R + (size_t)v * D_;
    for (int d = 0; d < D_; d += 4) {
        float4 rv = *(const float4*)(r + d);
        a0 += rv.x * hs[0][d] + rv.y * hs[0][d + 1] + rv.z * hs[0][d + 2] + rv.w * hs[0][d + 3];
        a1 += rv.x * hs[1][d] + rv.y * hs[1][d + 1] + rv.z * hs[1][d + 2] + rv.w * hs[1][d + 3];
        a2 += rv.x * hs[2][d] + rv.y * hs[2][d + 1] + rv.z * hs[2][d + 2] + rv.w * hs[2][d + 3];
        a3 += rv.x * hs[3][d] + rv.y * hs[3][d + 1] + rv.z * hs[3][d + 2] + rv.w * hs[3][d + 3];
    }
    const float sc = 0.04419417382415922f;
    out[0 * V_ + v] = a0 * sc;
    out[1 * V_ + v] = a1 * sc;
    out[2 * V_ + v] = a2 * sc;
    out[3 * V_ + v] = a3 * sc;
}

// ---------------------------------------------------------------------------
extern "C" void kernel_launch(void* const* d_in, const int* in_sizes, int n_in,
                              void* d_out, int out_size)
{
    const float* x  = (const float*)d_in[0];
    const float* te = (const float*)d_in[1];
    const float* pe = (const float*)d_in[2];
    const float* Wk = (const float*)d_in[3];
    const float* Wq = (const float*)d_in[4];
    const float* Wv = (const float*)d_in[5];
    const float* Wp = (const float*)d_in[6];
    const float* ro = (const float*)d_in[7];
    float* out = (float*)d_out;

    float* hf;
    __nv_bfloat16 *hh, *hl, *qh, *ql, *kh, *kl, *vh, *vl, *oh, *ol;
    __nv_bfloat16 *xh, *xl, *teh, *tel;
    __nv_bfloat16 *wqh, *wql, *wkh, *wkl, *wvh, *wvl, *wph, *wpl;
    cudaGetSymbolAddress((void**)&hf,  g_h);
    cudaGetSymbolAddress((void**)&hh,  g_hh);  cudaGetSymbolAddress((void**)&hl, g_hl);
    cudaGetSymbolAddress((void**)&qh,  g_qh);  cudaGetSymbolAddress((void**)&ql, g_ql);
    cudaGetSymbolAddress((void**)&kh,  g_kh);  cudaGetSymbolAddress((void**)&kl, g_kl);
    cudaGetSymbolAddress((void**)&vh,  g_vh);  cudaGetSymbolAddress((void**)&vl, g_vl);
    cudaGetSymbolAddress((void**)&oh,  g_oh);  cudaGetSymbolAddress((void**)&ol, g_ol);
    cudaGetSymbolAddress((void**)&xh,  g_xh);  cudaGetSymbolAddress((void**)&xl, g_xl);
    cudaGetSymbolAddress((void**)&teh, g_teh); cudaGetSymbolAddress((void**)&tel, g_tel);
    cudaGetSymbolAddress((void**)&wqh, g_wqh); cudaGetSymbolAddress((void**)&wql, g_wql);
    cudaGetSymbolAddress((void**)&wkh, g_wkh); cudaGetSymbolAddress((void**)&wkl, g_wkl);
    cudaGetSymbolAddress((void**)&wvh, g_wvh); cudaGetSymbolAddress((void**)&wvl, g_wvl);
    cudaGetSymbolAddress((void**)&wph, g_wph); cudaGetSymbolAddress((void**)&wpl, g_wpl);

    cudaFuncSetAttribute(attn_bf16, cudaFuncAttributeMaxDynamicSharedMemorySize, A_SMEM);

    const float sV = 0.022097086912079608f;  // 1/sqrt(2048)
    const float sD = 0.04419417382415922f;   // 1/sqrt(512)

    {
        int n4 = (B_ * T_ * V_) / 4;
        split_kernel<<<(n4 + 255) / 256, 256>>>((const float4*)x, (uint2*)xh, (uint2*)xl, n4);
        n4 = (D_ * V_) / 4;
        split_kernel<<<(n4 + 255) / 256, 256>>>((const float4*)te, (uint2*)teh, (uint2*)tel, n4);
        n4 = (L_ * D_ * D_) / 4;
        split_kernel<<<(n4 + 255) / 256, 256>>>((const float4*)Wq, (uint2*)wqh, (uint2*)wql, n4);
        split_kernel<<<(n4 + 255) / 256, 256>>>((const float4*)Wk, (uint2*)wkh, (uint2*)wkl, n4);
        split_kernel<<<(n4 + 255) / 256, 256>>>((const float4*)Wv, (uint2*)wvh, (uint2*)wvl, n4);
        split_kernel<<<(n4 + 255) / 256, 256>>>((const float4*)Wp, (uint2*)wph, (uint2*)wpl, n4);
    }

    dim3 ggrid(D_ / 128, (B_ * T_) / 128);

    // embed: h = x @ TE^T / sqrt(V) + pos
    gemm_nt_bf16<<<ggrid, 256>>>(xh, xl, teh, tel,
                                 nullptr, hh, hl, pe, B_ * T_, D_, V_, sV);

    for (int l = 0; l < L_; l++) {
        size_t wo = (size_t)l * D_ * D_;
        gemm_nt_bf16<<<ggrid, 256>>>(hh, hl, wqh + wo, wql + wo,
                                     nullptr, qh, ql, nullptr, B_ * T_, D_, D_, sD);
        gemm_nt_bf16<<<ggrid, 256>>>(hh, hl, wkh + wo, wkl + wo,
                                     nullptr, kh, kl, nullptr, B_ * T_, D_, D_, sD);
        gemm_nt_bf16<<<ggrid, 256>>>(hh, hl, wvh + wo, wvl + wo,
                                     nullptr, vh, vl, nullptr, B_ * T_, D_, D_, sD);

        attn_bf16<<<dim3(T_ / 128, H_, B_), 256, A_SMEM>>>(qh, ql, kh, kl, vh, vl, oh, ol);

        gemm_nt_bf16<<<ggrid, 256>>>(oh, ol, wph + wo, wpl + wo,
                                     hf, hh, hl, nullptr, B_ * T_, D_, D_, sD);
    }

    readout_kernel<<<V_ / 256, 256>>>(hf, ro, out);
}

// round 7
// speedup vs baseline: 2.5089x; 1.0129x over previous
#include <cuda_runtime.h>
#include <cuda_bf16.h>
#include <math.h>
#include <stdint.h>

#define B_  4
#define T_  2048
#define V_  2048
#define D_  512
#define H_  8
#define L_  4
#define HD_ 64
#define NT_ (B_ * T_ * D_)   // 4M elems

// ---- global scratch (no allocation allowed) ----
__device__ __align__(16) float g_h[NT_];                       // fp32 h (for readout)
__device__ __align__(16) __nv_bfloat16 g_hh[NT_], g_hl[NT_];
__device__ __align__(16) __nv_bfloat16 g_qh[NT_], g_ql[NT_];
__device__ __align__(16) __nv_bfloat16 g_kh[NT_], g_kl[NT_];
__device__ __align__(16) __nv_bfloat16 g_vh[NT_], g_vl[NT_];
__device__ __align__(16) __nv_bfloat16 g_oh[NT_], g_ol[NT_];
__device__ __align__(16) __nv_bfloat16 g_xh[B_ * T_ * V_], g_xl[B_ * T_ * V_];
__device__ __align__(16) __nv_bfloat16 g_teh[D_ * V_], g_tel[D_ * V_];
__device__ __align__(16) __nv_bfloat16 g_wqh[L_ * D_ * D_], g_wql[L_ * D_ * D_];
__device__ __align__(16) __nv_bfloat16 g_wkh[L_ * D_ * D_], g_wkl[L_ * D_ * D_];
__device__ __align__(16) __nv_bfloat16 g_wvh[L_ * D_ * D_], g_wvl[L_ * D_ * D_];
__device__ __align__(16) __nv_bfloat16 g_wph[L_ * D_ * D_], g_wpl[L_ * D_ * D_];

// ---------------------------------------------------------------------------
__device__ __forceinline__ void split2(float x, float y, uint32_t& h, uint32_t& l)
{
    __nv_bfloat16 xh = __float2bfloat16_rn(x);
    __nv_bfloat16 yh = __float2bfloat16_rn(y);
    __nv_bfloat16 xl = __float2bfloat16_rn(x - __bfloat162float(xh));
    __nv_bfloat16 yl = __float2bfloat16_rn(y - __bfloat162float(yh));
    __nv_bfloat162 hv = __halves2bfloat162(xh, yh);
    __nv_bfloat162 lv = __halves2bfloat162(xl, yl);
    h = *reinterpret_cast<uint32_t*>(&hv);
    l = *reinterpret_cast<uint32_t*>(&lv);
}

__device__ __forceinline__ void mma16816(float* d, const uint32_t* a, const uint32_t* b)
{
    asm volatile(
        "mma.sync.aligned.m16n8k16.row.col.f32.bf16.bf16.f32 "
        "{%0,%1,%2,%3}, {%4,%5,%6,%7}, {%8,%9}, {%0,%1,%2,%3};\n"
        : "+f"(d[0]), "+f"(d[1]), "+f"(d[2]), "+f"(d[3])
        : "r"(a[0]), "r"(a[1]), "r"(a[2]), "r"(a[3]), "r"(b[0]), "r"(b[1]));
}

__device__ __forceinline__ void ldsm4(uint32_t* r, uint32_t addr)
{
    asm volatile("ldmatrix.sync.aligned.m8n8.x4.shared.b16 {%0,%1,%2,%3}, [%4];"
                 : "=r"(r[0]), "=r"(r[1]), "=r"(r[2]), "=r"(r[3]) : "r"(addr));
}
__device__ __forceinline__ void ldsm4t(uint32_t* r, uint32_t addr)
{
    asm volatile("ldmatrix.sync.aligned.m8n8.x4.trans.shared.b16 {%0,%1,%2,%3}, [%4];"
                 : "=r"(r[0]), "=r"(r[1]), "=r"(r[2]), "=r"(r[3]) : "r"(addr));
}

__device__ __forceinline__ uint32_t smem_u32(const void* p)
{
    uint32_t a;
    asm("{ .reg .u64 t; cvta.to.shared.u64 t, %1; cvt.u32.u64 %0, t; }" : "=r"(a) : "l"(p));
    return a;
}

__device__ __forceinline__ void cp16(uint32_t saddr, const void* gaddr)
{
    asm volatile("cp.async.cg.shared.global [%0], [%1], 16;" :: "r"(saddr), "l"(gaddr));
}

// ---------------------------------------------------------------------------
// fp32 -> bf16 hi/lo splitter
// ---------------------------------------------------------------------------
__global__ void __launch_bounds__(256) split_kernel(
    const float4* __restrict__ src, uint2* __restrict__ hi, uint2* __restrict__ lo, int n4)
{
    int i = blockIdx.x * 256 + threadIdx.x;
    if (i < n4) {
        float4 f = src[i];
        uint32_t h0, l0, h1, l1;
        split2(f.x, f.y, h0, l0);
        split2(f.z, f.w, h1, l1);
        hi[i] = make_uint2(h0, h1);
        lo[i] = make_uint2(l0, l1);
    }
}

// ---------------------------------------------------------------------------
// NT GEMM, bf16 hi/lo inputs (mma.sync)
// ---------------------------------------------------------------------------
#define GST 24          // smem row stride in bf16 (48 bytes)
#define GBUF 3072       // 128 * 24 bf16 per (part, stage)

__global__ void __launch_bounds__(256) gemm_nt_bf16(
    const __nv_bfloat16* __restrict__ Ah, const __nv_bfloat16* __restrict__ Al,
    const __nv_bfloat16* __restrict__ Bh, const __nv_bfloat16* __restrict__ Bl,
    float* __restrict__ Cf, __nv_bfloat16* __restrict__ Chi, __nv_bfloat16* __restrict__ Clo,
    const float* __restrict__ bias, int M, int N, int K, float alpha)
{
    __shared__ __align__(16) __nv_bfloat16 sm[2][4][GBUF];  // 48KB

    const int tid  = threadIdx.x;
    const int lane = tid & 31;
    const int wid  = tid >> 5;
    const int wm   = (wid & 3) * 32;
    const int wn   = (wid >> 2) * 64;
    const int bm   = blockIdx.y * 128;
    const int bn   = blockIdx.x * 128;
    const int g    = lane >> 2;
    const int j    = lane & 3;

    const int lrow  = tid >> 1;
    const int lhalf = tid & 1;
    const __nv_bfloat16* pAh = Ah + (size_t)(bm + lrow) * K + lhalf * 8;
    const __nv_bfloat16* pAl = Al + (size_t)(bm + lrow) * K + lhalf * 8;
    const __nv_bfloat16* pBh = Bh + (size_t)(bn + lrow) * K + lhalf * 8;
    const __nv_bfloat16* pBl = Bl + (size_t)(bn + lrow) * K + lhalf * 8;
    const int sidx = lrow * GST + lhalf * 8;

    const int lr8  = (lane & 7) + ((lane >> 3) & 1) * 8;
    const int lc16 = (lane >> 4) * 16;
    const uint32_t smbase = smem_u32(&sm[0][0][0]);
    uint32_t offA[2], offB[4];
#pragma unroll
    for (int mt = 0; mt < 2; mt++) offA[mt] = (wm + mt * 16 + lr8) * 48 + lc16;
#pragma unroll
    for (int np = 0; np < 4; np++) offB[np] = (wn + np * 16 + lr8) * 48 + lc16;

    float acc[2][8][4];
#pragma unroll
    for (int mt = 0; mt < 2; mt++)
#pragma unroll
        for (int nt = 0; nt < 8; nt++)
#pragma unroll
            for (int i = 0; i < 4; i++) acc[mt][nt][i] = 0.f;

    const int KT = K >> 4;

    {
        *(uint4*)&sm[0][0][sidx] = *(const uint4*)pAh;
        *(uint4*)&sm[0][1][sidx] = *(const uint4*)pAl;
        *(uint4*)&sm[0][2][sidx] = *(const uint4*)pBh;
        *(uint4*)&sm[0][3][sidx] = *(const uint4*)pBl;
    }
    __syncthreads();

    for (int ks = 0; ks < KT; ks++) {
        const int cur = ks & 1, nxt = cur ^ 1;

        uint4 rah, ral, rbh, rbl;
        if (ks + 1 < KT) {
            int k0 = (ks + 1) << 4;
            rah = *(const uint4*)(pAh + k0);
            ral = *(const uint4*)(pAl + k0);
            rbh = *(const uint4*)(pBh + k0);
            rbl = *(const uint4*)(pBl + k0);
        }

        const uint32_t sb = smbase + cur * (4 * GBUF * 2);
        uint32_t fah[2][4], fal[2][4];
#pragma unroll
        for (int mt = 0; mt < 2; mt++) {
            ldsm4(fah[mt], sb + 0 * (GBUF * 2) + offA[mt]);
            ldsm4(fal[mt], sb + 1 * (GBUF * 2) + offA[mt]);
        }
#pragma unroll
        for (int np = 0; np < 4; np++) {
            uint32_t bh[4], bl[4];
            ldsm4(bh, sb + 2 * (GBUF * 2) + offB[np]);
            ldsm4(bl, sb + 3 * (GBUF * 2) + offB[np]);
            uint32_t bA_h[2] = { bh[0], bh[2] }, bB_h[2] = { bh[1], bh[3] };
            uint32_t bA_l[2] = { bl[0], bl[2] }, bB_l[2] = { bl[1], bl[3] };
#pragma unroll
            for (int mt = 0; mt < 2; mt++) {
                mma16816(acc[mt][np * 2],     fah[mt], bA_h);
                mma16816(acc[mt][np * 2],     fal[mt], bA_h);
                mma16816(acc[mt][np * 2],     fah[mt], bA_l);
                mma16816(acc[mt][np * 2 + 1], fah[mt], bB_h);
                mma16816(acc[mt][np * 2 + 1], fal[mt], bB_h);
                mma16816(acc[mt][np * 2 + 1], fah[mt], bB_l);
            }
        }

        if (ks + 1 < KT) {
            *(uint4*)&sm[nxt][0][sidx] = rah;
            *(uint4*)&sm[nxt][1][sidx] = ral;
            *(uint4*)&sm[nxt][2][sidx] = rbh;
            *(uint4*)&sm[nxt][3][sidx] = rbl;
        }
        __syncthreads();
    }

#pragma unroll
    for (int mt = 0; mt < 2; mt++) {
#pragma unroll
        for (int nt = 0; nt < 8; nt++) {
            int row = bm + wm + mt * 16 + g;
            int col = bn + wn + nt * 8 + j * 2;
            float2 v0 = make_float2(acc[mt][nt][0] * alpha, acc[mt][nt][1] * alpha);
            float2 v1 = make_float2(acc[mt][nt][2] * alpha, acc[mt][nt][3] * alpha);
            if (bias) {
                const float* b0 = bias + (size_t)(row & (T_ - 1)) * N + col;
                const float* b1 = bias + (size_t)((row + 8) & (T_ - 1)) * N + col;
                v0.x += b0[0]; v0.y += b0[1];
                v1.x += b1[0]; v1.y += b1[1];
            }
            size_t i0 = (size_t)row * N + col;
            size_t i1 = (size_t)(row + 8) * N + col;
            if (Cf) {
                *(float2*)&Cf[i0] = v0;
                *(float2*)&Cf[i1] = v1;
            }
            if (Chi) {
                uint32_t h, l;
                split2(v0.x, v0.y, h, l);
                *(uint32_t*)&Chi[i0] = h; *(uint32_t*)&Clo[i0] = l;
                split2(v1.x, v1.y, h, l);
                *(uint32_t*)&Chi[i1] = h; *(uint32_t*)&Clo[i1] = l;
            }
        }
    }
}

// ---------------------------------------------------------------------------
// Flash attention, cp.async double-buffered, FIXED-OFFSET softmax (no max).
// Q pre-scaled by 0.125*log2(e); p = exp2(sac - 6); offset cancels in O/l.
// ---------------------------------------------------------------------------
#define ASTR       72                 // bf16 row stride (144 bytes)
#define A_ARR      9216               // bytes per array (64 rows * 144B)
#define A_STAGE    (4 * A_ARR)        // Kh,Kl,Vh,Vl per stage = 36864B
#define A_SMEM     (2 * A_STAGE)      // 73728B
#define SM_OFF     6.0f               // softmax exponent offset (log2 units)

extern __shared__ char attnsmem[];

__device__ __forceinline__ void attn_issue(
    uint32_t sbase, int s,
    const __nv_bfloat16* Kh, const __nv_bfloat16* Kl,
    const __nv_bfloat16* Vh, const __nv_bfloat16* Vl,
    size_t base, int t, int ldrow, int ldc)
{
    size_t grow = base + (size_t)(t * 64 + ldrow) * D_;
    uint32_t so = sbase + s * A_STAGE + ldrow * 144;
    cp16(so + 0 * A_ARR + ldc * 16,       Kh + grow + ldc * 8);
    cp16(so + 0 * A_ARR + (ldc + 4) * 16, Kh + grow + (ldc + 4) * 8);
    cp16(so + 1 * A_ARR + ldc * 16,       Kl + grow + ldc * 8);
    cp16(so + 1 * A_ARR + (ldc + 4) * 16, Kl + grow + (ldc + 4) * 8);
    cp16(so + 2 * A_ARR + ldc * 16,       Vh + grow + ldc * 8);
    cp16(so + 2 * A_ARR + (ldc + 4) * 16, Vh + grow + (ldc + 4) * 8);
    cp16(so + 3 * A_ARR + ldc * 16,       Vl + grow + ldc * 8);
    cp16(so + 3 * A_ARR + (ldc + 4) * 16, Vl + grow + (ldc + 4) * 8);
    asm volatile("cp.async.commit_group;" ::: "memory");
}

__global__ void __launch_bounds__(256) attn_bf16(
    const __nv_bfloat16* __restrict__ Qh, const __nv_bfloat16* __restrict__ Ql,
    const __nv_bfloat16* __restrict__ Kh, const __nv_bfloat16* __restrict__ Kl,
    const __nv_bfloat16* __restrict__ Vh, const __nv_bfloat16* __restrict__ Vl,
    __nv_bfloat16* __restrict__ Ohi, __nv_bfloat16* __restrict__ Olo)
{
    const int tid  = threadIdx.x;
    const int lane = tid & 31;
    const int wid  = tid >> 5;
    const int g    = lane >> 2;
    const int j    = lane & 3;

    const int q0 = blockIdx.x * 128;
    const int hh = blockIdx.y;
    const int bb = blockIdx.z;
    const size_t base = ((size_t)bb * T_) * D_ + (size_t)hh * HD_;

    const int ldrow = tid >> 2;
    const int ldc   = tid & 3;
    const uint32_t sbase = smem_u32(attnsmem);

    // kick off stage 0 loads first
    attn_issue(sbase, 0, Kh, Kl, Vh, Vl, base, 0, ldrow, ldc);

    // ---- Q fragments from global; fold in 0.125*log2(e) with full re-split ----
    uint32_t Qfh[4][4], Qfl[4][4];
    {
        const uint32_t* qh32 = (const uint32_t*)(Qh + base);
        const uint32_t* ql32 = (const uint32_t*)(Ql + base);
        int r0 = q0 + wid * 16 + g;
        const float SC = 0.18033688011112042f;  // 0.125 * log2(e)
#pragma unroll
        for (int kf = 0; kf < 4; kf++) {
            int w0 = kf * 8 + j, w1 = kf * 8 + 4 + j;
            uint32_t rh[4], rl[4];
            rh[0] = qh32[(size_t)r0 * (D_ / 2) + w0];
            rh[1] = qh32[(size_t)(r0 + 8) * (D_ / 2) + w0];
            rh[2] = qh32[(size_t)r0 * (D_ / 2) + w1];
            rh[3] = qh32[(size_t)(r0 + 8) * (D_ / 2) + w1];
            rl[0] = ql32[(size_t)r0 * (D_ / 2) + w0];
            rl[1] = ql32[(size_t)(r0 + 8) * (D_ / 2) + w0];
            rl[2] = ql32[(size_t)r0 * (D_ / 2) + w1];
            rl[3] = ql32[(size_t)(r0 + 8) * (D_ / 2) + w1];
#pragma unroll
            for (int i = 0; i < 4; i++) {
                float2 a = __bfloat1622float2(*(__nv_bfloat162*)&rh[i]);
                float2 b = __bfloat1622float2(*(__nv_bfloat162*)&rl[i]);
                split2((a.x + b.x) * SC, (a.y + b.y) * SC, Qfh[kf][i], Qfl[kf][i]);
            }
        }
    }

    const int lr8  = (lane & 7) + ((lane >> 3) & 1) * 8;
    const int lc16 = (lane >> 4) * 16;

    float oac[8][4];
#pragma unroll
    for (int nt = 0; nt < 8; nt++)
#pragma unroll
        for (int i = 0; i < 4; i++) oac[nt][i] = 0.f;
    float l0 = 0.f, l1 = 0.f;

    const int NTILE = T_ / 64;

    for (int t = 0; t < NTILE; t++) {
        const int s = t & 1;

        if (t + 1 < NTILE) {
            attn_issue(sbase, s ^ 1, Kh, Kl, Vh, Vl, base, t + 1, ldrow, ldc);
            asm volatile("cp.async.wait_group 1;" ::: "memory");
        } else {
            asm volatile("cp.async.wait_group 0;" ::: "memory");
        }
        __syncthreads();

        const uint32_t kh_b = sbase + s * A_STAGE + 0 * A_ARR;
        const uint32_t kl_b = sbase + s * A_STAGE + 1 * A_ARR;
        const uint32_t vh_b = sbase + s * A_STAGE + 2 * A_ARR;
        const uint32_t vl_b = sbase + s * A_STAGE + 3 * A_ARR;

        // ---- S (in log2 units, Q pre-scaled) ----
        float sac[8][4];
#pragma unroll
        for (int nt = 0; nt < 8; nt++)
#pragma unroll
            for (int i = 0; i < 4; i++) sac[nt][i] = 0.f;

#pragma unroll
        for (int kf = 0; kf < 4; kf++) {
#pragma unroll
            for (int np = 0; np < 4; np++) {
                uint32_t off = (np * 16 + lr8) * 144 + kf * 32 + lc16;
                uint32_t bh[4], bl[4];
                ldsm4(bh, kh_b + off);
                ldsm4(bl, kl_b + off);
                uint32_t bA_h[2] = { bh[0], bh[2] }, bB_h[2] = { bh[1], bh[3] };
                uint32_t bA_l[2] = { bl[0], bl[2] }, bB_l[2] = { bl[1], bl[3] };
                mma16816(sac[np * 2],     Qfh[kf], bA_h);
                mma16816(sac[np * 2],     Qfl[kf], bA_h);
                mma16816(sac[np * 2],     Qfh[kf], bA_l);
                mma16816(sac[np * 2 + 1], Qfh[kf], bB_h);
                mma16816(sac[np * 2 + 1], Qfl[kf], bB_h);
                mma16816(sac[np * 2 + 1], Qfh[kf], bB_l);
            }
        }

        // ---- fixed-offset softmax: p = 2^(sac - 6), no max tracking ----
        float rs0 = 0.f, rs1 = 0.f;
#pragma unroll
        for (int nt = 0; nt < 8; nt++) {
            sac[nt][0] = exp2f(sac[nt][0] - SM_OFF);
            sac[nt][1] = exp2f(sac[nt][1] - SM_OFF);
            sac[nt][2] = exp2f(sac[nt][2] - SM_OFF);
            sac[nt][3] = exp2f(sac[nt][3] - SM_OFF);
            rs0 += sac[nt][0] + sac[nt][1];
            rs1 += sac[nt][2] + sac[nt][3];
        }
        l0 += rs0;
        l1 += rs1;

        // ---- O += P V ----
#pragma unroll
        for (int kf = 0; kf < 4; kf++) {
            uint32_t ph[4], pl[4];
            split2(sac[2 * kf][0],     sac[2 * kf][1],     ph[0], pl[0]);
            split2(sac[2 * kf][2],     sac[2 * kf][3],     ph[1], pl[1]);
            split2(sac[2 * kf + 1][0], sac[2 * kf + 1][1], ph[2], pl[2]);
            split2(sac[2 * kf + 1][2], sac[2 * kf + 1][3], ph[3], pl[3]);
#pragma unroll
            for (int np = 0; np < 4; np++) {
                uint32_t off = (kf * 16 + lr8) * 144 + np * 32 + lc16;
                uint32_t vh[4], vl[4];
                ldsm4t(vh, vh_b + off);
                ldsm4t(vl, vl_b + off);
                uint32_t vA_h[2] = { vh[0], vh[1] }, vB_h[2] = { vh[2], vh[3] };
                uint32_t vA_l[2] = { vl[0], vl[1] }, vB_l[2] = { vl[2], vl[3] };
                mma16816(oac[np * 2],     ph, vA_h);
                mma16816(oac[np * 2],     pl, vA_h);
                mma16816(oac[np * 2],     ph, vA_l);
                mma16816(oac[np * 2 + 1], ph, vB_h);
                mma16816(oac[np * 2 + 1], pl, vB_h);
                mma16816(oac[np * 2 + 1], ph, vB_l);
            }
        }
        __syncthreads();
    }

    // ---- row-sum reduction across the 4-lane groups, then epilogue ----
#pragma unroll
    for (int off = 1; off <= 2; off <<= 1) {
        l0 += __shfl_xor_sync(0xffffffffu, l0, off);
        l1 += __shfl_xor_sync(0xffffffffu, l1, off);
    }
    float inv0 = 1.f / l0, inv1 = 1.f / l1;
    int row = q0 + wid * 16 + g;
    uint32_t* oh32 = (uint32_t*)(Ohi + base);
    uint32_t* ol32 = (uint32_t*)(Olo + base);
#pragma unroll
    for (int nt = 0; nt < 8; nt++) {
        int w = nt * 4 + j;
        uint32_t h, l;
        split2(oac[nt][0] * inv0, oac[nt][1] * inv0, h, l);
        oh32[(size_t)row * (D_ / 2) + w] = h;
        ol32[(size_t)row * (D_ / 2) + w] = l;
        split2(oac[nt][2] * inv1, oac[nt][3] * inv1, h, l);
        oh32[(size_t)(row + 8) * (D_ / 2) + w] = h;
        ol32[(size_t)(row + 8) * (D_ / 2) + w] = l;
    }
}

// ---------------------------------------------------------------------------
__global__ void __launch_bounds__(256) readout_kernel(
    const float* __restrict__ hbuf, const float* __restrict__ R,
    float* __restrict__ out)
{
    __shared__ float hs[B_][D_];
    for (int i = threadIdx.x; i < B_ * D_; i += 256) {
        int b = i >> 9, d = i & 511;
        hs[b][d] = hbuf[((size_t)b * T_ + (T_ - 1)) * D_ + d];
    }
    __syncthreads();

    int v = blockIdx.x * 256 + threadIdx.x;
    float a0 = 0.f, a1 = 0.f, a2 = 0.f, a3 = 0.f;
    const float* r = R + (size_t)v * D_;
    for (int d = 0; d < D_; d += 4) {
        float4 rv = *(const float4*)(r + d);
        a0 += rv.x * hs[0][d] + rv.y * hs[0][d + 1] + rv.z * hs[0][d + 2] + rv.w * hs[0][d + 3];
        a1 += rv.x * hs[1][d] + rv.y * hs[1][d + 1] + rv.z * hs[1][d + 2] + rv.w * hs[1][d + 3];
        a2 += rv.x * hs[2][d] + rv.y * hs[2][d + 1] + rv.z * hs[2][d + 2] + rv.w * hs[2][d + 3];
        a3 += rv.x * hs[3][d] + rv.y * hs[3][d + 1] + rv.z * hs[3][d + 2] + rv.w * hs[3][d + 3];
    }
    const float sc = 0.04419417382415922f;
    out[0 * V_ + v] = a0 * sc;
    out[1 * V_ + v] = a1 * sc;
    out[2 * V_ + v] = a2 * sc;
    out[3 * V_ + v] = a3 * sc;
}

// ---------------------------------------------------------------------------
extern "C" void kernel_launch(void* const* d_in, const int* in_sizes, int n_in,
                              void* d_out, int out_size)
{
    const float* x  = (const float*)d_in[0];
    const float* te = (const float*)d_in[1];
    const float* pe = (const float*)d_in[2];
    const float* Wk = (const float*)d_in[3];
    const float* Wq = (const float*)d_in[4];
    const float* Wv = (const float*)d_in[5];
    const float* Wp = (const float*)d_in[6];
    const float* ro = (const float*)d_in[7];
    float* out = (float*)d_out;

    float* hf;
    __nv_bfloat16 *hh, *hl, *qh, *ql, *kh, *kl, *vh, *vl, *oh, *ol;
    __nv_bfloat16 *xh, *xl, *teh, *tel;
    __nv_bfloat16 *wqh, *wql, *wkh, *wkl, *wvh, *wvl, *wph, *wpl;
    cudaGetSymbolAddress((void**)&hf,  g_h);
    cudaGetSymbolAddress((void**)&hh,  g_hh);  cudaGetSymbolAddress((void**)&hl, g_hl);
    cudaGetSymbolAddress((void**)&qh,  g_qh);  cudaGetSymbolAddress((void**)&ql, g_ql);
    cudaGetSymbolAddress((void**)&kh,  g_kh);  cudaGetSymbolAddress((void**)&kl, g_kl);
    cudaGetSymbolAddress((void**)&vh,  g_vh);  cudaGetSymbolAddress((void**)&vl, g_vl);
    cudaGetSymbolAddress((void**)&oh,  g_oh);  cudaGetSymbolAddress((void**)&ol, g_ol);
    cudaGetSymbolAddress((void**)&xh,  g_xh);  cudaGetSymbolAddress((void**)&xl, g_xl);
    cudaGetSymbolAddress((void**)&teh, g_teh); cudaGetSymbolAddress((void**)&tel, g_tel);
    cudaGetSymbolAddress((void**)&wqh, g_wqh); cudaGetSymbolAddress((void**)&wql, g_wql);
    cudaGetSymbolAddress((void**)&wkh, g_wkh); cudaGetSymbolAddress((void**)&wkl, g_wkl);
    cudaGetSymbolAddress((void**)&wvh, g_wvh); cudaGetSymbolAddress((void**)&wvl, g_wvl);
    cudaGetSymbolAddress((void**)&wph, g_wph); cudaGetSymbolAddress((void**)&wpl, g_wpl);

    cudaFuncSetAttribute(attn_bf16, cudaFuncAttributeMaxDynamicSharedMemorySize, A_SMEM);

    const float sV = 0.022097086912079608f;  // 1/sqrt(2048)
    const float sD = 0.04419417382415922f;   // 1/sqrt(512)

    {
        int n4 = (B_ * T_ * V_) / 4;
        split_kernel<<<(n4 + 255) / 256, 256>>>((const float4*)x, (uint2*)xh, (uint2*)xl, n4);
        n4 = (D_ * V_) / 4;
        split_kernel<<<(n4 + 255) / 256, 256>>>((const float4*)te, (uint2*)teh, (uint2*)tel, n4);
        n4 = (L_ * D_ * D_) / 4;
        split_kernel<<<(n4 + 255) / 256, 256>>>((const float4*)Wq, (uint2*)wqh, (uint2*)wql, n4);
        split_kernel<<<(n4 + 255) / 256, 256>>>((const float4*)Wk, (uint2*)wkh, (uint2*)wkl, n4);
        split_kernel<<<(n4 + 255) / 256, 256>>>((const float4*)Wv, (uint2*)wvh, (uint2*)wvl, n4);
        split_kernel<<<(n4 + 255) / 256, 256>>>((const float4*)Wp, (uint2*)wph, (uint2*)wpl, n4);
    }

    dim3 ggrid(D_ / 128, (B_ * T_) / 128);

    // embed: h = x @ TE^T / sqrt(V) + pos
    gemm_nt_bf16<<<ggrid, 256>>>(xh, xl, teh, tel,
                                 nullptr, hh, hl, pe, B_ * T_, D_, V_, sV);

    for (int l = 0; l < L_; l++) {
        size_t wo = (size_t)l * D_ * D_;
        gemm_nt_bf16<<<ggrid, 256>>>(hh, hl, wqh + wo, wql + wo,
                                     nullptr, qh, ql, nullptr, B_ * T_, D_, D_, sD);
        gemm_nt_bf16<<<ggrid, 256>>>(hh, hl, wkh + wo, wkl + wo,
                                     nullptr, kh, kl, nullptr, B_ * T_, D_, D_, sD);
        gemm_nt_bf16<<<ggrid, 256>>>(hh, hl, wvh + wo, wvl + wo,
                                     nullptr, vh, vl, nullptr, B_ * T_, D_, D_, sD);

        attn_bf16<<<dim3(T_ / 128, H_, B_), 256, A_SMEM>>>(qh, ql, kh, kl, vh, vl, oh, ol);

        gemm_nt_bf16<<<ggrid, 256>>>(oh, ol, wph + wo, wpl + wo,
                                     hf, hh, hl, nullptr, B_ * T_, D_, D_, sD);
    }

    readout_kernel<<<V_ / 256, 256>>>(hf, ro, out);
}

// round 8
// speedup vs baseline: 2.5678x; 1.0235x over previous
#include <cuda_runtime.h>
#include <cuda_bf16.h>
#include <math.h>
#include <stdint.h>

#define B_  4
#define T_  2048
#define V_  2048
#define D_  512
#define H_  8
#define L_  4
#define HD_ 64
#define NT_ (B_ * T_ * D_)   // 4M elems

// ---- global scratch (no allocation allowed) ----
__device__ __align__(16) float g_h[NT_];                       // fp32 h (for readout)
__device__ __align__(16) __nv_bfloat16 g_hh[NT_], g_hl[NT_];
__device__ __align__(16) __nv_bfloat16 g_qh[NT_], g_ql[NT_];
__device__ __align__(16) __nv_bfloat16 g_kh[NT_], g_kl[NT_];
__device__ __align__(16) __nv_bfloat16 g_vh[NT_], g_vl[NT_];
__device__ __align__(16) __nv_bfloat16 g_oh[NT_], g_ol[NT_];
__device__ __align__(16) __nv_bfloat16 g_teh[D_ * V_], g_tel[D_ * V_];
__device__ __align__(16) __nv_bfloat16 g_wqh[L_ * D_ * D_], g_wql[L_ * D_ * D_];
__device__ __align__(16) __nv_bfloat16 g_wkh[L_ * D_ * D_], g_wkl[L_ * D_ * D_];
__device__ __align__(16) __nv_bfloat16 g_wvh[L_ * D_ * D_], g_wvl[L_ * D_ * D_];
__device__ __align__(16) __nv_bfloat16 g_wph[L_ * D_ * D_], g_wpl[L_ * D_ * D_];

// ---------------------------------------------------------------------------
__device__ __forceinline__ void split2(float x, float y, uint32_t& h, uint32_t& l)
{
    __nv_bfloat16 xh = __float2bfloat16_rn(x);
    __nv_bfloat16 yh = __float2bfloat16_rn(y);
    __nv_bfloat16 xl = __float2bfloat16_rn(x - __bfloat162float(xh));
    __nv_bfloat16 yl = __float2bfloat16_rn(y - __bfloat162float(yh));
    __nv_bfloat162 hv = __halves2bfloat162(xh, yh);
    __nv_bfloat162 lv = __halves2bfloat162(xl, yl);
    h = *reinterpret_cast<uint32_t*>(&hv);
    l = *reinterpret_cast<uint32_t*>(&lv);
}

__device__ __forceinline__ float ex2(float x)
{
    float y;
    asm("ex2.approx.f32 %0, %1;" : "=f"(y) : "f"(x));
    return y;
}

__device__ __forceinline__ void mma16816(float* d, const uint32_t* a, const uint32_t* b)
{
    asm volatile(
        "mma.sync.aligned.m16n8k16.row.col.f32.bf16.bf16.f32 "
        "{%0,%1,%2,%3}, {%4,%5,%6,%7}, {%8,%9}, {%0,%1,%2,%3};\n"
        : "+f"(d[0]), "+f"(d[1]), "+f"(d[2]), "+f"(d[3])
        : "r"(a[0]), "r"(a[1]), "r"(a[2]), "r"(a[3]), "r"(b[0]), "r"(b[1]));
}

__device__ __forceinline__ void ldsm4(uint32_t* r, uint32_t addr)
{
    asm volatile("ldmatrix.sync.aligned.m8n8.x4.shared.b16 {%0,%1,%2,%3}, [%4];"
                 : "=r"(r[0]), "=r"(r[1]), "=r"(r[2]), "=r"(r[3]) : "r"(addr));
}
__device__ __forceinline__ void ldsm4t(uint32_t* r, uint32_t addr)
{
    asm volatile("ldmatrix.sync.aligned.m8n8.x4.trans.shared.b16 {%0,%1,%2,%3}, [%4];"
                 : "=r"(r[0]), "=r"(r[1]), "=r"(r[2]), "=r"(r[3]) : "r"(addr));
}

__device__ __forceinline__ uint32_t smem_u32(const void* p)
{
    uint32_t a;
    asm("{ .reg .u64 t; cvta.to.shared.u64 t, %1; cvt.u32.u64 %0, t; }" : "=r"(a) : "l"(p));
    return a;
}

__device__ __forceinline__ void cp16(uint32_t saddr, const void* gaddr)
{
    asm volatile("cp.async.cg.shared.global [%0], [%1], 16;" :: "r"(saddr), "l"(gaddr));
}

// ---------------------------------------------------------------------------
// fp32 -> bf16 hi/lo splitter (te + weights only; x handled inline in embed)
// ---------------------------------------------------------------------------
__global__ void __launch_bounds__(256) split_kernel(
    const float4* __restrict__ src, uint2* __restrict__ hi, uint2* __restrict__ lo, int n4)
{
    int i = blockIdx.x * 256 + threadIdx.x;
    if (i < n4) {
        float4 f = src[i];
        uint32_t h0, l0, h1, l1;
        split2(f.x, f.y, h0, l0);
        split2(f.z, f.w, h1, l1);
        hi[i] = make_uint2(h0, h1);
        lo[i] = make_uint2(l0, l1);
    }
}

// ---------------------------------------------------------------------------
// Shared GEMM epilogue helper (macro-free duplication kept minimal)
// ---------------------------------------------------------------------------
#define GST 24          // smem row stride in bf16 (48 bytes)
#define GBUF 3072       // 128 * 24 bf16 per (part, stage)

// ---------------------------------------------------------------------------
// Fused QKV GEMM: z = blockIdx.z selects (Wq->q, Wk->k, Wv->v).
// A = h (bf16 hi/lo), 128x128x16 double-buffered, 2 CTAs/SM.
// ---------------------------------------------------------------------------
__global__ void __launch_bounds__(256, 2) gemm_qkv(
    const __nv_bfloat16* __restrict__ Ah, const __nv_bfloat16* __restrict__ Al,
    const __nv_bfloat16* __restrict__ Wh0, const __nv_bfloat16* __restrict__ Wl0,
    const __nv_bfloat16* __restrict__ Wh1, const __nv_bfloat16* __restrict__ Wl1,
    const __nv_bfloat16* __restrict__ Wh2, const __nv_bfloat16* __restrict__ Wl2,
    __nv_bfloat16* __restrict__ C0h, __nv_bfloat16* __restrict__ C0l,
    __nv_bfloat16* __restrict__ C1h, __nv_bfloat16* __restrict__ C1l,
    __nv_bfloat16* __restrict__ C2h, __nv_bfloat16* __restrict__ C2l,
    float alpha)
{
    __shared__ __align__(16) __nv_bfloat16 sm[2][4][GBUF];  // 48KB

    const int z = blockIdx.z;
    const __nv_bfloat16* Bh = (z == 0) ? Wh0 : (z == 1) ? Wh1 : Wh2;
    const __nv_bfloat16* Bl = (z == 0) ? Wl0 : (z == 1) ? Wl1 : Wl2;
    __nv_bfloat16* Chi = (z == 0) ? C0h : (z == 1) ? C1h : C2h;
    __nv_bfloat16* Clo = (z == 0) ? C0l : (z == 1) ? C1l : C2l;
    const int M = B_ * T_, N = D_, K = D_;

    const int tid  = threadIdx.x;
    const int lane = tid & 31;
    const int wid  = tid >> 5;
    const int wm   = (wid & 3) * 32;
    const int wn   = (wid >> 2) * 64;
    const int bm   = blockIdx.y * 128;
    const int bn   = blockIdx.x * 128;
    const int g    = lane >> 2;
    const int j    = lane & 3;

    const int lrow  = tid >> 1;
    const int lhalf = tid & 1;
    const __nv_bfloat16* pAh = Ah + (size_t)(bm + lrow) * K + lhalf * 8;
    const __nv_bfloat16* pAl = Al + (size_t)(bm + lrow) * K + lhalf * 8;
    const __nv_bfloat16* pBh = Bh + (size_t)(bn + lrow) * K + lhalf * 8;
    const __nv_bfloat16* pBl = Bl + (size_t)(bn + lrow) * K + lhalf * 8;
    const int sidx = lrow * GST + lhalf * 8;

    const int lr8  = (lane & 7) + ((lane >> 3) & 1) * 8;
    const int lc16 = (lane >> 4) * 16;
    const uint32_t smbase = smem_u32(&sm[0][0][0]);
    uint32_t offA[2], offB[4];
#pragma unroll
    for (int mt = 0; mt < 2; mt++) offA[mt] = (wm + mt * 16 + lr8) * 48 + lc16;
#pragma unroll
    for (int np = 0; np < 4; np++) offB[np] = (wn + np * 16 + lr8) * 48 + lc16;

    float acc[2][8][4];
#pragma unroll
    for (int mt = 0; mt < 2; mt++)
#pragma unroll
        for (int nt = 0; nt < 8; nt++)
#pragma unroll
            for (int i = 0; i < 4; i++) acc[mt][nt][i] = 0.f;

    const int KT = K >> 4;

    {
        *(uint4*)&sm[0][0][sidx] = *(const uint4*)pAh;
        *(uint4*)&sm[0][1][sidx] = *(const uint4*)pAl;
        *(uint4*)&sm[0][2][sidx] = *(const uint4*)pBh;
        *(uint4*)&sm[0][3][sidx] = *(const uint4*)pBl;
    }
    __syncthreads();

    for (int ks = 0; ks < KT; ks++) {
        const int cur = ks & 1, nxt = cur ^ 1;

        uint4 rah, ral, rbh, rbl;
        if (ks + 1 < KT) {
            int k0 = (ks + 1) << 4;
            rah = *(const uint4*)(pAh + k0);
            ral = *(const uint4*)(pAl + k0);
            rbh = *(const uint4*)(pBh + k0);
            rbl = *(const uint4*)(pBl + k0);
        }

        const uint32_t sb = smbase + cur * (4 * GBUF * 2);
        uint32_t fah[2][4], fal[2][4];
#pragma unroll
        for (int mt = 0; mt < 2; mt++) {
            ldsm4(fah[mt], sb + 0 * (GBUF * 2) + offA[mt]);
            ldsm4(fal[mt], sb + 1 * (GBUF * 2) + offA[mt]);
        }
#pragma unroll
        for (int np = 0; np < 4; np++) {
            uint32_t bh[4], bl[4];
            ldsm4(bh, sb + 2 * (GBUF * 2) + offB[np]);
            ldsm4(bl, sb + 3 * (GBUF * 2) + offB[np]);
            uint32_t bA_h[2] = { bh[0], bh[2] }, bB_h[2] = { bh[1], bh[3] };
            uint32_t bA_l[2] = { bl[0], bl[2] }, bB_l[2] = { bl[1], bl[3] };
#pragma unroll
            for (int mt = 0; mt < 2; mt++) {
                mma16816(acc[mt][np * 2],     fah[mt], bA_h);
                mma16816(acc[mt][np * 2],     fal[mt], bA_h);
                mma16816(acc[mt][np * 2],     fah[mt], bA_l);
                mma16816(acc[mt][np * 2 + 1], fah[mt], bB_h);
                mma16816(acc[mt][np * 2 + 1], fal[mt], bB_h);
                mma16816(acc[mt][np * 2 + 1], fah[mt], bB_l);
            }
        }

        if (ks + 1 < KT) {
            *(uint4*)&sm[nxt][0][sidx] = rah;
            *(uint4*)&sm[nxt][1][sidx] = ral;
            *(uint4*)&sm[nxt][2][sidx] = rbh;
            *(uint4*)&sm[nxt][3][sidx] = rbl;
        }
        __syncthreads();
    }

#pragma unroll
    for (int mt = 0; mt < 2; mt++) {
#pragma unroll
        for (int nt = 0; nt < 8; nt++) {
            int row = bm + wm + mt * 16 + g;
            int col = bn + wn + nt * 8 + j * 2;
            float2 v0 = make_float2(acc[mt][nt][0] * alpha, acc[mt][nt][1] * alpha);
            float2 v1 = make_float2(acc[mt][nt][2] * alpha, acc[mt][nt][3] * alpha);
            size_t i0 = (size_t)row * N + col;
            size_t i1 = (size_t)(row + 8) * N + col;
            uint32_t h, l;
            split2(v0.x, v0.y, h, l);
            *(uint32_t*)&Chi[i0] = h; *(uint32_t*)&Clo[i0] = l;
            split2(v1.x, v1.y, h, l);
            *(uint32_t*)&Chi[i1] = h; *(uint32_t*)&Clo[i1] = l;
        }
    }
}

// ---------------------------------------------------------------------------
// NT GEMM, bf16 hi/lo inputs (Wp projection: writes fp32 + hi/lo)
// ---------------------------------------------------------------------------
__global__ void __launch_bounds__(256, 2) gemm_nt_bf16(
    const __nv_bfloat16* __restrict__ Ah, const __nv_bfloat16* __restrict__ Al,
    const __nv_bfloat16* __restrict__ Bh, const __nv_bfloat16* __restrict__ Bl,
    float* __restrict__ Cf, __nv_bfloat16* __restrict__ Chi, __nv_bfloat16* __restrict__ Clo,
    const float* __restrict__ bias, int M, int N, int K, float alpha)
{
    __shared__ __align__(16) __nv_bfloat16 sm[2][4][GBUF];  // 48KB

    const int tid  = threadIdx.x;
    const int lane = tid & 31;
    const int wid  = tid >> 5;
    const int wm   = (wid & 3) * 32;
    const int wn   = (wid >> 2) * 64;
    const int bm   = blockIdx.y * 128;
    const int bn   = blockIdx.x * 128;
    const int g    = lane >> 2;
    const int j    = lane & 3;

    const int lrow  = tid >> 1;
    const int lhalf = tid & 1;
    const __nv_bfloat16* pAh = Ah + (size_t)(bm + lrow) * K + lhalf * 8;
    const __nv_bfloat16* pAl = Al + (size_t)(bm + lrow) * K + lhalf * 8;
    const __nv_bfloat16* pBh = Bh + (size_t)(bn + lrow) * K + lhalf * 8;
    const __nv_bfloat16* pBl = Bl + (size_t)(bn + lrow) * K + lhalf * 8;
    const int sidx = lrow * GST + lhalf * 8;

    const int lr8  = (lane & 7) + ((lane >> 3) & 1) * 8;
    const int lc16 = (lane >> 4) * 16;
    const uint32_t smbase = smem_u32(&sm[0][0][0]);
    uint32_t offA[2], offB[4];
#pragma unroll
    for (int mt = 0; mt < 2; mt++) offA[mt] = (wm + mt * 16 + lr8) * 48 + lc16;
#pragma unroll
    for (int np = 0; np < 4; np++) offB[np] = (wn + np * 16 + lr8) * 48 + lc16;

    float acc[2][8][4];
#pragma unroll
    for (int mt = 0; mt < 2; mt++)
#pragma unroll
        for (int nt = 0; nt < 8; nt++)
#pragma unroll
            for (int i = 0; i < 4; i++) acc[mt][nt][i] = 0.f;

    const int KT = K >> 4;

    {
        *(uint4*)&sm[0][0][sidx] = *(const uint4*)pAh;
        *(uint4*)&sm[0][1][sidx] = *(const uint4*)pAl;
        *(uint4*)&sm[0][2][sidx] = *(const uint4*)pBh;
        *(uint4*)&sm[0][3][sidx] = *(const uint4*)pBl;
    }
    __syncthreads();

    for (int ks = 0; ks < KT; ks++) {
        const int cur = ks & 1, nxt = cur ^ 1;

        uint4 rah, ral, rbh, rbl;
        if (ks + 1 < KT) {
            int k0 = (ks + 1) << 4;
            rah = *(const uint4*)(pAh + k0);
            ral = *(const uint4*)(pAl + k0);
            rbh = *(const uint4*)(pBh + k0);
            rbl = *(const uint4*)(pBl + k0);
        }

        const uint32_t sb = smbase + cur * (4 * GBUF * 2);
        uint32_t fah[2][4], fal[2][4];
#pragma unroll
        for (int mt = 0; mt < 2; mt++) {
            ldsm4(fah[mt], sb + 0 * (GBUF * 2) + offA[mt]);
            ldsm4(fal[mt], sb + 1 * (GBUF * 2) + offA[mt]);
        }
#pragma unroll
        for (int np = 0; np < 4; np++) {
            uint32_t bh[4], bl[4];
            ldsm4(bh, sb + 2 * (GBUF * 2) + offB[np]);
            ldsm4(bl, sb + 3 * (GBUF * 2) + offB[np]);
            uint32_t bA_h[2] = { bh[0], bh[2] }, bB_h[2] = { bh[1], bh[3] };
            uint32_t bA_l[2] = { bl[0], bl[2] }, bB_l[2] = { bl[1], bl[3] };
#pragma unroll
            for (int mt = 0; mt < 2; mt++) {
                mma16816(acc[mt][np * 2],     fah[mt], bA_h);
                mma16816(acc[mt][np * 2],     fal[mt], bA_h);
                mma16816(acc[mt][np * 2],     fah[mt], bA_l);
                mma16816(acc[mt][np * 2 + 1], fah[mt], bB_h);
                mma16816(acc[mt][np * 2 + 1], fal[mt], bB_h);
                mma16816(acc[mt][np * 2 + 1], fah[mt], bB_l);
            }
        }

        if (ks + 1 < KT) {
            *(uint4*)&sm[nxt][0][sidx] = rah;
            *(uint4*)&sm[nxt][1][sidx] = ral;
            *(uint4*)&sm[nxt][2][sidx] = rbh;
            *(uint4*)&sm[nxt][3][sidx] = rbl;
        }
        __syncthreads();
    }

#pragma unroll
    for (int mt = 0; mt < 2; mt++) {
#pragma unroll
        for (int nt = 0; nt < 8; nt++) {
            int row = bm + wm + mt * 16 + g;
            int col = bn + wn + nt * 8 + j * 2;
            float2 v0 = make_float2(acc[mt][nt][0] * alpha, acc[mt][nt][1] * alpha);
            float2 v1 = make_float2(acc[mt][nt][2] * alpha, acc[mt][nt][3] * alpha);
            if (bias) {
                const float* b0 = bias + (size_t)(row & (T_ - 1)) * N + col;
                const float* b1 = bias + (size_t)((row + 8) & (T_ - 1)) * N + col;
                v0.x += b0[0]; v0.y += b0[1];
                v1.x += b1[0]; v1.y += b1[1];
            }
            size_t i0 = (size_t)row * N + col;
            size_t i1 = (size_t)(row + 8) * N + col;
            if (Cf) {
                *(float2*)&Cf[i0] = v0;
                *(float2*)&Cf[i1] = v1;
            }
            uint32_t h, l;
            split2(v0.x, v0.y, h, l);
            *(uint32_t*)&Chi[i0] = h; *(uint32_t*)&Clo[i0] = l;
            split2(v1.x, v1.y, h, l);
            *(uint32_t*)&Chi[i1] = h; *(uint32_t*)&Clo[i1] = l;
        }
    }
}

// ---------------------------------------------------------------------------
// Embed GEMM: A is fp32 (x), split inline in the loader; B pre-split bf16.
// C = alpha * A @ B^T + bias; writes bf16 hi/lo.
// ---------------------------------------------------------------------------
__global__ void __launch_bounds__(256, 2) gemm_nt_f32a(
    const float* __restrict__ Af,
    const __nv_bfloat16* __restrict__ Bh, const __nv_bfloat16* __restrict__ Bl,
    __nv_bfloat16* __restrict__ Chi, __nv_bfloat16* __restrict__ Clo,
    const float* __restrict__ bias, int M, int N, int K, float alpha)
{
    __shared__ __align__(16) __nv_bfloat16 sm[2][4][GBUF];  // 48KB

    const int tid  = threadIdx.x;
    const int lane = tid & 31;
    const int wid  = tid >> 5;
    const int wm   = (wid & 3) * 32;
    const int wn   = (wid >> 2) * 64;
    const int bm   = blockIdx.y * 128;
    const int bn   = blockIdx.x * 128;
    const int g    = lane >> 2;
    const int j    = lane & 3;

    const int lrow  = tid >> 1;
    const int lhalf = tid & 1;
    const float* pAf = Af + (size_t)(bm + lrow) * K + lhalf * 8;
    const __nv_bfloat16* pBh = Bh + (size_t)(bn + lrow) * K + lhalf * 8;
    const __nv_bfloat16* pBl = Bl + (size_t)(bn + lrow) * K + lhalf * 8;
    const int sidx = lrow * GST + lhalf * 8;

    const int lr8  = (lane & 7) + ((lane >> 3) & 1) * 8;
    const int lc16 = (lane >> 4) * 16;
    const uint32_t smbase = smem_u32(&sm[0][0][0]);
    uint32_t offA[2], offB[4];
#pragma unroll
    for (int mt = 0; mt < 2; mt++) offA[mt] = (wm + mt * 16 + lr8) * 48 + lc16;
#pragma unroll
    for (int np = 0; np < 4; np++) offB[np] = (wn + np * 16 + lr8) * 48 + lc16;

    float acc[2][8][4];
#pragma unroll
    for (int mt = 0; mt < 2; mt++)
#pragma unroll
        for (int nt = 0; nt < 8; nt++)
#pragma unroll
            for (int i = 0; i < 4; i++) acc[mt][nt][i] = 0.f;

    const int KT = K >> 4;

    // prologue: stage 0 (split A inline)
    {
        float4 f0 = *(const float4*)(pAf);
        float4 f1 = *(const float4*)(pAf + 4);
        uint32_t h[4], l[4];
        split2(f0.x, f0.y, h[0], l[0]);
        split2(f0.z, f0.w, h[1], l[1]);
        split2(f1.x, f1.y, h[2], l[2]);
        split2(f1.z, f1.w, h[3], l[3]);
        *(uint4*)&sm[0][0][sidx] = make_uint4(h[0], h[1], h[2], h[3]);
        *(uint4*)&sm[0][1][sidx] = make_uint4(l[0], l[1], l[2], l[3]);
        *(uint4*)&sm[0][2][sidx] = *(const uint4*)pBh;
        *(uint4*)&sm[0][3][sidx] = *(const uint4*)pBl;
    }
    __syncthreads();

    for (int ks = 0; ks < KT; ks++) {
        const int cur = ks & 1, nxt = cur ^ 1;

        float4 rf0, rf1;
        uint4 rbh, rbl;
        if (ks + 1 < KT) {
            int k0 = (ks + 1) << 4;
            rf0 = *(const float4*)(pAf + k0);
            rf1 = *(const float4*)(pAf + k0 + 4);
            rbh = *(const uint4*)(pBh + k0);
            rbl = *(const uint4*)(pBl + k0);
        }

        const uint32_t sb = smbase + cur * (4 * GBUF * 2);
        uint32_t fah[2][4], fal[2][4];
#pragma unroll
        for (int mt = 0; mt < 2; mt++) {
            ldsm4(fah[mt], sb + 0 * (GBUF * 2) + offA[mt]);
            ldsm4(fal[mt], sb + 1 * (GBUF * 2) + offA[mt]);
        }
#pragma unroll
        for (int np = 0; np < 4; np++) {
            uint32_t bh[4], bl[4];
            ldsm4(bh, sb + 2 * (GBUF * 2) + offB[np]);
            ldsm4(bl, sb + 3 * (GBUF * 2) + offB[np]);
            uint32_t bA_h[2] = { bh[0], bh[2] }, bB_h[2] = { bh[1], bh[3] };
            uint32_t bA_l[2] = { bl[0], bl[2] }, bB_l[2] = { bl[1], bl[3] };
#pragma unroll
            for (int mt = 0; mt < 2; mt++) {
                mma16816(acc[mt][np * 2],     fah[mt], bA_h);
                mma16816(acc[mt][np * 2],     fal[mt], bA_h);
                mma16816(acc[mt][np * 2],     fah[mt], bA_l);
                mma16816(acc[mt][np * 2 + 1], fah[mt], bB_h);
                mma16816(acc[mt][np * 2 + 1], fal[mt], bB_h);
                mma16816(acc[mt][np * 2 + 1], fah[mt], bB_l);
            }
        }

        if (ks + 1 < KT) {
            uint32_t h[4], l[4];
            split2(rf0.x, rf0.y, h[0], l[0]);
            split2(rf0.z, rf0.w, h[1], l[1]);
            split2(rf1.x, rf1.y, h[2], l[2]);
            split2(rf1.z, rf1.w, h[3], l[3]);
            *(uint4*)&sm[nxt][0][sidx] = make_uint4(h[0], h[1], h[2], h[3]);
            *(uint4*)&sm[nxt][1][sidx] = make_uint4(l[0], l[1], l[2], l[3]);
            *(uint4*)&sm[nxt][2][sidx] = rbh;
            *(uint4*)&sm[nxt][3][sidx] = rbl;
        }
        __syncthreads();
    }

#pragma unroll
    for (int mt = 0; mt < 2; mt++) {
#pragma unroll
        for (int nt = 0; nt < 8; nt++) {
            int row = bm + wm + mt * 16 + g;
            int col = bn + wn + nt * 8 + j * 2;
            float2 v0 = make_float2(acc[mt][nt][0] * alpha, acc[mt][nt][1] * alpha);
            float2 v1 = make_float2(acc[mt][nt][2] * alpha, acc[mt][nt][3] * alpha);
            const float* b0 = bias + (size_t)(row & (T_ - 1)) * N + col;
            const float* b1 = bias + (size_t)((row + 8) & (T_ - 1)) * N + col;
            v0.x += b0[0]; v0.y += b0[1];
            v1.x += b1[0]; v1.y += b1[1];
            size_t i0 = (size_t)row * N + col;
            size_t i1 = (size_t)(row + 8) * N + col;
            uint32_t h, l;
            split2(v0.x, v0.y, h, l);
            *(uint32_t*)&Chi[i0] = h; *(uint32_t*)&Clo[i0] = l;
            split2(v1.x, v1.y, h, l);
            *(uint32_t*)&Chi[i1] = h; *(uint32_t*)&Clo[i1] = l;
        }
    }
}

// ---------------------------------------------------------------------------
// Flash attention, cp.async double-buffered, fixed-offset softmax (ex2.approx).
// ---------------------------------------------------------------------------
#define ASTR       72                 // bf16 row stride (144 bytes)
#define A_ARR      9216               // bytes per array (64 rows * 144B)
#define A_STAGE    (4 * A_ARR)        // Kh,Kl,Vh,Vl per stage = 36864B
#define A_SMEM     (2 * A_STAGE)      // 73728B
#define SM_OFF     6.0f               // softmax exponent offset (log2 units)

extern __shared__ char attnsmem[];

__device__ __forceinline__ void attn_issue(
    uint32_t sbase, int s,
    const __nv_bfloat16* Kh, const __nv_bfloat16* Kl,
    const __nv_bfloat16* Vh, const __nv_bfloat16* Vl,
    size_t base, int t, int ldrow, int ldc)
{
    size_t grow = base + (size_t)(t * 64 + ldrow) * D_;
    uint32_t so = sbase + s * A_STAGE + ldrow * 144;
    cp16(so + 0 * A_ARR + ldc * 16,       Kh + grow + ldc * 8);
    cp16(so + 0 * A_ARR + (ldc + 4) * 16, Kh + grow + (ldc + 4) * 8);
    cp16(so + 1 * A_ARR + ldc * 16,       Kl + grow + ldc * 8);
    cp16(so + 1 * A_ARR + (ldc + 4) * 16, Kl + grow + (ldc + 4) * 8);
    cp16(so + 2 * A_ARR + ldc * 16,       Vh + grow + ldc * 8);
    cp16(so + 2 * A_ARR + (ldc + 4) * 16, Vh + grow + (ldc + 4) * 8);
    cp16(so + 3 * A_ARR + ldc * 16,       Vl + grow + ldc * 8);
    cp16(so + 3 * A_ARR + (ldc + 4) * 16, Vl + grow + (ldc + 4) * 8);
    asm volatile("cp.async.commit_group;" ::: "memory");
}

__global__ void __launch_bounds__(256) attn_bf16(
    const __nv_bfloat16* __restrict__ Qh, const __nv_bfloat16* __restrict__ Ql,
    const __nv_bfloat16* __restrict__ Kh, const __nv_bfloat16* __restrict__ Kl,
    const __nv_bfloat16* __restrict__ Vh, const __nv_bfloat16* __restrict__ Vl,
    __nv_bfloat16* __restrict__ Ohi, __nv_bfloat16* __restrict__ Olo)
{
    const int tid  = threadIdx.x;
    const int lane = tid & 31;
    const int wid  = tid >> 5;
    const int g    = lane >> 2;
    const int j    = lane & 3;

    const int q0 = blockIdx.x * 128;
    const int hh = blockIdx.y;
    const int bb = blockIdx.z;
    const size_t base = ((size_t)bb * T_) * D_ + (size_t)hh * HD_;

    const int ldrow = tid >> 2;
    const int ldc   = tid & 3;
    const uint32_t sbase = smem_u32(attnsmem);

    attn_issue(sbase, 0, Kh, Kl, Vh, Vl, base, 0, ldrow, ldc);

    // ---- Q fragments; fold in 0.125*log2(e) with full re-split ----
    uint32_t Qfh[4][4], Qfl[4][4];
    {
        const uint32_t* qh32 = (const uint32_t*)(Qh + base);
        const uint32_t* ql32 = (const uint32_t*)(Ql + base);
        int r0 = q0 + wid * 16 + g;
        const float SC = 0.18033688011112042f;  // 0.125 * log2(e)
#pragma unroll
        for (int kf = 0; kf < 4; kf++) {
            int w0 = kf * 8 + j, w1 = kf * 8 + 4 + j;
            uint32_t rh[4], rl[4];
            rh[0] = qh32[(size_t)r0 * (D_ / 2) + w0];
            rh[1] = qh32[(size_t)(r0 + 8) * (D_ / 2) + w0];
            rh[2] = qh32[(size_t)r0 * (D_ / 2) + w1];
            rh[3] = qh32[(size_t)(r0 + 8) * (D_ / 2) + w1];
            rl[0] = ql32[(size_t)r0 * (D_ / 2) + w0];
            rl[1] = ql32[(size_t)(r0 + 8) * (D_ / 2) + w0];
            rl[2] = ql32[(size_t)r0 * (D_ / 2) + w1];
            rl[3] = ql32[(size_t)(r0 + 8) * (D_ / 2) + w1];
#pragma unroll
            for (int i = 0; i < 4; i++) {
                float2 a = __bfloat1622float2(*(__nv_bfloat162*)&rh[i]);
                float2 b = __bfloat1622float2(*(__nv_bfloat162*)&rl[i]);
                split2((a.x + b.x) * SC, (a.y + b.y) * SC, Qfh[kf][i], Qfl[kf][i]);
            }
        }
    }

    const int lr8  = (lane & 7) + ((lane >> 3) & 1) * 8;
    const int lc16 = (lane >> 4) * 16;

    float oac[8][4];
#pragma unroll
    for (int nt = 0; nt < 8; nt++)
#pragma unroll
        for (int i = 0; i < 4; i++) oac[nt][i] = 0.f;
    float l0 = 0.f, l1 = 0.f;

    const int NTILE = T_ / 64;

    for (int t = 0; t < NTILE; t++) {
        const int s = t & 1;

        if (t + 1 < NTILE) {
            attn_issue(sbase, s ^ 1, Kh, Kl, Vh, Vl, base, t + 1, ldrow, ldc);
            asm volatile("cp.async.wait_group 1;" ::: "memory");
        } else {
            asm volatile("cp.async.wait_group 0;" ::: "memory");
        }
        __syncthreads();

        const uint32_t kh_b = sbase + s * A_STAGE + 0 * A_ARR;
        const uint32_t kl_b = sbase + s * A_STAGE + 1 * A_ARR;
        const uint32_t vh_b = sbase + s * A_STAGE + 2 * A_ARR;
        const uint32_t vl_b = sbase + s * A_STAGE + 3 * A_ARR;

        float sac[8][4];
#pragma unroll
        for (int nt = 0; nt < 8; nt++)
#pragma unroll
            for (int i = 0; i < 4; i++) sac[nt][i] = 0.f;

#pragma unroll
        for (int kf = 0; kf < 4; kf++) {
#pragma unroll
            for (int np = 0; np < 4; np++) {
                uint32_t off = (np * 16 + lr8) * 144 + kf * 32 + lc16;
                uint32_t bh[4], bl[4];
                ldsm4(bh, kh_b + off);
                ldsm4(bl, kl_b + off);
                uint32_t bA_h[2] = { bh[0], bh[2] }, bB_h[2] = { bh[1], bh[3] };
                uint32_t bA_l[2] = { bl[0], bl[2] }, bB_l[2] = { bl[1], bl[3] };
                mma16816(sac[np * 2],     Qfh[kf], bA_h);
                mma16816(sac[np * 2],     Qfl[kf], bA_h);
                mma16816(sac[np * 2],     Qfh[kf], bA_l);
                mma16816(sac[np * 2 + 1], Qfh[kf], bB_h);
                mma16816(sac[np * 2 + 1], Qfl[kf], bB_h);
                mma16816(sac[np * 2 + 1], Qfh[kf], bB_l);
            }
        }

        // fixed-offset softmax: p = 2^(sac - 6)
        float rs0 = 0.f, rs1 = 0.f;
#pragma unroll
        for (int nt = 0; nt < 8; nt++) {
            sac[nt][0] = ex2(sac[nt][0] - SM_OFF);
            sac[nt][1] = ex2(sac[nt][1] - SM_OFF);
            sac[nt][2] = ex2(sac[nt][2] - SM_OFF);
            sac[nt][3] = ex2(sac[nt][3] - SM_OFF);
            rs0 += sac[nt][0] + sac[nt][1];
            rs1 += sac[nt][2] + sac[nt][3];
        }
        l0 += rs0;
        l1 += rs1;

#pragma unroll
        for (int kf = 0; kf < 4; kf++) {
            uint32_t ph[4], pl[4];
            split2(sac[2 * kf][0],     sac[2 * kf][1],     ph[0], pl[0]);
            split2(sac[2 * kf][2],     sac[2 * kf][3],     ph[1], pl[1]);
            split2(sac[2 * kf + 1][0], sac[2 * kf + 1][1], ph[2], pl[2]);
            split2(sac[2 * kf + 1][2], sac[2 * kf + 1][3], ph[3], pl[3]);
#pragma unroll
            for (int np = 0; np < 4; np++) {
                uint32_t off = (kf * 16 + lr8) * 144 + np * 32 + lc16;
                uint32_t vh[4], vl[4];
                ldsm4t(vh, vh_b + off);
                ldsm4t(vl, vl_b + off);
                uint32_t vA_h[2] = { vh[0], vh[1] }, vB_h[2] = { vh[2], vh[3] };
                uint32_t vA_l[2] = { vl[0], vl[1] }, vB_l[2] = { vl[2], vl[3] };
                mma16816(oac[np * 2],     ph, vA_h);
                mma16816(oac[np * 2],     pl, vA_h);
                mma16816(oac[np * 2],     ph, vA_l);
                mma16816(oac[np * 2 + 1], ph, vB_h);
                mma16816(oac[np * 2 + 1], pl, vB_h);
                mma16816(oac[np * 2 + 1], ph, vB_l);
            }
        }
        __syncthreads();
    }

#pragma unroll
    for (int off = 1; off <= 2; off <<= 1) {
        l0 += __shfl_xor_sync(0xffffffffu, l0, off);
        l1 += __shfl_xor_sync(0xffffffffu, l1, off);
    }
    float inv0 = 1.f / l0, inv1 = 1.f / l1;
    int row = q0 + wid * 16 + g;
    uint32_t* oh32 = (uint32_t*)(Ohi + base);
    uint32_t* ol32 = (uint32_t*)(Olo + base);
#pragma unroll
    for (int nt = 0; nt < 8; nt++) {
        int w = nt * 4 + j;
        uint32_t h, l;
        split2(oac[nt][0] * inv0, oac[nt][1] * inv0, h, l);
        oh32[(size_t)row * (D_ / 2) + w] = h;
        ol32[(size_t)row * (D_ / 2) + w] = l;
        split2(oac[nt][2] * inv1, oac[nt][3] * inv1, h, l);
        oh32[(size_t)(row + 8) * (D_ / 2) + w] = h;
        ol32[(size_t)(row + 8) * (D_ / 2) + w] = l;
    }
}

// ---------------------------------------------------------------------------
__global__ void __launch_bounds__(256) readout_kernel(
    const float* __restrict__ hbuf, const float* __restrict__ R,
    float* __restrict__ out)
{
    __shared__ float hs[B_][D_];
    for (int i = threadIdx.x; i < B_ * D_; i += 256) {
        int b = i >> 9, d = i & 511;
        hs[b][d] = hbuf[((size_t)b * T_ + (T_ - 1)) * D_ + d];
    }
    __syncthreads();

    int v = blockIdx.x * 256 + threadIdx.x;
    float a0 = 0.f, a1 = 0.f, a2 = 0.f, a3 = 0.f;
    const float* r = R + (size_t)v * D_;
    for (int d = 0; d < D_; d += 4) {
        float4 rv = *(const float4*)(r + d);
        a0 += rv.x * hs[0][d] + rv.y * hs[0][d + 1] + rv.z * hs[0][d + 2] + rv.w * hs[0][d + 3];
        a1 += rv.x * hs[1][d] + rv.y * hs[1][d + 1] + rv.z * hs[1][d + 2] + rv.w * hs[1][d + 3];
        a2 += rv.x * hs[2][d] + rv.y * hs[2][d + 1] + rv.z * hs[2][d + 2] + rv.w * hs[2][d + 3];
        a3 += rv.x * hs[3][d] + rv.y * hs[3][d + 1] + rv.z * hs[3][d + 2] + rv.w * hs[3][d + 3];
    }
    const float sc = 0.04419417382415922f;
    out[0 * V_ + v] = a0 * sc;
    out[1 * V_ + v] = a1 * sc;
    out[2 * V_ + v] = a2 * sc;
    out[3 * V_ + v] = a3 * sc;
}

// ---------------------------------------------------------------------------
extern "C" void kernel_launch(void* const* d_in, const int* in_sizes, int n_in,
                              void* d_out, int out_size)
{
    const float* x  = (const float*)d_in[0];
    const float* te = (const float*)d_in[1];
    const float* pe = (const float*)d_in[2];
    const float* Wk = (const float*)d_in[3];
    const float* Wq = (const float*)d_in[4];
    const float* Wv = (const float*)d_in[5];
    const float* Wp = (const float*)d_in[6];
    const float* ro = (const float*)d_in[7];
    float* out = (float*)d_out;

    float* hf;
    __nv_bfloat16 *hh, *hl, *qh, *ql, *kh, *kl, *vh, *vl, *oh, *ol;
    __nv_bfloat16 *teh, *tel;
    __nv_bfloat16 *wqh, *wql, *wkh, *wkl, *wvh, *wvl, *wph, *wpl;
    cudaGetSymbolAddress((void**)&hf,  g_h);
    cudaGetSymbolAddress((void**)&hh,  g_hh);  cudaGetSymbolAddress((void**)&hl, g_hl);
    cudaGetSymbolAddress((void**)&qh,  g_qh);  cudaGetSymbolAddress((void**)&ql, g_ql);
    cudaGetSymbolAddress((void**)&kh,  g_kh);  cudaGetSymbolAddress((void**)&kl, g_kl);
    cudaGetSymbolAddress((void**)&vh,  g_vh);  cudaGetSymbolAddress((void**)&vl, g_vl);
    cudaGetSymbolAddress((void**)&oh,  g_oh);  cudaGetSymbolAddress((void**)&ol, g_ol);
    cudaGetSymbolAddress((void**)&teh, g_teh); cudaGetSymbolAddress((void**)&tel, g_tel);
    cudaGetSymbolAddress((void**)&wqh, g_wqh); cudaGetSymbolAddress((void**)&wql, g_wql);
    cudaGetSymbolAddress((void**)&wkh, g_wkh); cudaGetSymbolAddress((void**)&wkl, g_wkl);
    cudaGetSymbolAddress((void**)&wvh, g_wvh); cudaGetSymbolAddress((void**)&wvl, g_wvl);
    cudaGetSymbolAddress((void**)&wph, g_wph); cudaGetSymbolAddress((void**)&wpl, g_wpl);

    cudaFuncSetAttribute(attn_bf16, cudaFuncAttributeMaxDynamicSharedMemorySize, A_SMEM);

    const float sV = 0.022097086912079608f;  // 1/sqrt(2048)
    const float sD = 0.04419417382415922f;   // 1/sqrt(512)

    {
        int n4 = (D_ * V_) / 4;
        split_kernel<<<(n4 + 255) / 256, 256>>>((const float4*)te, (uint2*)teh, (uint2*)tel, n4);
        n4 = (L_ * D_ * D_) / 4;
        split_kernel<<<(n4 + 255) / 256, 256>>>((const float4*)Wq, (uint2*)wqh, (uint2*)wql, n4);
        split_kernel<<<(n4 + 255) / 256, 256>>>((const float4*)Wk, (uint2*)wkh, (uint2*)wkl, n4);
        split_kernel<<<(n4 + 255) / 256, 256>>>((const float4*)Wv, (uint2*)wvh, (uint2*)wvl, n4);
        split_kernel<<<(n4 + 255) / 256, 256>>>((const float4*)Wp, (uint2*)wph, (uint2*)wpl, n4);
    }

    dim3 ggrid(D_ / 128, (B_ * T_) / 128);           // (4, 64)
    dim3 qkvgrid(D_ / 128, (B_ * T_) / 128, 3);      // (4, 64, 3)

    // embed: h = x @ TE^T / sqrt(V) + pos (A = fp32 x, split inline)
    gemm_nt_f32a<<<ggrid, 256>>>(x, teh, tel, hh, hl, pe, B_ * T_, D_, V_, sV);

    for (int l = 0; l < L_; l++) {
        size_t wo = (size_t)l * D_ * D_;
        gemm_qkv<<<qkvgrid, 256>>>(hh, hl,
                                   wqh + wo, wql + wo, wkh + wo, wkl + wo, wvh + wo, wvl + wo,
                                   qh, ql, kh, kl, vh, vl, sD);

        attn_bf16<<<dim3(T_ / 128, H_, B_), 256, A_SMEM>>>(qh, ql, kh, kl, vh, vl, oh, ol);

        gemm_nt_bf16<<<ggrid, 256>>>(oh, ol, wph + wo, wpl + wo,
                                     hf, hh, hl, nullptr, B_ * T_, D_, D_, sD);
    }

    readout_kernel<<<V_ / 256, 256>>>(hf, ro, out);
}

// round 9
// speedup vs baseline: 2.8032x; 1.0917x over previous
#include <cuda_runtime.h>
#include <cuda_bf16.h>
#include <math.h>
#include <stdint.h>

#define B_  4
#define T_  2048
#define V_  2048
#define D_  512
#define H_  8
#define L_  4
#define HD_ 64
#define NT_ (B_ * T_ * D_)   // 4M elems

// ---- global scratch (no allocation allowed) ----
__device__ __align__(16) float g_h[NT_];                       // fp32 h (for readout)
__device__ __align__(16) __nv_bfloat16 g_hh[NT_], g_hl[NT_];
__device__ __align__(16) __nv_bfloat16 g_qh[NT_], g_ql[NT_];
__device__ __align__(16) __nv_bfloat16 g_kh[NT_], g_kl[NT_];
__device__ __align__(16) __nv_bfloat16 g_vh[NT_], g_vl[NT_];
__device__ __align__(16) __nv_bfloat16 g_oh[NT_], g_ol[NT_];
__device__ __align__(16) __nv_bfloat16 g_teh[D_ * V_], g_tel[D_ * V_];
__device__ __align__(16) __nv_bfloat16 g_wqh[L_ * D_ * D_], g_wql[L_ * D_ * D_];
__device__ __align__(16) __nv_bfloat16 g_wkh[L_ * D_ * D_], g_wkl[L_ * D_ * D_];
__device__ __align__(16) __nv_bfloat16 g_wvh[L_ * D_ * D_], g_wvl[L_ * D_ * D_];
__device__ __align__(16) __nv_bfloat16 g_wph[L_ * D_ * D_], g_wpl[L_ * D_ * D_];

// ---------------------------------------------------------------------------
// Packed bf16x3 split: a = hi + lo.  Uses vector converts (fewer issue slots).
// ---------------------------------------------------------------------------
__device__ __forceinline__ void split2(float x, float y, uint32_t& h, uint32_t& l)
{
    __nv_bfloat162 hv = __float22bfloat162_rn(make_float2(x, y));
    float2 hf2 = __bfloat1622float2(hv);
    __nv_bfloat162 lv = __float22bfloat162_rn(make_float2(x - hf2.x, y - hf2.y));
    h = *reinterpret_cast<uint32_t*>(&hv);
    l = *reinterpret_cast<uint32_t*>(&lv);
}

__device__ __forceinline__ float ex2(float x)
{
    float y;
    asm("ex2.approx.f32 %0, %1;" : "=f"(y) : "f"(x));
    return y;
}

__device__ __forceinline__ void mma16816(float* d, const uint32_t* a, const uint32_t* b)
{
    asm volatile(
        "mma.sync.aligned.m16n8k16.row.col.f32.bf16.bf16.f32 "
        "{%0,%1,%2,%3}, {%4,%5,%6,%7}, {%8,%9}, {%0,%1,%2,%3};\n"
        : "+f"(d[0]), "+f"(d[1]), "+f"(d[2]), "+f"(d[3])
        : "r"(a[0]), "r"(a[1]), "r"(a[2]), "r"(a[3]), "r"(b[0]), "r"(b[1]));
}

__device__ __forceinline__ void ldsm4(uint32_t* r, uint32_t addr)
{
    asm volatile("ldmatrix.sync.aligned.m8n8.x4.shared.b16 {%0,%1,%2,%3}, [%4];"
                 : "=r"(r[0]), "=r"(r[1]), "=r"(r[2]), "=r"(r[3]) : "r"(addr));
}
__device__ __forceinline__ void ldsm4t(uint32_t* r, uint32_t addr)
{
    asm volatile("ldmatrix.sync.aligned.m8n8.x4.trans.shared.b16 {%0,%1,%2,%3}, [%4];"
                 : "=r"(r[0]), "=r"(r[1]), "=r"(r[2]), "=r"(r[3]) : "r"(addr));
}

__device__ __forceinline__ uint32_t smem_u32(const void* p)
{
    uint32_t a;
    asm("{ .reg .u64 t; cvta.to.shared.u64 t, %1; cvt.u32.u64 %0, t; }" : "=r"(a) : "l"(p));
    return a;
}

__device__ __forceinline__ void cp16(uint32_t saddr, const void* gaddr)
{
    asm volatile("cp.async.cg.shared.global [%0], [%1], 16;" :: "r"(saddr), "l"(gaddr));
}

// ---------------------------------------------------------------------------
// fp32 -> bf16 hi/lo splitter (te + weights only)
// ---------------------------------------------------------------------------
__global__ void __launch_bounds__(256) split_kernel(
    const float4* __restrict__ src, uint2* __restrict__ hi, uint2* __restrict__ lo, int n4)
{
    int i = blockIdx.x * 256 + threadIdx.x;
    if (i < n4) {
        float4 f = src[i];
        uint32_t h0, l0, h1, l1;
        split2(f.x, f.y, h0, l0);
        split2(f.z, f.w, h1, l1);
        hi[i] = make_uint2(h0, h1);
        lo[i] = make_uint2(l0, l1);
    }
}

#define GST 24          // smem row stride in bf16 (48 bytes)
#define GBUF 3072       // 128 * 24 bf16 per (part, stage)

// ---------------------------------------------------------------------------
// Fused QKV GEMM: blockIdx.z selects (Wq->q, Wk->k, Wv->v).
// ---------------------------------------------------------------------------
__global__ void __launch_bounds__(256, 2) gemm_qkv(
    const __nv_bfloat16* __restrict__ Ah, const __nv_bfloat16* __restrict__ Al,
    const __nv_bfloat16* __restrict__ Wh0, const __nv_bfloat16* __restrict__ Wl0,
    const __nv_bfloat16* __restrict__ Wh1, const __nv_bfloat16* __restrict__ Wl1,
    const __nv_bfloat16* __restrict__ Wh2, const __nv_bfloat16* __restrict__ Wl2,
    __nv_bfloat16* __restrict__ C0h, __nv_bfloat16* __restrict__ C0l,
    __nv_bfloat16* __restrict__ C1h, __nv_bfloat16* __restrict__ C1l,
    __nv_bfloat16* __restrict__ C2h, __nv_bfloat16* __restrict__ C2l,
    float alpha)
{
    __shared__ __align__(16) __nv_bfloat16 sm[2][4][GBUF];  // 48KB

    const int z = blockIdx.z;
    const __nv_bfloat16* Bh = (z == 0) ? Wh0 : (z == 1) ? Wh1 : Wh2;
    const __nv_bfloat16* Bl = (z == 0) ? Wl0 : (z == 1) ? Wl1 : Wl2;
    __nv_bfloat16* Chi = (z == 0) ? C0h : (z == 1) ? C1h : C2h;
    __nv_bfloat16* Clo = (z == 0) ? C0l : (z == 1) ? C1l : C2l;
    const int N = D_, K = D_;

    const int tid  = threadIdx.x;
    const int lane = tid & 31;
    const int wid  = tid >> 5;
    const int wm   = (wid & 3) * 32;
    const int wn   = (wid >> 2) * 64;
    const int bm   = blockIdx.y * 128;
    const int bn   = blockIdx.x * 128;
    const int g    = lane >> 2;
    const int j    = lane & 3;

    const int lrow  = tid >> 1;
    const int lhalf = tid & 1;
    const __nv_bfloat16* pAh = Ah + (size_t)(bm + lrow) * K + lhalf * 8;
    const __nv_bfloat16* pAl = Al + (size_t)(bm + lrow) * K + lhalf * 8;
    const __nv_bfloat16* pBh = Bh + (size_t)(bn + lrow) * K + lhalf * 8;
    const __nv_bfloat16* pBl = Bl + (size_t)(bn + lrow) * K + lhalf * 8;
    const int sidx = lrow * GST + lhalf * 8;

    const int lr8  = (lane & 7) + ((lane >> 3) & 1) * 8;
    const int lc16 = (lane >> 4) * 16;
    const uint32_t smbase = smem_u32(&sm[0][0][0]);
    uint32_t offA[2], offB[4];
#pragma unroll
    for (int mt = 0; mt < 2; mt++) offA[mt] = (wm + mt * 16 + lr8) * 48 + lc16;
#pragma unroll
    for (int np = 0; np < 4; np++) offB[np] = (wn + np * 16 + lr8) * 48 + lc16;

    float acc[2][8][4];
#pragma unroll
    for (int mt = 0; mt < 2; mt++)
#pragma unroll
        for (int nt = 0; nt < 8; nt++)
#pragma unroll
            for (int i = 0; i < 4; i++) acc[mt][nt][i] = 0.f;

    const int KT = K >> 4;

    {
        *(uint4*)&sm[0][0][sidx] = *(const uint4*)pAh;
        *(uint4*)&sm[0][1][sidx] = *(const uint4*)pAl;
        *(uint4*)&sm[0][2][sidx] = *(const uint4*)pBh;
        *(uint4*)&sm[0][3][sidx] = *(const uint4*)pBl;
    }
    __syncthreads();

    for (int ks = 0; ks < KT; ks++) {
        const int cur = ks & 1, nxt = cur ^ 1;

        uint4 rah, ral, rbh, rbl;
        if (ks + 1 < KT) {
            int k0 = (ks + 1) << 4;
            rah = *(const uint4*)(pAh + k0);
            ral = *(const uint4*)(pAl + k0);
            rbh = *(const uint4*)(pBh + k0);
            rbl = *(const uint4*)(pBl + k0);
        }

        const uint32_t sb = smbase + cur * (4 * GBUF * 2);
        uint32_t fah[2][4], fal[2][4];
#pragma unroll
        for (int mt = 0; mt < 2; mt++) {
            ldsm4(fah[mt], sb + 0 * (GBUF * 2) + offA[mt]);
            ldsm4(fal[mt], sb + 1 * (GBUF * 2) + offA[mt]);
        }
#pragma unroll
        for (int np = 0; np < 4; np++) {
            uint32_t bh[4], bl[4];
            ldsm4(bh, sb + 2 * (GBUF * 2) + offB[np]);
            ldsm4(bl, sb + 3 * (GBUF * 2) + offB[np]);
            uint32_t bA_h[2] = { bh[0], bh[2] }, bB_h[2] = { bh[1], bh[3] };
            uint32_t bA_l[2] = { bl[0], bl[2] }, bB_l[2] = { bl[1], bl[3] };
#pragma unroll
            for (int mt = 0; mt < 2; mt++) {
                mma16816(acc[mt][np * 2],     fah[mt], bA_h);
                mma16816(acc[mt][np * 2],     fal[mt], bA_h);
                mma16816(acc[mt][np * 2],     fah[mt], bA_l);
                mma16816(acc[mt][np * 2 + 1], fah[mt], bB_h);
                mma16816(acc[mt][np * 2 + 1], fal[mt], bB_h);
                mma16816(acc[mt][np * 2 + 1], fah[mt], bB_l);
            }
        }

        if (ks + 1 < KT) {
            *(uint4*)&sm[nxt][0][sidx] = rah;
            *(uint4*)&sm[nxt][1][sidx] = ral;
            *(uint4*)&sm[nxt][2][sidx] = rbh;
            *(uint4*)&sm[nxt][3][sidx] = rbl;
        }
        __syncthreads();
    }

#pragma unroll
    for (int mt = 0; mt < 2; mt++) {
#pragma unroll
        for (int nt = 0; nt < 8; nt++) {
            int row = bm + wm + mt * 16 + g;
            int col = bn + wn + nt * 8 + j * 2;
            float2 v0 = make_float2(acc[mt][nt][0] * alpha, acc[mt][nt][1] * alpha);
            float2 v1 = make_float2(acc[mt][nt][2] * alpha, acc[mt][nt][3] * alpha);
            size_t i0 = (size_t)row * N + col;
            size_t i1 = (size_t)(row + 8) * N + col;
            uint32_t h, l;
            split2(v0.x, v0.y, h, l);
            *(uint32_t*)&Chi[i0] = h; *(uint32_t*)&Clo[i0] = l;
            split2(v1.x, v1.y, h, l);
            *(uint32_t*)&Chi[i1] = h; *(uint32_t*)&Clo[i1] = l;
        }
    }
}

// ---------------------------------------------------------------------------
// NT GEMM (Wp projection; optional fp32 out)
// ---------------------------------------------------------------------------
__global__ void __launch_bounds__(256, 2) gemm_nt_bf16(
    const __nv_bfloat16* __restrict__ Ah, const __nv_bfloat16* __restrict__ Al,
    const __nv_bfloat16* __restrict__ Bh, const __nv_bfloat16* __restrict__ Bl,
    float* __restrict__ Cf, __nv_bfloat16* __restrict__ Chi, __nv_bfloat16* __restrict__ Clo,
    const float* __restrict__ bias, int M, int N, int K, float alpha)
{
    __shared__ __align__(16) __nv_bfloat16 sm[2][4][GBUF];  // 48KB

    const int tid  = threadIdx.x;
    const int lane = tid & 31;
    const int wid  = tid >> 5;
    const int wm   = (wid & 3) * 32;
    const int wn   = (wid >> 2) * 64;
    const int bm   = blockIdx.y * 128;
    const int bn   = blockIdx.x * 128;
    const int g    = lane >> 2;
    const int j    = lane & 3;

    const int lrow  = tid >> 1;
    const int lhalf = tid & 1;
    const __nv_bfloat16* pAh = Ah + (size_t)(bm + lrow) * K + lhalf * 8;
    const __nv_bfloat16* pAl = Al + (size_t)(bm + lrow) * K + lhalf * 8;
    const __nv_bfloat16* pBh = Bh + (size_t)(bn + lrow) * K + lhalf * 8;
    const __nv_bfloat16* pBl = Bl + (size_t)(bn + lrow) * K + lhalf * 8;
    const int sidx = lrow * GST + lhalf * 8;

    const int lr8  = (lane & 7) + ((lane >> 3) & 1) * 8;
    const int lc16 = (lane >> 4) * 16;
    const uint32_t smbase = smem_u32(&sm[0][0][0]);
    uint32_t offA[2], offB[4];
#pragma unroll
    for (int mt = 0; mt < 2; mt++) offA[mt] = (wm + mt * 16 + lr8) * 48 + lc16;
#pragma unroll
    for (int np = 0; np < 4; np++) offB[np] = (wn + np * 16 + lr8) * 48 + lc16;

    float acc[2][8][4];
#pragma unroll
    for (int mt = 0; mt < 2; mt++)
#pragma unroll
        for (int nt = 0; nt < 8; nt++)
#pragma unroll
            for (int i = 0; i < 4; i++) acc[mt][nt][i] = 0.f;

    const int KT = K >> 4;

    {
        *(uint4*)&sm[0][0][sidx] = *(const uint4*)pAh;
        *(uint4*)&sm[0][1][sidx] = *(const uint4*)pAl;
        *(uint4*)&sm[0][2][sidx] = *(const uint4*)pBh;
        *(uint4*)&sm[0][3][sidx] = *(const uint4*)pBl;
    }
    __syncthreads();

    for (int ks = 0; ks < KT; ks++) {
        const int cur = ks & 1, nxt = cur ^ 1;

        uint4 rah, ral, rbh, rbl;
        if (ks + 1 < KT) {
            int k0 = (ks + 1) << 4;
            rah = *(const uint4*)(pAh + k0);
            ral = *(const uint4*)(pAl + k0);
            rbh = *(const uint4*)(pBh + k0);
            rbl = *(const uint4*)(pBl + k0);
        }

        const uint32_t sb = smbase + cur * (4 * GBUF * 2);
        uint32_t fah[2][4], fal[2][4];
#pragma unroll
        for (int mt = 0; mt < 2; mt++) {
            ldsm4(fah[mt], sb + 0 * (GBUF * 2) + offA[mt]);
            ldsm4(fal[mt], sb + 1 * (GBUF * 2) + offA[mt]);
        }
#pragma unroll
        for (int np = 0; np < 4; np++) {
            uint32_t bh[4], bl[4];
            ldsm4(bh, sb + 2 * (GBUF * 2) + offB[np]);
            ldsm4(bl, sb + 3 * (GBUF * 2) + offB[np]);
            uint32_t bA_h[2] = { bh[0], bh[2] }, bB_h[2] = { bh[1], bh[3] };
            uint32_t bA_l[2] = { bl[0], bl[2] }, bB_l[2] = { bl[1], bl[3] };
#pragma unroll
            for (int mt = 0; mt < 2; mt++) {
                mma16816(acc[mt][np * 2],     fah[mt], bA_h);
                mma16816(acc[mt][np * 2],     fal[mt], bA_h);
                mma16816(acc[mt][np * 2],     fah[mt], bA_l);
                mma16816(acc[mt][np * 2 + 1], fah[mt], bB_h);
                mma16816(acc[mt][np * 2 + 1], fal[mt], bB_h);
                mma16816(acc[mt][np * 2 + 1], fah[mt], bB_l);
            }
        }

        if (ks + 1 < KT) {
            *(uint4*)&sm[nxt][0][sidx] = rah;
            *(uint4*)&sm[nxt][1][sidx] = ral;
            *(uint4*)&sm[nxt][2][sidx] = rbh;
            *(uint4*)&sm[nxt][3][sidx] = rbl;
        }
        __syncthreads();
    }

#pragma unroll
    for (int mt = 0; mt < 2; mt++) {
#pragma unroll
        for (int nt = 0; nt < 8; nt++) {
            int row = bm + wm + mt * 16 + g;
            int col = bn + wn + nt * 8 + j * 2;
            float2 v0 = make_float2(acc[mt][nt][0] * alpha, acc[mt][nt][1] * alpha);
            float2 v1 = make_float2(acc[mt][nt][2] * alpha, acc[mt][nt][3] * alpha);
            if (bias) {
                const float* b0 = bias + (size_t)(row & (T_ - 1)) * N + col;
                const float* b1 = bias + (size_t)((row + 8) & (T_ - 1)) * N + col;
                v0.x += b0[0]; v0.y += b0[1];
                v1.x += b1[0]; v1.y += b1[1];
            }
            size_t i0 = (size_t)row * N + col;
            size_t i1 = (size_t)(row + 8) * N + col;
            if (Cf) {
                *(float2*)&Cf[i0] = v0;
                *(float2*)&Cf[i1] = v1;
            }
            uint32_t h, l;
            split2(v0.x, v0.y, h, l);
            *(uint32_t*)&Chi[i0] = h; *(uint32_t*)&Clo[i0] = l;
            split2(v1.x, v1.y, h, l);
            *(uint32_t*)&Chi[i1] = h; *(uint32_t*)&Clo[i1] = l;
        }
    }
}

// ---------------------------------------------------------------------------
// Embed GEMM: A fp32 (x), split inline; B pre-split bf16.
// ---------------------------------------------------------------------------
__global__ void __launch_bounds__(256, 2) gemm_nt_f32a(
    const float* __restrict__ Af,
    const __nv_bfloat16* __restrict__ Bh, const __nv_bfloat16* __restrict__ Bl,
    __nv_bfloat16* __restrict__ Chi, __nv_bfloat16* __restrict__ Clo,
    const float* __restrict__ bias, int M, int N, int K, float alpha)
{
    __shared__ __align__(16) __nv_bfloat16 sm[2][4][GBUF];  // 48KB

    const int tid  = threadIdx.x;
    const int lane = tid & 31;
    const int wid  = tid >> 5;
    const int wm   = (wid & 3) * 32;
    const int wn   = (wid >> 2) * 64;
    const int bm   = blockIdx.y * 128;
    const int bn   = blockIdx.x * 128;
    const int g    = lane >> 2;
    const int j    = lane & 3;

    const int lrow  = tid >> 1;
    const int lhalf = tid & 1;
    const float* pAf = Af + (size_t)(bm + lrow) * K + lhalf * 8;
    const __nv_bfloat16* pBh = Bh + (size_t)(bn + lrow) * K + lhalf * 8;
    const __nv_bfloat16* pBl = Bl + (size_t)(bn + lrow) * K + lhalf * 8;
    const int sidx = lrow * GST + lhalf * 8;

    const int lr8  = (lane & 7) + ((lane >> 3) & 1) * 8;
    const int lc16 = (lane >> 4) * 16;
    const uint32_t smbase = smem_u32(&sm[0][0][0]);
    uint32_t offA[2], offB[4];
#pragma unroll
    for (int mt = 0; mt < 2; mt++) offA[mt] = (wm + mt * 16 + lr8) * 48 + lc16;
#pragma unroll
    for (int np = 0; np < 4; np++) offB[np] = (wn + np * 16 + lr8) * 48 + lc16;

    float acc[2][8][4];
#pragma unroll
    for (int mt = 0; mt < 2; mt++)
#pragma unroll
        for (int nt = 0; nt < 8; nt++)
#pragma unroll
            for (int i = 0; i < 4; i++) acc[mt][nt][i] = 0.f;

    const int KT = K >> 4;

    {
        float4 f0 = *(const float4*)(pAf);
        float4 f1 = *(const float4*)(pAf + 4);
        uint32_t h[4], l[4];
        split2(f0.x, f0.y, h[0], l[0]);
        split2(f0.z, f0.w, h[1], l[1]);
        split2(f1.x, f1.y, h[2], l[2]);
        split2(f1.z, f1.w, h[3], l[3]);
        *(uint4*)&sm[0][0][sidx] = make_uint4(h[0], h[1], h[2], h[3]);
        *(uint4*)&sm[0][1][sidx] = make_uint4(l[0], l[1], l[2], l[3]);
        *(uint4*)&sm[0][2][sidx] = *(const uint4*)pBh;
        *(uint4*)&sm[0][3][sidx] = *(const uint4*)pBl;
    }
    __syncthreads();

    for (int ks = 0; ks < KT; ks++) {
        const int cur = ks & 1, nxt = cur ^ 1;

        float4 rf0, rf1;
        uint4 rbh, rbl;
        if (ks + 1 < KT) {
            int k0 = (ks + 1) << 4;
            rf0 = *(const float4*)(pAf + k0);
            rf1 = *(const float4*)(pAf + k0 + 4);
            rbh = *(const uint4*)(pBh + k0);
            rbl = *(const uint4*)(pBl + k0);
        }

        const uint32_t sb = smbase + cur * (4 * GBUF * 2);
        uint32_t fah[2][4], fal[2][4];
#pragma unroll
        for (int mt = 0; mt < 2; mt++) {
            ldsm4(fah[mt], sb + 0 * (GBUF * 2) + offA[mt]);
            ldsm4(fal[mt], sb + 1 * (GBUF * 2) + offA[mt]);
        }
#pragma unroll
        for (int np = 0; np < 4; np++) {
            uint32_t bh[4], bl[4];
            ldsm4(bh, sb + 2 * (GBUF * 2) + offB[np]);
            ldsm4(bl, sb + 3 * (GBUF * 2) + offB[np]);
            uint32_t bA_h[2] = { bh[0], bh[2] }, bB_h[2] = { bh[1], bh[3] };
            uint32_t bA_l[2] = { bl[0], bl[2] }, bB_l[2] = { bl[1], bl[3] };
#pragma unroll
            for (int mt = 0; mt < 2; mt++) {
                mma16816(acc[mt][np * 2],     fah[mt], bA_h);
                mma16816(acc[mt][np * 2],     fal[mt], bA_h);
                mma16816(acc[mt][np * 2],     fah[mt], bA_l);
                mma16816(acc[mt][np * 2 + 1], fah[mt], bB_h);
                mma16816(acc[mt][np * 2 + 1], fal[mt], bB_h);
                mma16816(acc[mt][np * 2 + 1], fah[mt], bB_l);
            }
        }

        if (ks + 1 < KT) {
            uint32_t h[4], l[4];
            split2(rf0.x, rf0.y, h[0], l[0]);
            split2(rf0.z, rf0.w, h[1], l[1]);
            split2(rf1.x, rf1.y, h[2], l[2]);
            split2(rf1.z, rf1.w, h[3], l[3]);
            *(uint4*)&sm[nxt][0][sidx] = make_uint4(h[0], h[1], h[2], h[3]);
            *(uint4*)&sm[nxt][1][sidx] = make_uint4(l[0], l[1], l[2], l[3]);
            *(uint4*)&sm[nxt][2][sidx] = rbh;
            *(uint4*)&sm[nxt][3][sidx] = rbl;
        }
        __syncthreads();
    }

#pragma unroll
    for (int mt = 0; mt < 2; mt++) {
#pragma unroll
        for (int nt = 0; nt < 8; nt++) {
            int row = bm + wm + mt * 16 + g;
            int col = bn + wn + nt * 8 + j * 2;
            float2 v0 = make_float2(acc[mt][nt][0] * alpha, acc[mt][nt][1] * alpha);
            float2 v1 = make_float2(acc[mt][nt][2] * alpha, acc[mt][nt][3] * alpha);
            const float* b0 = bias + (size_t)(row & (T_ - 1)) * N + col;
            const float* b1 = bias + (size_t)((row + 8) & (T_ - 1)) * N + col;
            v0.x += b0[0]; v0.y += b0[1];
            v1.x += b1[0]; v1.y += b1[1];
            size_t i0 = (size_t)row * N + col;
            size_t i1 = (size_t)(row + 8) * N + col;
            uint32_t h, l;
            split2(v0.x, v0.y, h, l);
            *(uint32_t*)&Chi[i0] = h; *(uint32_t*)&Clo[i0] = l;
            split2(v1.x, v1.y, h, l);
            *(uint32_t*)&Chi[i1] = h; *(uint32_t*)&Clo[i1] = l;
        }
    }
}

// ---------------------------------------------------------------------------
// Flash attention, cp.async double-buffered, fixed-offset softmax.
// 2 CTAs/SM (148KB smem total, regs capped at 128).
// ---------------------------------------------------------------------------
#define ASTR       72                 // bf16 row stride (144 bytes)
#define A_ARR      9216               // bytes per array (64 rows * 144B)
#define A_STAGE    (4 * A_ARR)        // Kh,Kl,Vh,Vl per stage = 36864B
#define A_SMEM     (2 * A_STAGE)      // 73728B
#define SM_OFF     6.0f               // softmax exponent offset (log2 units)

extern __shared__ char attnsmem[];

__device__ __forceinline__ void attn_issue(
    uint32_t sbase, int s,
    const __nv_bfloat16* Kh, const __nv_bfloat16* Kl,
    const __nv_bfloat16* Vh, const __nv_bfloat16* Vl,
    size_t base, int t, int ldrow, int ldc)
{
    size_t grow = base + (size_t)(t * 64 + ldrow) * D_;
    uint32_t so = sbase + s * A_STAGE + ldrow * 144;
    cp16(so + 0 * A_ARR + ldc * 16,       Kh + grow + ldc * 8);
    cp16(so + 0 * A_ARR + (ldc + 4) * 16, Kh + grow + (ldc + 4) * 8);
    cp16(so + 1 * A_ARR + ldc * 16,       Kl + grow + ldc * 8);
    cp16(so + 1 * A_ARR + (ldc + 4) * 16, Kl + grow + (ldc + 4) * 8);
    cp16(so + 2 * A_ARR + ldc * 16,       Vh + grow + ldc * 8);
    cp16(so + 2 * A_ARR + (ldc + 4) * 16, Vh + grow + (ldc + 4) * 8);
    cp16(so + 3 * A_ARR + ldc * 16,       Vl + grow + ldc * 8);
    cp16(so + 3 * A_ARR + (ldc + 4) * 16, Vl + grow + (ldc + 4) * 8);
    asm volatile("cp.async.commit_group;" ::: "memory");
}

__global__ void __launch_bounds__(256, 2) attn_bf16(
    const __nv_bfloat16* __restrict__ Qh, const __nv_bfloat16* __restrict__ Ql,
    const __nv_bfloat16* __restrict__ Kh, const __nv_bfloat16* __restrict__ Kl,
    const __nv_bfloat16* __restrict__ Vh, const __nv_bfloat16* __restrict__ Vl,
    __nv_bfloat16* __restrict__ Ohi, __nv_bfloat16* __restrict__ Olo)
{
    const int tid  = threadIdx.x;
    const int lane = tid & 31;
    const int wid  = tid >> 5;
    const int g    = lane >> 2;
    const int j    = lane & 3;

    const int q0 = blockIdx.x * 128;
    const int hh = blockIdx.y;
    const int bb = blockIdx.z;
    const size_t base = ((size_t)bb * T_) * D_ + (size_t)hh * HD_;

    const int ldrow = tid >> 2;
    const int ldc   = tid & 3;
    const uint32_t sbase = smem_u32(attnsmem);

    attn_issue(sbase, 0, Kh, Kl, Vh, Vl, base, 0, ldrow, ldc);

    // ---- Q fragments; fold in 0.125*log2(e) with full re-split ----
    uint32_t Qfh[4][4], Qfl[4][4];
    {
        const uint32_t* qh32 = (const uint32_t*)(Qh + base);
        const uint32_t* ql32 = (const uint32_t*)(Ql + base);
        int r0 = q0 + wid * 16 + g;
        const float SC = 0.18033688011112042f;  // 0.125 * log2(e)
#pragma unroll
        for (int kf = 0; kf < 4; kf++) {
            int w0 = kf * 8 + j, w1 = kf * 8 + 4 + j;
            uint32_t rh[4], rl[4];
            rh[0] = qh32[(size_t)r0 * (D_ / 2) + w0];
            rh[1] = qh32[(size_t)(r0 + 8) * (D_ / 2) + w0];
            rh[2] = qh32[(size_t)r0 * (D_ / 2) + w1];
            rh[3] = qh32[(size_t)(r0 + 8) * (D_ / 2) + w1];
            rl[0] = ql32[(size_t)r0 * (D_ / 2) + w0];
            rl[1] = ql32[(size_t)(r0 + 8) * (D_ / 2) + w0];
            rl[2] = ql32[(size_t)r0 * (D_ / 2) + w1];
            rl[3] = ql32[(size_t)(r0 + 8) * (D_ / 2) + w1];
#pragma unroll
            for (int i = 0; i < 4; i++) {
                float2 a = __bfloat1622float2(*(__nv_bfloat162*)&rh[i]);
                float2 b = __bfloat1622float2(*(__nv_bfloat162*)&rl[i]);
                split2((a.x + b.x) * SC, (a.y + b.y) * SC, Qfh[kf][i], Qfl[kf][i]);
            }
        }
    }

    const int lr8  = (lane & 7) + ((lane >> 3) & 1) * 8;
    const int lc16 = (lane >> 4) * 16;

    float oac[8][4];
#pragma unroll
    for (int nt = 0; nt < 8; nt++)
#pragma unroll
        for (int i = 0; i < 4; i++) oac[nt][i] = 0.f;
    float l0 = 0.f, l1 = 0.f;

    const int NTILE = T_ / 64;

    for (int t = 0; t < NTILE; t++) {
        const int s = t & 1;

        if (t + 1 < NTILE) {
            attn_issue(sbase, s ^ 1, Kh, Kl, Vh, Vl, base, t + 1, ldrow, ldc);
            asm volatile("cp.async.wait_group 1;" ::: "memory");
        } else {
            asm volatile("cp.async.wait_group 0;" ::: "memory");
        }
        __syncthreads();

        const uint32_t kh_b = sbase + s * A_STAGE + 0 * A_ARR;
        const uint32_t kl_b = sbase + s * A_STAGE + 1 * A_ARR;
        const uint32_t vh_b = sbase + s * A_STAGE + 2 * A_ARR;
        const uint32_t vl_b = sbase + s * A_STAGE + 3 * A_ARR;

        float sac[8][4];
#pragma unroll
        for (int nt = 0; nt < 8; nt++)
#pragma unroll
            for (int i = 0; i < 4; i++) sac[nt][i] = 0.f;

#pragma unroll
        for (int kf = 0; kf < 4; kf++) {
#pragma unroll
            for (int np = 0; np < 4; np++) {
                uint32_t off = (np * 16 + lr8) * 144 + kf * 32 + lc16;
                uint32_t bh[4], bl[4];
                ldsm4(bh, kh_b + off);
                ldsm4(bl, kl_b + off);
                uint32_t bA_h[2] = { bh[0], bh[2] }, bB_h[2] = { bh[1], bh[3] };
                uint32_t bA_l[2] = { bl[0], bl[2] }, bB_l[2] = { bl[1], bl[3] };
                mma16816(sac[np * 2],     Qfh[kf], bA_h);
                mma16816(sac[np * 2],     Qfl[kf], bA_h);
                mma16816(sac[np * 2],     Qfh[kf], bA_l);
                mma16816(sac[np * 2 + 1], Qfh[kf], bB_h);
                mma16816(sac[np * 2 + 1], Qfl[kf], bB_h);
                mma16816(sac[np * 2 + 1], Qfh[kf], bB_l);
            }
        }

        // fixed-offset softmax: p = 2^(sac - 6)
        float rs0 = 0.f, rs1 = 0.f;
#pragma unroll
        for (int nt = 0; nt < 8; nt++) {
            sac[nt][0] = ex2(sac[nt][0] - SM_OFF);
            sac[nt][1] = ex2(sac[nt][1] - SM_OFF);
            sac[nt][2] = ex2(sac[nt][2] - SM_OFF);
            sac[nt][3] = ex2(sac[nt][3] - SM_OFF);
            rs0 += sac[nt][0] + sac[nt][1];
            rs1 += sac[nt][2] + sac[nt][3];
        }
        l0 += rs0;
        l1 += rs1;

#pragma unroll
        for (int kf = 0; kf < 4; kf++) {
            uint32_t ph[4], pl[4];
            split2(sac[2 * kf][0],     sac[2 * kf][1],     ph[0], pl[0]);
            split2(sac[2 * kf][2],     sac[2 * kf][3],     ph[1], pl[1]);
            split2(sac[2 * kf + 1][0], sac[2 * kf + 1][1], ph[2], pl[2]);
            split2(sac[2 * kf + 1][2], sac[2 * kf + 1][3], ph[3], pl[3]);
#pragma unroll
            for (int np = 0; np < 4; np++) {
                uint32_t off = (kf * 16 + lr8) * 144 + np * 32 + lc16;
                uint32_t vh[4], vl[4];
                ldsm4t(vh, vh_b + off);
                ldsm4t(vl, vl_b + off);
                uint32_t vA_h[2] = { vh[0], vh[1] }, vB_h[2] = { vh[2], vh[3] };
                uint32_t vA_l[2] = { vl[0], vl[1] }, vB_l[2] = { vl[2], vl[3] };
                mma16816(oac[np * 2],     ph, vA_h);
                mma16816(oac[np * 2],     pl, vA_h);
                mma16816(oac[np * 2],     ph, vA_l);
                mma16816(oac[np * 2 + 1], ph, vB_h);
                mma16816(oac[np * 2 + 1], pl, vB_h);
                mma16816(oac[np * 2 + 1], ph, vB_l);
            }
        }
        __syncthreads();
    }

#pragma unroll
    for (int off = 1; off <= 2; off <<= 1) {
        l0 += __shfl_xor_sync(0xffffffffu, l0, off);
        l1 += __shfl_xor_sync(0xffffffffu, l1, off);
    }
    float inv0 = 1.f / l0, inv1 = 1.f / l1;
    int row = q0 + wid * 16 + g;
    uint32_t* oh32 = (uint32_t*)(Ohi + base);
    uint32_t* ol32 = (uint32_t*)(Olo + base);
#pragma unroll
    for (int nt = 0; nt < 8; nt++) {
        int w = nt * 4 + j;
        uint32_t h, l;
        split2(oac[nt][0] * inv0, oac[nt][1] * inv0, h, l);
        oh32[(size_t)row * (D_ / 2) + w] = h;
        ol32[(size_t)row * (D_ / 2) + w] = l;
        split2(oac[nt][2] * inv1, oac[nt][3] * inv1, h, l);
        oh32[(size_t)(row + 8) * (D_ / 2) + w] = h;
        ol32[(size_t)(row + 8) * (D_ / 2) + w] = l;
    }
}

// ---------------------------------------------------------------------------
__global__ void __launch_bounds__(256) readout_kernel(
    const float* __restrict__ hbuf, const float* __restrict__ R,
    float* __restrict__ out)
{
    __shared__ float hs[B_][D_];
    for (int i = threadIdx.x; i < B_ * D_; i += 256) {
        int b = i >> 9, d = i & 511;
        hs[b][d] = hbuf[((size_t)b * T_ + (T_ - 1)) * D_ + d];
    }
    __syncthreads();

    int v = blockIdx.x * 256 + threadIdx.x;
    float a0 = 0.f, a1 = 0.f, a2 = 0.f, a3 = 0.f;
    const float* r = R + (size_t)v * D_;
    for (int d = 0; d < D_; d += 4) {
        float4 rv = *(const float4*)(r + d);
        a0 += rv.x * hs[0][d] + rv.y * hs[0][d + 1] + rv.z * hs[0][d + 2] + rv.w * hs[0][d + 3];
        a1 += rv.x * hs[1][d] + rv.y * hs[1][d + 1] + rv.z * hs[1][d + 2] + rv.w * hs[1][d + 3];
        a2 += rv.x * hs[2][d] + rv.y * hs[2][d + 1] + rv.z * hs[2][d + 2] + rv.w * hs[2][d + 3];
        a3 += rv.x * hs[3][d] + rv.y * hs[3][d + 1] + rv.z * hs[3][d + 2] + rv.w * hs[3][d + 3];
    }
    const float sc = 0.04419417382415922f;
    out[0 * V_ + v] = a0 * sc;
    out[1 * V_ + v] = a1 * sc;
    out[2 * V_ + v] = a2 * sc;
    out[3 * V_ + v] = a3 * sc;
}

// ---------------------------------------------------------------------------
extern "C" void kernel_launch(void* const* d_in, const int* in_sizes, int n_in,
                              void* d_out, int out_size)
{
    const float* x  = (const float*)d_in[0];
    const float* te = (const float*)d_in[1];
    const float* pe = (const float*)d_in[2];
    const float* Wk = (const float*)d_in[3];
    const float* Wq = (const float*)d_in[4];
    const float* Wv = (const float*)d_in[5];
    const float* Wp = (const float*)d_in[6];
    const float* ro = (const float*)d_in[7];
    float* out = (float*)d_out;

    float* hf;
    __nv_bfloat16 *hh, *hl, *qh, *ql, *kh, *kl, *vh, *vl, *oh, *ol;
    __nv_bfloat16 *teh, *tel;
    __nv_bfloat16 *wqh, *wql, *wkh, *wkl, *wvh, *wvl, *wph, *wpl;
    cudaGetSymbolAddress((void**)&hf,  g_h);
    cudaGetSymbolAddress((void**)&hh,  g_hh);  cudaGetSymbolAddress((void**)&hl, g_hl);
    cudaGetSymbolAddress((void**)&qh,  g_qh);  cudaGetSymbolAddress((void**)&ql, g_ql);
    cudaGetSymbolAddress((void**)&kh,  g_kh);  cudaGetSymbolAddress((void**)&kl, g_kl);
    cudaGetSymbolAddress((void**)&vh,  g_vh);  cudaGetSymbolAddress((void**)&vl, g_vl);
    cudaGetSymbolAddress((void**)&oh,  g_oh);  cudaGetSymbolAddress((void**)&ol, g_ol);
    cudaGetSymbolAddress((void**)&teh, g_teh); cudaGetSymbolAddress((void**)&tel, g_tel);
    cudaGetSymbolAddress((void**)&wqh, g_wqh); cudaGetSymbolAddress((void**)&wql, g_wql);
    cudaGetSymbolAddress((void**)&wkh, g_wkh); cudaGetSymbolAddress((void**)&wkl, g_wkl);
    cudaGetSymbolAddress((void**)&wvh, g_wvh); cudaGetSymbolAddress((void**)&wvl, g_wvl);
    cudaGetSymbolAddress((void**)&wph, g_wph); cudaGetSymbolAddress((void**)&wpl, g_wpl);

    cudaFuncSetAttribute(attn_bf16, cudaFuncAttributeMaxDynamicSharedMemorySize, A_SMEM);

    const float sV = 0.022097086912079608f;  // 1/sqrt(2048)
    const float sD = 0.04419417382415922f;   // 1/sqrt(512)

    {
        int n4 = (D_ * V_) / 4;
        split_kernel<<<(n4 + 255) / 256, 256>>>((const float4*)te, (uint2*)teh, (uint2*)tel, n4);
        n4 = (L_ * D_ * D_) / 4;
        split_kernel<<<(n4 + 255) / 256, 256>>>((const float4*)Wq, (uint2*)wqh, (uint2*)wql, n4);
        split_kernel<<<(n4 + 255) / 256, 256>>>((const float4*)Wk, (uint2*)wkh, (uint2*)wkl, n4);
        split_kernel<<<(n4 + 255) / 256, 256>>>((const float4*)Wv, (uint2*)wvh, (uint2*)wvl, n4);
        split_kernel<<<(n4 + 255) / 256, 256>>>((const float4*)Wp, (uint2*)wph, (uint2*)wpl, n4);
    }

    dim3 ggrid(D_ / 128, (B_ * T_) / 128);           // (4, 64)
    dim3 qkvgrid(D_ / 128, (B_ * T_) / 128, 3);      // (4, 64, 3)

    // embed: h = x @ TE^T / sqrt(V) + pos
    gemm_nt_f32a<<<ggrid, 256>>>(x, teh, tel, hh, hl, pe, B_ * T_, D_, V_, sV);

    for (int l = 0; l < L_; l++) {
        size_t wo = (size_t)l * D_ * D_;
        gemm_qkv<<<qkvgrid, 256>>>(hh, hl,
                                   wqh + wo, wql + wo, wkh + wo, wkl + wo, wvh + wo, wvl + wo,
                                   qh, ql, kh, kl, vh, vl, sD);

        attn_bf16<<<dim3(T_ / 128, H_, B_), 256, A_SMEM>>>(qh, ql, kh, kl, vh, vl, oh, ol);

        // fp32 h only needed after the last layer (readout)
        gemm_nt_bf16<<<ggrid, 256>>>(oh, ol, wph + wo, wpl + wo,
                                     (l == L_ - 1) ? hf : nullptr, hh, hl,
                                     nullptr, B_ * T_, D_, D_, sD);
    }

    readout_kernel<<<V_ / 256, 256>>>(hf, ro, out);
}